// round 1
// baseline (speedup 1.0000x reference)
#include <cuda_runtime.h>
#include <math.h>
#include <stdint.h>

#define Bc 2
#define Tc 256
#define Ec 512
#define Gc 8
#define GDc 64
#define Lc 8
#define NU 64
#define Vc 50257
#define Sc 8
#define EPSc 1.1920929e-7f

// ---------------- device scratch (no allocations allowed) ----------------
__device__ float g_x[Bc*Tc*Ec];
__device__ float g_xn[Bc*Tc*Ec];
__device__ float g_pcont[Bc*Tc];
__device__ float g_cos[Tc*32];
__device__ float g_sin[Tc*32];
__device__ float g_weff[Sc*NU];
__device__ float g_apsum[NU*GDc];
__device__ float g_mpsum[NU*GDc];
__device__ float g_adap[NU*GDc*Ec];      // adapters + folded identity skip
__device__ float g_xi [Bc*Tc*NU*GDc];
__device__ float g_q  [Bc*Tc*NU*GDc];
__device__ float g_k  [Bc*Tc*NU*GDc];
__device__ float g_v  [Bc*Tc*NU*GDc];
__device__ float g_att[Bc*Tc*NU*GDc];
__device__ float g_up [Bc*Tc*NU*GDc];

// ---------------- prep kernels ----------------
__global__ void k_tables() {
    int t = blockIdx.x, i = threadIdx.x;   // i < 32
    double invf = pow(10000.0, -((double)(2*i)) / (double)GDc);
    double f = (double)t * invf;
    g_cos[t*32+i] = (float)cos(f);
    g_sin[t*32+i] = (float)sin(f);
}

__global__ void k_depths(const float* __restrict__ dep) {
    int n = threadIdx.x;                   // 64 threads
    __shared__ float d0[NU], d1[NU];
    d0[n] = 0.f; __syncthreads();
    for (int it = 0; it < Lc; it++) {
        float acc = 0.f;
        for (int j = 0; j < NU; j++)
            acc += fmaxf(dep[n*NU+j], 0.f) * (d0[j] + 1.f);
        d1[n] = acc; __syncthreads();
        d0[n] = d1[n]; __syncthreads();
    }
    float dn = d0[n];
    for (int t = 0; t < Sc; t++) {
        float td = (float)t * ((float)Lc / (float)Sc);
        float w = expf(-fabsf(dn - td));
        g_weff[t*NU+n] = (w > 0.15f) ? w : 0.f;
    }
}

__global__ void k_sums(const float* __restrict__ ap, const float* __restrict__ mp) {
    int i = blockIdx.x*blockDim.x + threadIdx.x;    // < 4096 = (n*64+g)
    if (i >= NU*GDc) return;
    float s = 0.f;
    for (int k = 0; k < GDc; k++) s += ap[i*GDc + k];
    g_apsum[i] = s;
    float s2 = 0.f;
    for (int k = 0; k < 4*GDc; k++) s2 += mp[i*4*GDc + k];
    g_mpsum[i] = s2;
}

__global__ void k_adap(const float* __restrict__ adapters) {
    int tid = blockIdx.x*blockDim.x + threadIdx.x;  // < 64*64*512
    int row = tid >> 9;        // n*64+g
    int e   = tid & 511;
    int n = row >> 6, g = row & 63;
    float add = (e == ((n & (Gc-1))*GDc + g)) ? 1.f : 0.f;
    g_adap[tid] = adapters[tid] + add;
}

__global__ void k_embed(const int* __restrict__ idx, const float* __restrict__ wte) {
    int bt = blockIdx.x;
    int tx = threadIdx.x;                  // 256
    __shared__ float sred[256];
    int row = idx[bt];
    const float* w = wte + (size_t)row * Ec;
    float a = w[tx], b = w[tx+256];
    sred[tx] = a*a + b*b;
    __syncthreads();
    for (int s = 128; s > 0; s >>= 1) { if (tx < s) sred[tx] += sred[tx+s]; __syncthreads(); }
    float r = rsqrtf(sred[0] / (float)Ec + EPSc);
    g_x[(size_t)bt*Ec + tx]       = a*r;
    g_x[(size_t)bt*Ec + tx + 256] = b*r;
    if (tx == 0) g_pcont[bt] = 1.f;
}

// ---------------- GEMM: C[m,n] = sum_k A[m,k]*B[n,k]  (both row-major, K-contig) ----------------
// MODE 0: plain store.  MODE 1: 15*tanh(c/15) epilogue.
template<int MODE>
__global__ void gemm_nt(const float* __restrict__ A, const float* __restrict__ B,
                        float* __restrict__ C, int M, int N, int K) {
    const int BM = 64, BN = 64, BK = 16;
    __shared__ float As[BK][BM];
    __shared__ float Bs[BK][BN];
    int bm = blockIdx.y * BM, bn = blockIdx.x * BN;
    int tx = threadIdx.x;                  // 256 threads
    int tcol = (tx & 15) * 4;
    int trow = (tx >> 4) * 4;
    float acc[4][4] = {};
    for (int k0 = 0; k0 < K; k0 += BK) {
        #pragma unroll
        for (int i = tx; i < BM*BK; i += 256) {
            int r = i / BK, c = i % BK;
            As[c][r] = (bm + r < M) ? A[(size_t)(bm+r)*K + k0 + c] : 0.f;
        }
        #pragma unroll
        for (int i = tx; i < BN*BK; i += 256) {
            int r = i / BK, c = i % BK;
            Bs[c][r] = (bn + r < N) ? B[(size_t)(bn+r)*K + k0 + c] : 0.f;
        }
        __syncthreads();
        #pragma unroll
        for (int kk = 0; kk < BK; kk++) {
            float a[4], b[4];
            #pragma unroll
            for (int i = 0; i < 4; i++) a[i] = As[kk][trow+i];
            #pragma unroll
            for (int j = 0; j < 4; j++) b[j] = Bs[kk][tcol+j];
            #pragma unroll
            for (int i = 0; i < 4; i++)
                #pragma unroll
                for (int j = 0; j < 4; j++) acc[i][j] += a[i]*b[j];
        }
        __syncthreads();
    }
    #pragma unroll
    for (int i = 0; i < 4; i++) {
        int m = bm + trow + i; if (m >= M) continue;
        #pragma unroll
        for (int j = 0; j < 4; j++) {
            int n = bn + tcol + j; if (n >= N) continue;
            float v = acc[i][j];
            if (MODE == 1) v = 15.f * tanhf(v / 15.f);
            C[(size_t)m*N + n] = v;
        }
    }
}

// ---------------- per-step kernels ----------------
// qkv projection + rope + rms, one block per (bt, n), 64 threads
__global__ void k_qkv(const float* __restrict__ qkv_w) {
    int bt = blockIdx.x, n = blockIdx.y, d = threadIdx.x;
    int tpos = bt & (Tc-1);
    __shared__ float sxi[GDc], sq[GDc], sk[GDc], sred[GDc];
    size_t base = ((size_t)bt*NU + n)*GDc;
    sxi[d] = g_xi[base + d];
    __syncthreads();
    const float* w = qkv_w + (size_t)n * 192 * GDc;
    float q = 0.f, k = 0.f, v = 0.f;
    #pragma unroll 16
    for (int g = 0; g < GDc; g++) {
        float xg = sxi[g];
        q += xg * w[(     d)*GDc + g];
        k += xg * w[( 64 + d)*GDc + g];
        v += xg * w[(128 + d)*GDc + g];
    }
    g_v[base + d] = v;
    sq[d] = q; sk[d] = k;
    __syncthreads();
    if (d < 32) {
        float c = g_cos[tpos*32 + d], s = g_sin[tpos*32 + d];
        float q1 = sq[d], q2 = sq[d+32];
        sq[d] = q1*c + q2*s;  sq[d+32] = -q1*s + q2*c;
        float k1 = sk[d], k2 = sk[d+32];
        sk[d] = k1*c + k2*s;  sk[d+32] = -k1*s + k2*c;
    }
    __syncthreads();
    float qv = sq[d], kv = sk[d];
    sred[d] = qv*qv; __syncthreads();
    for (int s = 32; s > 0; s >>= 1) { if (d < s) sred[d] += sred[d+s]; __syncthreads(); }
    float qs = rsqrtf(sred[0] / (float)GDc + EPSc);
    __syncthreads();
    sred[d] = kv*kv; __syncthreads();
    for (int s = 32; s > 0; s >>= 1) { if (d < s) sred[d] += sred[d+s]; __syncthreads(); }
    float ks = rsqrtf(sred[0] / (float)GDc + EPSc);
    g_q[base + d] = qv * qs;
    g_k[base + d] = kv * ks;
}

// attention: one block per (t, n, b), 256 threads
__global__ void k_attn() {
    int t = blockIdx.x, n = blockIdx.y, b = blockIdx.z;
    int j = threadIdx.x;                   // 0..255
    __shared__ float sq[GDc], sp[Tc], sr[Tc], sacc[4][GDc];
    if (j < GDc) sq[j] = g_q[(((size_t)b*Tc + t)*NU + n)*GDc + j];
    __syncthreads();
    float sc = -1e30f;
    if (j <= t) {
        const float* kp = g_k + (((size_t)b*Tc + j)*NU + n)*GDc;
        float acc = 0.f;
        #pragma unroll 16
        for (int g = 0; g < GDc; g++) acc += sq[g]*kp[g];
        sc = acc * 0.125f;
    }
    sr[j] = sc; __syncthreads();
    for (int s = 128; s > 0; s >>= 1) { if (j < s) sr[j] = fmaxf(sr[j], sr[j+s]); __syncthreads(); }
    float m = sr[0]; __syncthreads();
    float e = (j <= t) ? expf(sc - m) : 0.f;
    sp[j] = e; sr[j] = e; __syncthreads();
    for (int s = 128; s > 0; s >>= 1) { if (j < s) sr[j] += sr[j+s]; __syncthreads(); }
    float inv = 1.f / sr[0];
    int g = j & 63, c = j >> 6;
    float acc = 0.f;
    for (int s = c; s <= t; s += 4)
        acc += sp[s] * g_v[(((size_t)b*Tc + s)*NU + n)*GDc + g];
    sacc[c][g] = acc; __syncthreads();
    if (j < GDc) {
        float a = (sacc[0][j] + sacc[1][j] + sacc[2][j] + sacc[3][j]) * inv;
        g_att[(((size_t)b*Tc + t)*NU + n)*GDc + j] = a;
    }
}

// mid/mlp: up = (att*apsum + fcsum*mpsum) * weff ; one block per (bt, n), 64 threads
__global__ void k_mlp(const float* __restrict__ mlp_fc, int step) {
    int bt = blockIdx.x, n = blockIdx.y, d = threadIdx.x;
    __shared__ float sy[GDc], sred[GDc];
    size_t base = ((size_t)bt*NU + n)*GDc;
    float xi  = g_xi [base + d];
    float att = g_att[base + d];
    float aps = g_apsum[n*GDc + d];
    float xm = xi + att * aps;
    sred[d] = xm*xm; __syncthreads();
    for (int s = 32; s > 0; s >>= 1) { if (d < s) sred[d] += sred[d+s]; __syncthreads(); }
    float r = rsqrtf(sred[0] / (float)GDc + EPSc);
    sy[d] = xm * r;
    __syncthreads();
    const float* fcw = mlp_fc + (size_t)n * 256 * GDc;
    float acc = 0.f;
    #pragma unroll
    for (int i = 0; i < 4; i++) {
        const float* wr = fcw + (size_t)(d + 64*i)*GDc;
        float f = 0.f;
        #pragma unroll 16
        for (int g = 0; g < GDc; g++) f += sy[g]*wr[g];
        f = fmaxf(f, 0.f);
        acc += f*f;
    }
    sred[d] = acc; __syncthreads();
    for (int s = 32; s > 0; s >>= 1) { if (d < s) sred[d] += sred[d+s]; __syncthreads(); }
    float fcsum = sred[0];
    float w = g_weff[step*NU + n];
    g_up[base + d] = (att*aps + fcsum * g_mpsum[n*GDc + d]) * w;
}

// sum over layers + x update + router; one block per bt, 512 threads
__global__ void k_update(const float* __restrict__ router_w, const float* __restrict__ router_b) {
    int bt = blockIdx.x;
    int e = threadIdx.x;                   // 512
    __shared__ float sred[Ec];
    int gi = e >> 6, gd = e & 63;
    float fu = 0.f;
    #pragma unroll
    for (int l = 0; l < Lc; l++)
        fu += g_up[((size_t)bt*NU + l*Gc + gi)*GDc + gd];
    float pc = g_pcont[bt];
    float xv = g_x[(size_t)bt*Ec + e] + fu * pc;
    g_x[(size_t)bt*Ec + e] = xv;
    sred[e] = xv * router_w[e];
    __syncthreads();
    for (int s = 256; s > 0; s >>= 1) { if (e < s) sred[e] += sred[e+s]; __syncthreads(); }
    if (e == 0) {
        float ph = 1.f / (1.f + expf(-(sred[0] + router_b[0])));
        g_pcont[bt] = pc * (1.f - ph);
    }
}

__global__ void k_rmsfinal() {
    int bt = blockIdx.x;
    int tx = threadIdx.x;                  // 256
    __shared__ float sred[256];
    float a = g_x[(size_t)bt*Ec + tx], b = g_x[(size_t)bt*Ec + tx + 256];
    sred[tx] = a*a + b*b;
    __syncthreads();
    for (int s = 128; s > 0; s >>= 1) { if (tx < s) sred[tx] += sred[tx+s]; __syncthreads(); }
    float r = rsqrtf(sred[0] / (float)Ec + EPSc);
    g_xn[(size_t)bt*Ec + tx]       = a*r;
    g_xn[(size_t)bt*Ec + tx + 256] = b*r;
}

// ---------------- launch ----------------
extern "C" void kernel_launch(void* const* d_in, const int* in_sizes, int n_in,
                              void* d_out, int out_size) {
    const int*   idx       = (const int*)  d_in[0];
    // d_in[1] = n_steps (always 8 by construction)
    const float* wte       = (const float*)d_in[2];
    const float* adapters  = (const float*)d_in[3];
    const float* qkv_w     = (const float*)d_in[4];
    const float* attn_proj = (const float*)d_in[5];
    const float* mlp_fc    = (const float*)d_in[6];
    const float* mlp_proj  = (const float*)d_in[7];
    const float* dep       = (const float*)d_in[8];
    const float* router_w  = (const float*)d_in[9];
    const float* router_b  = (const float*)d_in[10];
    const float* lm_head   = (const float*)d_in[11];
    float* out = (float*)d_out;

    float *px, *pxn, *padap, *pxi;
    cudaGetSymbolAddress((void**)&px,    g_x);
    cudaGetSymbolAddress((void**)&pxn,   g_xn);
    cudaGetSymbolAddress((void**)&padap, g_adap);
    cudaGetSymbolAddress((void**)&pxi,   g_xi);

    k_tables<<<Tc, 32>>>();
    k_depths<<<1, NU>>>(dep);
    k_sums<<<(NU*GDc + 255)/256, 256>>>(attn_proj, mlp_proj);
    k_adap<<<(NU*GDc*Ec)/256, 256>>>(adapters);
    k_embed<<<Bc*Tc, 256>>>(idx, wte);

    for (int t = 0; t < Sc; t++) {
        // xi = x @ adap'^T : M=512, N=4096, K=512
        gemm_nt<0><<<dim3(NU*GDc/64, Bc*Tc/64), 256>>>(px, padap, pxi, Bc*Tc, NU*GDc, Ec);
        k_qkv <<<dim3(Bc*Tc, NU), GDc>>>(qkv_w);
        k_attn<<<dim3(Tc, NU, Bc), 256>>>();
        k_mlp <<<dim3(Bc*Tc, NU), GDc>>>(mlp_fc, t);
        k_update<<<Bc*Tc, Ec>>>(router_w, router_b);
    }

    k_rmsfinal<<<Bc*Tc, 256>>>();
    // logits: M=512, N=50257, K=512, with 15*tanh(/15) epilogue
    gemm_nt<1><<<dim3((Vc + 63)/64, Bc*Tc/64), 256>>>(pxn, lm_head, out, Bc*Tc, Vc, Ec);
}

// round 2
// speedup vs baseline: 12.2699x; 12.2699x over previous
#include <cuda_runtime.h>
#include <math.h>
#include <stdint.h>

#define Bc 2
#define Tc 256
#define Ec 512
#define Gc 8
#define GDc 64
#define Lc 8
#define NU 64
#define Vc 50257
#define Sc 8
#define EPSc 1.1920929e-7f

// ---------------- device scratch (no allocations allowed) ----------------
__device__ float g_x[Bc*Tc*Ec];
__device__ float g_xn[Bc*Tc*Ec];
__device__ float g_pcont[Bc*Tc];
__device__ float g_cos[Tc*32];
__device__ float g_sin[Tc*32];
__device__ float g_weff[Sc*NU];
__device__ float g_apsum[NU*GDc];
__device__ float g_mpsum[NU*GDc];
__device__ float g_adap[NU*GDc*Ec];          // adapters + folded identity skip
// n-major activations: [n][bt][gd]
__device__ float g_xi [NU*Bc*Tc*GDc];
__device__ float g_q  [NU*Bc*Tc*GDc];
__device__ float g_k  [NU*Bc*Tc*GDc];
__device__ float g_v  [NU*Bc*Tc*GDc];
__device__ float g_att[NU*Bc*Tc*GDc];
__device__ float g_y  [NU*Bc*Tc*GDc];
__device__ float g_fcsum[NU*Bc*Tc];
__device__ float g_scores[Bc*NU*Tc*Tc];      // [b*64+n][t][s]

// ---------------- prep kernels ----------------
__global__ void k_tables() {
    int t = blockIdx.x, i = threadIdx.x;   // i < 32
    double invf = pow(10000.0, -((double)(2*i)) / (double)GDc);
    double f = (double)t * invf;
    g_cos[t*32+i] = (float)cos(f);
    g_sin[t*32+i] = (float)sin(f);
}

__global__ void k_depths(const float* __restrict__ dep) {
    int n = threadIdx.x;                   // 64 threads
    __shared__ float d0[NU], d1[NU];
    d0[n] = 0.f; __syncthreads();
    for (int it = 0; it < Lc; it++) {
        float acc = 0.f;
        for (int j = 0; j < NU; j++)
            acc += fmaxf(dep[n*NU+j], 0.f) * (d0[j] + 1.f);
        d1[n] = acc; __syncthreads();
        d0[n] = d1[n]; __syncthreads();
    }
    float dn = d0[n];
    for (int t = 0; t < Sc; t++) {
        float td = (float)t * ((float)Lc / (float)Sc);
        float w = expf(-fabsf(dn - td));
        g_weff[t*NU+n] = (w > 0.15f) ? w : 0.f;
    }
}

__global__ void k_sums(const float* __restrict__ ap, const float* __restrict__ mp) {
    int i = blockIdx.x*blockDim.x + threadIdx.x;    // < 4096 = (n*64+g)
    if (i >= NU*GDc) return;
    float s = 0.f;
    for (int k = 0; k < GDc; k++) s += ap[i*GDc + k];
    g_apsum[i] = s;
    float s2 = 0.f;
    for (int k = 0; k < 4*GDc; k++) s2 += mp[i*4*GDc + k];
    g_mpsum[i] = s2;
}

__global__ void k_adap(const float* __restrict__ adapters) {
    int tid = blockIdx.x*blockDim.x + threadIdx.x;  // < 64*64*512
    int row = tid >> 9;        // n*64+g
    int e   = tid & 511;
    int n = row >> 6, g = row & 63;
    float add = (e == ((n & (Gc-1))*GDc + g)) ? 1.f : 0.f;
    g_adap[tid] = adapters[tid] + add;
}

__global__ void k_embed(const int* __restrict__ idx, const float* __restrict__ wte) {
    int bt = blockIdx.x;
    int tx = threadIdx.x;                  // 256
    __shared__ float sred[256];
    int row = idx[bt];
    const float* w = wte + (size_t)row * Ec;
    float a = w[tx], b = w[tx+256];
    sred[tx] = a*a + b*b;
    __syncthreads();
    for (int s = 128; s > 0; s >>= 1) { if (tx < s) sred[tx] += sred[tx+s]; __syncthreads(); }
    float r = rsqrtf(sred[0] / (float)Ec + EPSc);
    g_x[(size_t)bt*Ec + tx]       = a*r;
    g_x[(size_t)bt*Ec + tx + 256] = b*r;
    if (tx == 0) g_pcont[bt] = 1.f;
}

// ---------------- GEMM: C[m,n] = sum_k A[m,k]*B[n,k]  (both row-major, K-contig) ----------------
// MODE 0: plain store.  MODE 1: 15*tanh(c/15).  MODE 2: scatter to n-major xi layout.
template<int MODE>
__global__ void gemm_nt(const float* __restrict__ A, const float* __restrict__ B,
                        float* __restrict__ C, int M, int N, int K) {
    const int BM = 64, BN = 64, BK = 16;
    __shared__ float As[BK][BM];
    __shared__ float Bs[BK][BN];
    int bm = blockIdx.y * BM, bn = blockIdx.x * BN;
    int tx = threadIdx.x;                  // 256 threads
    int tcol = (tx & 15) * 4;
    int trow = (tx >> 4) * 4;
    float acc[4][4] = {};
    for (int k0 = 0; k0 < K; k0 += BK) {
        #pragma unroll
        for (int i = tx; i < BM*BK; i += 256) {
            int r = i / BK, c = i % BK;
            As[c][r] = (bm + r < M) ? A[(size_t)(bm+r)*K + k0 + c] : 0.f;
        }
        #pragma unroll
        for (int i = tx; i < BN*BK; i += 256) {
            int r = i / BK, c = i % BK;
            Bs[c][r] = (bn + r < N) ? B[(size_t)(bn+r)*K + k0 + c] : 0.f;
        }
        __syncthreads();
        #pragma unroll
        for (int kk = 0; kk < BK; kk++) {
            float a[4], b[4];
            #pragma unroll
            for (int i = 0; i < 4; i++) a[i] = As[kk][trow+i];
            #pragma unroll
            for (int j = 0; j < 4; j++) b[j] = Bs[kk][tcol+j];
            #pragma unroll
            for (int i = 0; i < 4; i++)
                #pragma unroll
                for (int j = 0; j < 4; j++) acc[i][j] += a[i]*b[j];
        }
        __syncthreads();
    }
    #pragma unroll
    for (int i = 0; i < 4; i++) {
        int m = bm + trow + i; if (m >= M) continue;
        #pragma unroll
        for (int j = 0; j < 4; j++) {
            int n = bn + tcol + j; if (n >= N) continue;
            float v = acc[i][j];
            if (MODE == 1) v = 15.f * tanhf(v / 15.f);
            if (MODE == 2) {
                // column n -> (unit = n>>6, g = n&63); store [unit][m][g]
                C[(size_t)((n >> 6) * M + m) * GDc + (n & 63)] = v;
            } else {
                C[(size_t)m*N + n] = v;
            }
        }
    }
}

// ---------------- per-step kernels ----------------
// batched qkv GEMM: grid (bt_tile=8, n=64, z=3); 64x64x64 per block
__global__ void k_qkvgemm(const float* __restrict__ qkv_w) {
    __shared__ float As[64][65];   // As[k][m] = xi[m][k]
    __shared__ float Bs[64][65];   // Bs[k][o] = w[o][k]
    int btile = blockIdx.x, n = blockIdx.y, z = blockIdx.z;
    int tx = threadIdx.x;
    const float* Ab = g_xi + ((size_t)n*Bc*Tc + btile*64)*GDc;
    const float* Wb = qkv_w + ((size_t)n*192 + z*64)*GDc;
    #pragma unroll
    for (int i = tx; i < 64*64; i += 256) {
        int r = i >> 6, c = i & 63;
        As[c][r] = Ab[i];
        Bs[c][r] = Wb[i];
    }
    __syncthreads();
    int tcol = (tx & 15)*4, trow = (tx >> 4)*4;
    float acc[4][4] = {};
    #pragma unroll
    for (int k = 0; k < 64; k++) {
        float a[4], b[4];
        #pragma unroll
        for (int i = 0; i < 4; i++) a[i] = As[k][trow+i];
        #pragma unroll
        for (int j = 0; j < 4; j++) b[j] = Bs[k][tcol+j];
        #pragma unroll
        for (int i = 0; i < 4; i++)
            #pragma unroll
            for (int j = 0; j < 4; j++) acc[i][j] += a[i]*b[j];
    }
    float* Ob = (z == 0 ? g_q : z == 1 ? g_k : g_v) + ((size_t)n*Bc*Tc + btile*64)*GDc;
    #pragma unroll
    for (int i = 0; i < 4; i++)
        #pragma unroll
        for (int j = 0; j < 4; j++)
            Ob[(trow+i)*GDc + tcol+j] = acc[i][j];
}

// rope + rms for q and k; 32 lanes per row, 8 rows per block
__global__ void k_roperms() {
    int lane = threadIdx.x & 31;
    int row  = blockIdx.x * 8 + (threadIdx.x >> 5);   // row = n*512 + bt
    int t = row & (Tc-1);
    float c = g_cos[t*32 + lane], s = g_sin[t*32 + lane];
    {
        float* qp = g_q + (size_t)row*GDc;
        float x1 = qp[lane], x2 = qp[lane+32];
        float n1 = x1*c + x2*s, n2 = -x1*s + x2*c;
        float ss = n1*n1 + n2*n2;
        #pragma unroll
        for (int o = 16; o; o >>= 1) ss += __shfl_xor_sync(0xFFFFFFFFu, ss, o);
        float r = rsqrtf(ss / (float)GDc + EPSc);
        qp[lane] = n1*r; qp[lane+32] = n2*r;
    }
    {
        float* kp = g_k + (size_t)row*GDc;
        float x1 = kp[lane], x2 = kp[lane+32];
        float n1 = x1*c + x2*s, n2 = -x1*s + x2*c;
        float ss = n1*n1 + n2*n2;
        #pragma unroll
        for (int o = 16; o; o >>= 1) ss += __shfl_xor_sync(0xFFFFFFFFu, ss, o);
        float r = rsqrtf(ss / (float)GDc + EPSc);
        kp[lane] = n1*r; kp[lane+32] = n2*r;
    }
}

// scores = Q K^T * scale, lower-triangle tiles only; grid (ts=4, tq=4, bn=128)
__global__ void k_scores() {
    int ts = blockIdx.x, tq = blockIdx.y, bn = blockIdx.z;
    if (ts > tq) return;
    int n = bn & 63, b = bn >> 6;
    __shared__ float As[64][65];   // Q^T
    __shared__ float Bs[64][65];   // K^T
    int tx = threadIdx.x;
    const float* Qb = g_q + ((size_t)n*Bc*Tc + b*Tc + tq*64)*GDc;
    const float* Kb = g_k + ((size_t)n*Bc*Tc + b*Tc + ts*64)*GDc;
    #pragma unroll
    for (int i = tx; i < 64*64; i += 256) {
        int r = i >> 6, c = i & 63;
        As[c][r] = Qb[i];
        Bs[c][r] = Kb[i];
    }
    __syncthreads();
    int tcol = (tx & 15)*4, trow = (tx >> 4)*4;
    float acc[4][4] = {};
    #pragma unroll
    for (int k = 0; k < 64; k++) {
        float a[4], bv[4];
        #pragma unroll
        for (int i = 0; i < 4; i++) a[i] = As[k][trow+i];
        #pragma unroll
        for (int j = 0; j < 4; j++) bv[j] = Bs[k][tcol+j];
        #pragma unroll
        for (int i = 0; i < 4; i++)
            #pragma unroll
            for (int j = 0; j < 4; j++) acc[i][j] += a[i]*bv[j];
    }
    float* Sb = g_scores + (size_t)bn*Tc*Tc;
    #pragma unroll
    for (int i = 0; i < 4; i++) {
        int t = tq*64 + trow + i;
        #pragma unroll
        for (int j = 0; j < 4; j++)
            Sb[(size_t)t*Tc + ts*64 + tcol + j] = acc[i][j] * 0.125f;
    }
}

// rowwise softmax over valid prefix; writes zeros above diagonal
__global__ void k_softmax() {
    int t = blockIdx.x, bn = blockIdx.y;
    int j = threadIdx.x;                   // 256
    float* rowp = g_scores + ((size_t)bn*Tc + t)*Tc;
    __shared__ float sw[8];
    float sc = (j <= t) ? rowp[j] : -1e30f;
    float m = sc;
    #pragma unroll
    for (int o = 16; o; o >>= 1) m = fmaxf(m, __shfl_xor_sync(0xFFFFFFFFu, m, o));
    if ((j & 31) == 0) sw[j >> 5] = m;
    __syncthreads();
    if (j < 8) {
        float v = sw[j];
        #pragma unroll
        for (int o = 4; o; o >>= 1) v = fmaxf(v, __shfl_xor_sync(0xFFu, v, o));
        sw[j] = v;
    }
    __syncthreads();
    m = sw[0];
    float e = (j <= t) ? expf(sc - m) : 0.f;
    __syncthreads();
    float su = e;
    #pragma unroll
    for (int o = 16; o; o >>= 1) su += __shfl_xor_sync(0xFFFFFFFFu, su, o);
    if ((j & 31) == 0) sw[j >> 5] = su;
    __syncthreads();
    if (j < 8) {
        float v = sw[j];
        #pragma unroll
        for (int o = 4; o; o >>= 1) v += __shfl_xor_sync(0xFFu, v, o);
        sw[j] = v;
    }
    __syncthreads();
    rowp[j] = e / sw[0];
}

// att = P @ V ; grid (tq=4, bn=128); skips upper k-tiles
__global__ void k_av() {
    int tq = blockIdx.x, bn = blockIdx.y;
    int n = bn & 63, b = bn >> 6;
    __shared__ float Ps[64][65];   // Ps[m][k]
    __shared__ float Vs[64][65];   // Vs[k][g]
    int tx = threadIdx.x;
    int tcol = (tx & 15)*4, trow = (tx >> 4)*4;
    float acc[4][4] = {};
    const float* Pb = g_scores + ((size_t)bn*Tc + tq*64)*Tc;
    for (int kt = 0; kt <= tq; kt++) {
        const float* Vb = g_v + ((size_t)n*Bc*Tc + b*Tc + kt*64)*GDc;
        #pragma unroll
        for (int i = tx; i < 64*64; i += 256) {
            int r = i >> 6, c = i & 63;
            Ps[r][c] = Pb[(size_t)r*Tc + kt*64 + c];
            Vs[r][c] = Vb[i];
        }
        __syncthreads();
        #pragma unroll
        for (int k = 0; k < 64; k++) {
            float a[4], bv[4];
            #pragma unroll
            for (int i = 0; i < 4; i++) a[i] = Ps[trow+i][k];
            #pragma unroll
            for (int j = 0; j < 4; j++) bv[j] = Vs[k][tcol+j];
            #pragma unroll
            for (int i = 0; i < 4; i++)
                #pragma unroll
                for (int j = 0; j < 4; j++) acc[i][j] += a[i]*bv[j];
        }
        __syncthreads();
    }
    float* Ob = g_att + ((size_t)n*Bc*Tc + b*Tc + tq*64)*GDc;
    #pragma unroll
    for (int i = 0; i < 4; i++)
        #pragma unroll
        for (int j = 0; j < 4; j++)
            Ob[(trow+i)*GDc + tcol+j] = acc[i][j];
}

// y = rms(xi + att*apsum) ; 32 lanes per row, 8 rows per block
__global__ void k_mid() {
    int lane = threadIdx.x & 31;
    int row  = blockIdx.x * 8 + (threadIdx.x >> 5);   // row = n*512 + bt
    int n = row >> 9;
    const float* xip = g_xi + (size_t)row*GDc;
    const float* atp = g_att + (size_t)row*GDc;
    const float* app = g_apsum + n*GDc;
    float x1 = xip[lane]    + atp[lane]   *app[lane];
    float x2 = xip[lane+32] + atp[lane+32]*app[lane+32];
    float ss = x1*x1 + x2*x2;
    #pragma unroll
    for (int o = 16; o; o >>= 1) ss += __shfl_xor_sync(0xFFFFFFFFu, ss, o);
    float r = rsqrtf(ss / (float)GDc + EPSc);
    float* yp = g_y + (size_t)row*GDc;
    yp[lane] = x1*r; yp[lane+32] = x2*r;
}

// fcsum = sum_o relu(y @ fc^T)^2 ; grid (bt_tile=8, n=64)
__global__ void k_fc(const float* __restrict__ mlp_fc) {
    __shared__ float Ys[64][65];   // Ys[m][k]
    __shared__ float Ws[64][65];   // Ws[k][o]
    int btile = blockIdx.x, n = blockIdx.y;
    int tx = threadIdx.x;
    const float* Yb = g_y + ((size_t)n*Bc*Tc + btile*64)*GDc;
    #pragma unroll
    for (int i = tx; i < 64*64; i += 256) {
        int r = i >> 6, c = i & 63;
        Ys[r][c] = Yb[i];
    }
    int tcol = (tx & 15)*4, trow = (tx >> 4)*4;
    float rowacc[4] = {};
    for (int ot = 0; ot < 4; ot++) {
        const float* Wb = mlp_fc + ((size_t)n*256 + ot*64)*GDc;
        #pragma unroll
        for (int i = tx; i < 64*64; i += 256) {
            int r = i >> 6, c = i & 63;
            Ws[c][r] = Wb[i];       // transposed, conflict-free (stride 65)
        }
        __syncthreads();
        float acc[4][4] = {};
        #pragma unroll
        for (int k = 0; k < 64; k++) {
            float a[4], bv[4];
            #pragma unroll
            for (int i = 0; i < 4; i++) a[i] = Ys[trow+i][k];
            #pragma unroll
            for (int j = 0; j < 4; j++) bv[j] = Ws[k][tcol+j];
            #pragma unroll
            for (int i = 0; i < 4; i++)
                #pragma unroll
                for (int j = 0; j < 4; j++) acc[i][j] += a[i]*bv[j];
        }
        #pragma unroll
        for (int i = 0; i < 4; i++)
            #pragma unroll
            for (int j = 0; j < 4; j++) {
                float f = fmaxf(acc[i][j], 0.f);
                rowacc[i] += f*f;
            }
        __syncthreads();
    }
    // reduce across the 16 threads of the same row group (consecutive lanes)
    #pragma unroll
    for (int i = 0; i < 4; i++) {
        float v = rowacc[i];
        #pragma unroll
        for (int o = 8; o; o >>= 1) v += __shfl_xor_sync(0xFFFFFFFFu, v, o, 16);
        if ((tx & 15) == 0)
            g_fcsum[(size_t)n*Bc*Tc + btile*64 + trow + i] = v;
    }
}

// x update + router; one block per bt, 512 threads
__global__ void k_update(const float* __restrict__ router_w, const float* __restrict__ router_b, int step) {
    int bt = blockIdx.x;
    int e = threadIdx.x;                   // 512
    __shared__ float sred[Ec];
    int gi = e >> 6, gd = e & 63;
    float fu = 0.f;
    #pragma unroll
    for (int l = 0; l < Lc; l++) {
        int n = l*Gc + gi;
        size_t row = (size_t)n*Bc*Tc + bt;
        float att = g_att[row*GDc + gd];
        float aps = g_apsum[n*GDc + gd];
        float fcs = g_fcsum[row];
        float mps = g_mpsum[n*GDc + gd];
        float w   = g_weff[step*NU + n];
        fu += (att*aps + fcs*mps) * w;
    }
    float pc = g_pcont[bt];
    float xv = g_x[(size_t)bt*Ec + e] + fu * pc;
    g_x[(size_t)bt*Ec + e] = xv;
    sred[e] = xv * router_w[e];
    __syncthreads();
    for (int s = 256; s > 0; s >>= 1) { if (e < s) sred[e] += sred[e+s]; __syncthreads(); }
    if (e == 0) {
        float ph = 1.f / (1.f + expf(-(sred[0] + router_b[0])));
        g_pcont[bt] = pc * (1.f - ph);
    }
}

__global__ void k_rmsfinal() {
    int bt = blockIdx.x;
    int tx = threadIdx.x;                  // 256
    __shared__ float sred[256];
    float a = g_x[(size_t)bt*Ec + tx], b = g_x[(size_t)bt*Ec + tx + 256];
    sred[tx] = a*a + b*b;
    __syncthreads();
    for (int s = 128; s > 0; s >>= 1) { if (tx < s) sred[tx] += sred[tx+s]; __syncthreads(); }
    float r = rsqrtf(sred[0] / (float)Ec + EPSc);
    g_xn[(size_t)bt*Ec + tx]       = a*r;
    g_xn[(size_t)bt*Ec + tx + 256] = b*r;
}

// ---------------- launch ----------------
extern "C" void kernel_launch(void* const* d_in, const int* in_sizes, int n_in,
                              void* d_out, int out_size) {
    const int*   idx       = (const int*)  d_in[0];
    // d_in[1] = n_steps (always 8 by construction)
    const float* wte       = (const float*)d_in[2];
    const float* adapters  = (const float*)d_in[3];
    const float* qkv_w     = (const float*)d_in[4];
    const float* attn_proj = (const float*)d_in[5];
    const float* mlp_fc    = (const float*)d_in[6];
    const float* mlp_proj  = (const float*)d_in[7];
    const float* dep       = (const float*)d_in[8];
    const float* router_w  = (const float*)d_in[9];
    const float* router_b  = (const float*)d_in[10];
    const float* lm_head   = (const float*)d_in[11];
    float* out = (float*)d_out;

    float *px, *pxn, *padap, *pxi;
    cudaGetSymbolAddress((void**)&px,    g_x);
    cudaGetSymbolAddress((void**)&pxn,   g_xn);
    cudaGetSymbolAddress((void**)&padap, g_adap);
    cudaGetSymbolAddress((void**)&pxi,   g_xi);

    k_tables<<<Tc, 32>>>();
    k_depths<<<1, NU>>>(dep);
    k_sums<<<(NU*GDc + 255)/256, 256>>>(attn_proj, mlp_proj);
    k_adap<<<(NU*GDc*Ec)/256, 256>>>(adapters);
    k_embed<<<Bc*Tc, 256>>>(idx, wte);

    for (int t = 0; t < Sc; t++) {
        // xi = x @ adap^T, scatter-stored n-major: M=512, N=4096, K=512
        gemm_nt<2><<<dim3(NU*GDc/64, Bc*Tc/64), 256>>>(px, padap, pxi, Bc*Tc, NU*GDc, Ec);
        k_qkvgemm<<<dim3(Bc*Tc/64, NU, 3), 256>>>(qkv_w);
        k_roperms<<<NU*Bc*Tc/8, 256>>>();
        k_scores<<<dim3(4, 4, Bc*NU), 256>>>();
        k_softmax<<<dim3(Tc, Bc*NU), 256>>>();
        k_av<<<dim3(4, Bc*NU), 256>>>();
        k_mid<<<NU*Bc*Tc/8, 256>>>();
        k_fc<<<dim3(Bc*Tc/64, NU), 256>>>(mlp_fc);
        k_update<<<Bc*Tc, Ec>>>(router_w, router_b, t);
    }

    k_rmsfinal<<<Bc*Tc, 256>>>();
    // logits: M=512, N=50257, K=512, with 15*tanh(/15) epilogue
    gemm_nt<1><<<dim3((Vc + 63)/64, Bc*Tc/64), 256>>>(pxn, lm_head, out, Bc*Tc, Vc, Ec);
}

// round 6
// speedup vs baseline: 25.9929x; 2.1184x over previous
#include <cuda_runtime.h>
#include <cuda_bf16.h>
#include <math.h>
#include <stdint.h>

#define Bc 2
#define Tc 256
#define Ec 512
#define Gc 8
#define GDc 64
#define Lc 8
#define NU 64
#define Vc 50257
#define VPAD 50304
#define Sc 8
#define EPSc 1.1920929e-7f

// ---------------- device scratch (no allocations allowed) ----------------
__device__ float g_x[Bc*Tc*Ec];
__device__ float g_xn[Bc*Tc*Ec];
__device__ float g_pcont[Bc*Tc];
__device__ float g_cos[Tc*32];
__device__ float g_sin[Tc*32];
__device__ float g_weff[Sc*NU];
__device__ float g_apsum[NU*GDc];
__device__ float g_mpsum[NU*GDc];
__device__ float g_adap[NU*GDc*Ec];          // adapters + folded identity skip
// n-major activations: [n][bt][gd]
__device__ float g_xi [NU*Bc*Tc*GDc];
__device__ float g_q  [NU*Bc*Tc*GDc];
__device__ float g_k  [NU*Bc*Tc*GDc];
__device__ float g_v  [NU*Bc*Tc*GDc];
__device__ float g_att[NU*Bc*Tc*GDc];
__device__ float g_y  [NU*Bc*Tc*GDc];
__device__ float g_fcsum[NU*Bc*Tc];
__device__ float g_scores[Bc*NU*Tc*Tc];      // [b*64+n][t][s]
// pre-split bf16 weights (hi/lo), 16B-aligned for vector loads
__device__ __align__(16) __nv_bfloat16 g_adap_h[NU*GDc*Ec], g_adap_l[NU*GDc*Ec];
__device__ __align__(16) __nv_bfloat16 g_fcw_h[NU*256*GDc], g_fcw_l[NU*256*GDc];
__device__ __align__(16) __nv_bfloat16 g_lmh_h[VPAD*Ec],    g_lmh_l[VPAD*Ec];

// ---------------- mma helper (baseline PTX, valid on sm_103 non-a) ----------------
__device__ __forceinline__ void mma_bf16(float* d, const uint32_t* a, uint32_t b0, uint32_t b1) {
    asm volatile("mma.sync.aligned.m16n8k16.row.col.f32.bf16.bf16.f32 "
        "{%0,%1,%2,%3}, {%4,%5,%6,%7}, {%8,%9}, {%0,%1,%2,%3};"
        : "+f"(d[0]), "+f"(d[1]), "+f"(d[2]), "+f"(d[3])
        : "r"(a[0]), "r"(a[1]), "r"(a[2]), "r"(a[3]), "r"(b0), "r"(b1));
}

// ---------------- prep kernels ----------------
__global__ void k_tables() {
    int t = blockIdx.x, i = threadIdx.x;   // i < 32
    double invf = pow(10000.0, -((double)(2*i)) / (double)GDc);
    double f = (double)t * invf;
    g_cos[t*32+i] = (float)cos(f);
    g_sin[t*32+i] = (float)sin(f);
}

__global__ void k_depths(const float* __restrict__ dep) {
    int n = threadIdx.x;                   // 64 threads
    __shared__ float d0[NU], d1[NU];
    d0[n] = 0.f; __syncthreads();
    for (int it = 0; it < Lc; it++) {
        float acc = 0.f;
        for (int j = 0; j < NU; j++)
            acc += fmaxf(dep[n*NU+j], 0.f) * (d0[j] + 1.f);
        d1[n] = acc; __syncthreads();
        d0[n] = d1[n]; __syncthreads();
    }
    float dn = d0[n];
    for (int t = 0; t < Sc; t++) {
        float td = (float)t * ((float)Lc / (float)Sc);
        float w = expf(-fabsf(dn - td));
        g_weff[t*NU+n] = (w > 0.15f) ? w : 0.f;
    }
}

__global__ void k_sums(const float* __restrict__ ap, const float* __restrict__ mp) {
    int i = blockIdx.x*blockDim.x + threadIdx.x;    // < 4096 = (n*64+g)
    if (i >= NU*GDc) return;
    float s = 0.f;
    for (int k = 0; k < GDc; k++) s += ap[i*GDc + k];
    g_apsum[i] = s;
    float s2 = 0.f;
    for (int k = 0; k < 4*GDc; k++) s2 += mp[i*4*GDc + k];
    g_mpsum[i] = s2;
}

__global__ void k_adap(const float* __restrict__ adapters) {
    int tid = blockIdx.x*blockDim.x + threadIdx.x;  // < 64*64*512
    int row = tid >> 9;        // n*64+g
    int e   = tid & 511;
    int n = row >> 6, g = row & 63;
    float add = (e == ((n & (Gc-1))*GDc + g)) ? 1.f : 0.f;
    g_adap[tid] = adapters[tid] + add;
}

// split fp32 -> bf16 hi/lo, zero beyond n_src (for padded rows)
__global__ void k_split(const float* __restrict__ src, __nv_bfloat16* __restrict__ h,
                        __nv_bfloat16* __restrict__ l, int n_src, int n_pad) {
    int i = blockIdx.x*blockDim.x + threadIdx.x;
    if (i >= n_pad) return;
    float v = (i < n_src) ? src[i] : 0.f;
    __nv_bfloat16 hv = __float2bfloat16(v);
    h[i] = hv;
    l[i] = __float2bfloat16(v - __bfloat162float(hv));
}

__global__ void k_embed(const int* __restrict__ idx, const float* __restrict__ wte) {
    int bt = blockIdx.x;
    int tx = threadIdx.x;                  // 256
    __shared__ float sred[256];
    int row = idx[bt];
    const float* w = wte + (size_t)row * Ec;
    float a = w[tx], b = w[tx+256];
    sred[tx] = a*a + b*b;
    __syncthreads();
    for (int s = 128; s > 0; s >>= 1) { if (tx < s) sred[tx] += sred[tx+s]; __syncthreads(); }
    float r = rsqrtf(sred[0] / (float)Ec + EPSc);
    g_x[(size_t)bt*Ec + tx]       = a*r;
    g_x[(size_t)bt*Ec + tx + 256] = b*r;
    if (tx == 0) g_pcont[bt] = 1.f;
}

// ---------------- HMMA split-bf16 GEMM ----------------
// C[m,n] = sum_k A[m,k]*B[n,k]. A fp32 (split in-kernel), B pre-split bf16 hi/lo.
// Block tile 128x128, K chunk 64. 8 warps: wm=wid&3 (M), wn=wid>>2 (N).
// MODE 1: 15*tanh(c/15) + guard N (scalar stores; N may be odd).
// MODE 2: scatter to n-major xi layout (N mult of 128).
// smem: Ah[128*72], Al, Bh[128*72], Bl bf16 (72-elem stride: conflict-free frags)
#define SG_AH 0
#define SG_AL 18432
#define SG_BH 36864
#define SG_BL 55296
#define SMEM_G 73728

template<int MODE>
__global__ void __launch_bounds__(256) mma_gemm(
    const float* __restrict__ A, const __nv_bfloat16* __restrict__ Bh,
    const __nv_bfloat16* __restrict__ Bl, float* __restrict__ C,
    int M, int N, int K)
{
    extern __shared__ char sm[];
    int tx = threadIdx.x, wid = tx >> 5, lane = tx & 31;
    int wm = wid & 3, wn = wid >> 2;
    int bm = blockIdx.y * 128, bn = blockIdx.x * 128;

    float acc[2][8][4];
    #pragma unroll
    for (int i = 0; i < 2; i++)
        #pragma unroll
        for (int j = 0; j < 8; j++)
            #pragma unroll
            for (int q = 0; q < 4; q++) acc[i][j][q] = 0.f;

    int nchunks = K >> 6;
    for (int ch = 0; ch < nchunks; ch++) {
        int k0 = ch << 6;
        // stage A (fp32 -> split bf16)
        #pragma unroll
        for (int i = tx; i < 2048; i += 256) {
            int r = i >> 4, c4 = (i & 15) << 2;
            float4 v = *(const float4*)(A + (size_t)(bm + r) * K + k0 + c4);
            __nv_bfloat16 h0 = __float2bfloat16(v.x), h1 = __float2bfloat16(v.y);
            __nv_bfloat16 h2 = __float2bfloat16(v.z), h3 = __float2bfloat16(v.w);
            __nv_bfloat16 l0 = __float2bfloat16(v.x - __bfloat162float(h0));
            __nv_bfloat16 l1 = __float2bfloat16(v.y - __bfloat162float(h1));
            __nv_bfloat16 l2 = __float2bfloat16(v.z - __bfloat162float(h2));
            __nv_bfloat16 l3 = __float2bfloat16(v.w - __bfloat162float(h3));
            uint2 hw, lw;
            hw.x = (uint32_t)__bfloat16_as_ushort(h0) | ((uint32_t)__bfloat16_as_ushort(h1) << 16);
            hw.y = (uint32_t)__bfloat16_as_ushort(h2) | ((uint32_t)__bfloat16_as_ushort(h3) << 16);
            lw.x = (uint32_t)__bfloat16_as_ushort(l0) | ((uint32_t)__bfloat16_as_ushort(l1) << 16);
            lw.y = (uint32_t)__bfloat16_as_ushort(l2) | ((uint32_t)__bfloat16_as_ushort(l3) << 16);
            uint32_t off = (uint32_t)(r * 72 + c4) * 2;
            *(uint2*)(sm + SG_AH + off) = hw;
            *(uint2*)(sm + SG_AL + off) = lw;
        }
        // stage B (pre-split bf16, padded rows -> no guard)
        #pragma unroll
        for (int i = tx; i < 2048; i += 256) {
            int r = i >> 4, c4 = (i & 15) << 2;
            size_t g = (size_t)(bn + r) * K + k0 + c4;
            uint32_t off = (uint32_t)(r * 72 + c4) * 2;
            *(uint2*)(sm + SG_BH + off) = *(const uint2*)(Bh + g);
            *(uint2*)(sm + SG_BL + off) = *(const uint2*)(Bl + g);
        }
        __syncthreads();
        #pragma unroll
        for (int ks = 0; ks < 4; ks++) {
            uint32_t ah[2][4], al[2][4];
            #pragma unroll
            for (int mi = 0; mi < 2; mi++) {
                uint32_t ro = (uint32_t)((wm*32 + mi*16 + (lane >> 2)) * 72 + ks*16 + (lane & 3)*2);
                ah[mi][0] = *(const uint32_t*)(sm + SG_AH + ro*2);
                ah[mi][1] = *(const uint32_t*)(sm + SG_AH + (ro + 8*72)*2);
                ah[mi][2] = *(const uint32_t*)(sm + SG_AH + (ro + 8)*2);
                ah[mi][3] = *(const uint32_t*)(sm + SG_AH + (ro + 8*72 + 8)*2);
                al[mi][0] = *(const uint32_t*)(sm + SG_AL + ro*2);
                al[mi][1] = *(const uint32_t*)(sm + SG_AL + (ro + 8*72)*2);
                al[mi][2] = *(const uint32_t*)(sm + SG_AL + (ro + 8)*2);
                al[mi][3] = *(const uint32_t*)(sm + SG_AL + (ro + 8*72 + 8)*2);
            }
            #pragma unroll
            for (int ni = 0; ni < 8; ni++) {
                uint32_t bo = (uint32_t)((wn*64 + ni*8 + (lane >> 2)) * 72 + ks*16 + (lane & 3)*2);
                uint32_t bh0 = *(const uint32_t*)(sm + SG_BH + bo*2);
                uint32_t bh1 = *(const uint32_t*)(sm + SG_BH + (bo + 8)*2);
                uint32_t bl0 = *(const uint32_t*)(sm + SG_BL + bo*2);
                uint32_t bl1 = *(const uint32_t*)(sm + SG_BL + (bo + 8)*2);
                #pragma unroll
                for (int mi = 0; mi < 2; mi++) {
                    mma_bf16(acc[mi][ni], ah[mi], bh0, bh1);
                    mma_bf16(acc[mi][ni], ah[mi], bl0, bl1);
                    mma_bf16(acc[mi][ni], al[mi], bh0, bh1);
                }
            }
        }
        __syncthreads();
    }

    // epilogue straight from registers
    #pragma unroll
    for (int mi = 0; mi < 2; mi++) {
        int m = bm + wm*32 + mi*16 + (lane >> 2);
        #pragma unroll
        for (int ni = 0; ni < 8; ni++) {
            int n = bn + wn*64 + ni*8 + (lane & 3)*2;
            float v0 = acc[mi][ni][0], v1 = acc[mi][ni][1];
            float v2 = acc[mi][ni][2], v3 = acc[mi][ni][3];
            if (MODE == 1) {
                // scalar stores: N (=50257) is odd so float2 would misalign
                if (n < N) {
                    C[(size_t)m*N + n]     = 15.f*tanhf(v0*(1.f/15.f));
                    C[(size_t)(m+8)*N + n] = 15.f*tanhf(v2*(1.f/15.f));
                }
                if (n + 1 < N) {
                    C[(size_t)m*N + n + 1]     = 15.f*tanhf(v1*(1.f/15.f));
                    C[(size_t)(m+8)*N + n + 1] = 15.f*tanhf(v3*(1.f/15.f));
                }
            } else { // MODE 2: scatter to [unit][m][g]; stride 64 -> aligned
                size_t b0 = ((size_t)(n >> 6) * M + m) * GDc + (n & 63);
                size_t b2 = ((size_t)(n >> 6) * M + m + 8) * GDc + (n & 63);
                *(float2*)(C + b0) = make_float2(v0, v1);
                *(float2*)(C + b2) = make_float2(v2, v3);
            }
        }
    }
}

// ---------------- fc via HMMA: fcsum = sum_o relu(y @ W^T)^2 ----------------
// grid (4 btiles, 64 units), block 256. M=128, N=256 (4 chunks of 64), K=64.
#define SF_AH 0
#define SF_AL 18432
#define SF_BH 36864
#define SF_BL 46080
#define SF_RS 55296
#define SMEM_FC 56320

__global__ void __launch_bounds__(256) k_fcmma(
    const __nv_bfloat16* __restrict__ Wh, const __nv_bfloat16* __restrict__ Wl)
{
    extern __shared__ char sm[];
    int tx = threadIdx.x, wid = tx >> 5, lane = tx & 31;
    int wm = wid & 3, wn = wid >> 2;
    int btile = blockIdx.x, n = blockIdx.y;
    const float* A = g_y + ((size_t)n * Bc*Tc + btile*128) * GDc;

    // stage A (y tile 128x64) split
    #pragma unroll
    for (int i = tx; i < 2048; i += 256) {
        int r = i >> 4, c4 = (i & 15) << 2;
        float4 v = *(const float4*)(A + (size_t)r * GDc + c4);
        __nv_bfloat16 h0 = __float2bfloat16(v.x), h1 = __float2bfloat16(v.y);
        __nv_bfloat16 h2 = __float2bfloat16(v.z), h3 = __float2bfloat16(v.w);
        __nv_bfloat16 l0 = __float2bfloat16(v.x - __bfloat162float(h0));
        __nv_bfloat16 l1 = __float2bfloat16(v.y - __bfloat162float(h1));
        __nv_bfloat16 l2 = __float2bfloat16(v.z - __bfloat162float(h2));
        __nv_bfloat16 l3 = __float2bfloat16(v.w - __bfloat162float(h3));
        uint2 hw, lw;
        hw.x = (uint32_t)__bfloat16_as_ushort(h0) | ((uint32_t)__bfloat16_as_ushort(h1) << 16);
        hw.y = (uint32_t)__bfloat16_as_ushort(h2) | ((uint32_t)__bfloat16_as_ushort(h3) << 16);
        lw.x = (uint32_t)__bfloat16_as_ushort(l0) | ((uint32_t)__bfloat16_as_ushort(l1) << 16);
        lw.y = (uint32_t)__bfloat16_as_ushort(l2) | ((uint32_t)__bfloat16_as_ushort(l3) << 16);
        uint32_t off = (uint32_t)(r * 72 + c4) * 2;
        *(uint2*)(sm + SF_AH + off) = hw;
        *(uint2*)(sm + SF_AL + off) = lw;
    }

    float rs[4] = {0.f, 0.f, 0.f, 0.f};
    for (int nc = 0; nc < 4; nc++) {
        // stage W chunk (64 rows x 64 k)
        #pragma unroll
        for (int i = tx; i < 1024; i += 256) {
            int r = i >> 4, c4 = (i & 15) << 2;
            size_t g = ((size_t)n * 256 + nc*64 + r) * GDc + c4;
            uint32_t off = (uint32_t)(r * 72 + c4) * 2;
            *(uint2*)(sm + SF_BH + off) = *(const uint2*)(Wh + g);
            *(uint2*)(sm + SF_BL + off) = *(const uint2*)(Wl + g);
        }
        __syncthreads();
        float acc[2][4][4];
        #pragma unroll
        for (int i = 0; i < 2; i++)
            #pragma unroll
            for (int j = 0; j < 4; j++)
                #pragma unroll
                for (int q = 0; q < 4; q++) acc[i][j][q] = 0.f;
        #pragma unroll
        for (int ks = 0; ks < 4; ks++) {
            uint32_t ah[2][4], al[2][4];
            #pragma unroll
            for (int mi = 0; mi < 2; mi++) {
                uint32_t ro = (uint32_t)((wm*32 + mi*16 + (lane >> 2)) * 72 + ks*16 + (lane & 3)*2);
                ah[mi][0] = *(const uint32_t*)(sm + SF_AH + ro*2);
                ah[mi][1] = *(const uint32_t*)(sm + SF_AH + (ro + 8*72)*2);
                ah[mi][2] = *(const uint32_t*)(sm + SF_AH + (ro + 8)*2);
                ah[mi][3] = *(const uint32_t*)(sm + SF_AH + (ro + 8*72 + 8)*2);
                al[mi][0] = *(const uint32_t*)(sm + SF_AL + ro*2);
                al[mi][1] = *(const uint32_t*)(sm + SF_AL + (ro + 8*72)*2);
                al[mi][2] = *(const uint32_t*)(sm + SF_AL + (ro + 8)*2);
                al[mi][3] = *(const uint32_t*)(sm + SF_AL + (ro + 8*72 + 8)*2);
            }
            #pragma unroll
            for (int ni = 0; ni < 4; ni++) {
                uint32_t bo = (uint32_t)((wn*32 + ni*8 + (lane >> 2)) * 72 + ks*16 + (lane & 3)*2);
                uint32_t bh0 = *(const uint32_t*)(sm + SF_BH + bo*2);
                uint32_t bh1 = *(const uint32_t*)(sm + SF_BH + (bo + 8)*2);
                uint32_t bl0 = *(const uint32_t*)(sm + SF_BL + bo*2);
                uint32_t bl1 = *(const uint32_t*)(sm + SF_BL + (bo + 8)*2);
                #pragma unroll
                for (int mi = 0; mi < 2; mi++) {
                    mma_bf16(acc[mi][ni], ah[mi], bh0, bh1);
                    mma_bf16(acc[mi][ni], ah[mi], bl0, bl1);
                    mma_bf16(acc[mi][ni], al[mi], bh0, bh1);
                }
            }
        }
        #pragma unroll
        for (int mi = 0; mi < 2; mi++)
            #pragma unroll
            for (int ni = 0; ni < 4; ni++) {
                float f0 = fmaxf(acc[mi][ni][0], 0.f), f1 = fmaxf(acc[mi][ni][1], 0.f);
                float f2 = fmaxf(acc[mi][ni][2], 0.f), f3 = fmaxf(acc[mi][ni][3], 0.f);
                rs[mi*2+0] += f0*f0 + f1*f1;
                rs[mi*2+1] += f2*f2 + f3*f3;
            }
        __syncthreads();
    }
    // reduce across quad lanes (same rows, different cols)
    #pragma unroll
    for (int j = 0; j < 4; j++) {
        rs[j] += __shfl_xor_sync(0xFFFFFFFFu, rs[j], 1);
        rs[j] += __shfl_xor_sync(0xFFFFFFFFu, rs[j], 2);
    }
    float* srs = (float*)(sm + SF_RS);
    if ((lane & 3) == 0) {
        int rr = lane >> 2;
        #pragma unroll
        for (int mi = 0; mi < 2; mi++) {
            srs[wn*128 + wm*32 + mi*16 + rr]     = rs[mi*2+0];
            srs[wn*128 + wm*32 + mi*16 + rr + 8] = rs[mi*2+1];
        }
    }
    __syncthreads();
    if (tx < 128)
        g_fcsum[(size_t)n * Bc*Tc + btile*128 + tx] = srs[tx] + srs[128 + tx];
}

// ---------------- per-step SIMT kernels ----------------
__global__ void k_qkvgemm(const float* __restrict__ qkv_w) {
    __shared__ float As[64][65];
    __shared__ float Bs[64][65];
    int btile = blockIdx.x, n = blockIdx.y, z = blockIdx.z;
    int tx = threadIdx.x;
    const float* Ab = g_xi + ((size_t)n*Bc*Tc + btile*64)*GDc;
    const float* Wb = qkv_w + ((size_t)n*192 + z*64)*GDc;
    #pragma unroll
    for (int i = tx; i < 64*64; i += 256) {
        int r = i >> 6, c = i & 63;
        As[c][r] = Ab[i];
        Bs[c][r] = Wb[i];
    }
    __syncthreads();
    int tcol = (tx & 15)*4, trow = (tx >> 4)*4;
    float acc[4][4] = {};
    #pragma unroll
    for (int k = 0; k < 64; k++) {
        float a[4], b[4];
        #pragma unroll
        for (int i = 0; i < 4; i++) a[i] = As[k][trow+i];
        #pragma unroll
        for (int j = 0; j < 4; j++) b[j] = Bs[k][tcol+j];
        #pragma unroll
        for (int i = 0; i < 4; i++)
            #pragma unroll
            for (int j = 0; j < 4; j++) acc[i][j] += a[i]*b[j];
    }
    float* Ob = (z == 0 ? g_q : z == 1 ? g_k : g_v) + ((size_t)n*Bc*Tc + btile*64)*GDc;
    #pragma unroll
    for (int i = 0; i < 4; i++)
        #pragma unroll
        for (int j = 0; j < 4; j++)
            Ob[(trow+i)*GDc + tcol+j] = acc[i][j];
}

__global__ void k_roperms() {
    int lane = threadIdx.x & 31;
    int row  = blockIdx.x * 8 + (threadIdx.x >> 5);
    int t = row & (Tc-1);
    float c = g_cos[t*32 + lane], s = g_sin[t*32 + lane];
    {
        float* qp = g_q + (size_t)row*GDc;
        float x1 = qp[lane], x2 = qp[lane+32];
        float n1 = x1*c + x2*s, n2 = -x1*s + x2*c;
        float ss = n1*n1 + n2*n2;
        #pragma unroll
        for (int o = 16; o; o >>= 1) ss += __shfl_xor_sync(0xFFFFFFFFu, ss, o);
        float r = rsqrtf(ss / (float)GDc + EPSc);
        qp[lane] = n1*r; qp[lane+32] = n2*r;
    }
    {
        float* kp = g_k + (size_t)row*GDc;
        float x1 = kp[lane], x2 = kp[lane+32];
        float n1 = x1*c + x2*s, n2 = -x1*s + x2*c;
        float ss = n1*n1 + n2*n2;
        #pragma unroll
        for (int o = 16; o; o >>= 1) ss += __shfl_xor_sync(0xFFFFFFFFu, ss, o);
        float r = rsqrtf(ss / (float)GDc + EPSc);
        kp[lane] = n1*r; kp[lane+32] = n2*r;
    }
}

__global__ void k_scores() {
    int ts = blockIdx.x, tq = blockIdx.y, bn = blockIdx.z;
    if (ts > tq) return;
    int n = bn & 63, b = bn >> 6;
    __shared__ float As[64][65];
    __shared__ float Bs[64][65];
    int tx = threadIdx.x;
    const float* Qb = g_q + ((size_t)n*Bc*Tc + b*Tc + tq*64)*GDc;
    const float* Kb = g_k + ((size_t)n*Bc*Tc + b*Tc + ts*64)*GDc;
    #pragma unroll
    for (int i = tx; i < 64*64; i += 256) {
        int r = i >> 6, c = i & 63;
        As[c][r] = Qb[i];
        Bs[c][r] = Kb[i];
    }
    __syncthreads();
    int tcol = (tx & 15)*4, trow = (tx >> 4)*4;
    float acc[4][4] = {};
    #pragma unroll
    for (int k = 0; k < 64; k++) {
        float a[4], bv[4];
        #pragma unroll
        for (int i = 0; i < 4; i++) a[i] = As[k][trow+i];
        #pragma unroll
        for (int j = 0; j < 4; j++) bv[j] = Bs[k][tcol+j];
        #pragma unroll
        for (int i = 0; i < 4; i++)
            #pragma unroll
            for (int j = 0; j < 4; j++) acc[i][j] += a[i]*bv[j];
    }
    float* Sb = g_scores + (size_t)bn*Tc*Tc;
    #pragma unroll
    for (int i = 0; i < 4; i++) {
        int t = tq*64 + trow + i;
        #pragma unroll
        for (int j = 0; j < 4; j++)
            Sb[(size_t)t*Tc + ts*64 + tcol + j] = acc[i][j] * 0.125f;
    }
}

__global__ void k_softmax() {
    int t = blockIdx.x, bn = blockIdx.y;
    int j = threadIdx.x;
    float* rowp = g_scores + ((size_t)bn*Tc + t)*Tc;
    __shared__ float sw[8];
    float sc = (j <= t) ? rowp[j] : -1e30f;
    float m = sc;
    #pragma unroll
    for (int o = 16; o; o >>= 1) m = fmaxf(m, __shfl_xor_sync(0xFFFFFFFFu, m, o));
    if ((j & 31) == 0) sw[j >> 5] = m;
    __syncthreads();
    if (j < 8) {
        float v = sw[j];
        #pragma unroll
        for (int o = 4; o; o >>= 1) v = fmaxf(v, __shfl_xor_sync(0xFFu, v, o));
        sw[j] = v;
    }
    __syncthreads();
    m = sw[0];
    float e = (j <= t) ? expf(sc - m) : 0.f;
    __syncthreads();
    float su = e;
    #pragma unroll
    for (int o = 16; o; o >>= 1) su += __shfl_xor_sync(0xFFFFFFFFu, su, o);
    if ((j & 31) == 0) sw[j >> 5] = su;
    __syncthreads();
    if (j < 8) {
        float v = sw[j];
        #pragma unroll
        for (int o = 4; o; o >>= 1) v += __shfl_xor_sync(0xFFu, v, o);
        sw[j] = v;
    }
    __syncthreads();
    rowp[j] = e / sw[0];
}

__global__ void k_av() {
    int tq = blockIdx.x, bn = blockIdx.y;
    int n = bn & 63, b = bn >> 6;
    __shared__ float Ps[64][65];
    __shared__ float Vs[64][65];
    int tx = threadIdx.x;
    int tcol = (tx & 15)*4, trow = (tx >> 4)*4;
    float acc[4][4] = {};
    const float* Pb = g_scores + ((size_t)bn*Tc + tq*64)*Tc;
    for (int kt = 0; kt <= tq; kt++) {
        const float* Vb = g_v + ((size_t)n*Bc*Tc + b*Tc + kt*64)*GDc;
        #pragma unroll
        for (int i = tx; i < 64*64; i += 256) {
            int r = i >> 6, c = i & 63;
            Ps[r][c] = Pb[(size_t)r*Tc + kt*64 + c];
            Vs[r][c] = Vb[i];
        }
        __syncthreads();
        #pragma unroll
        for (int k = 0; k < 64; k++) {
            float a[4], bv[4];
            #pragma unroll
            for (int i = 0; i < 4; i++) a[i] = Ps[trow+i][k];
            #pragma unroll
            for (int j = 0; j < 4; j++) bv[j] = Vs[k][tcol+j];
            #pragma unroll
            for (int i = 0; i < 4; i++)
                #pragma unroll
                for (int j = 0; j < 4; j++) acc[i][j] += a[i]*bv[j];
        }
        __syncthreads();
    }
    float* Ob = g_att + ((size_t)n*Bc*Tc + b*Tc + tq*64)*GDc;
    #pragma unroll
    for (int i = 0; i < 4; i++)
        #pragma unroll
        for (int j = 0; j < 4; j++)
            Ob[(trow+i)*GDc + tcol+j] = acc[i][j];
}

__global__ void k_mid() {
    int lane = threadIdx.x & 31;
    int row  = blockIdx.x * 8 + (threadIdx.x >> 5);
    int n = row >> 9;
    const float* xip = g_xi + (size_t)row*GDc;
    const float* atp = g_att + (size_t)row*GDc;
    const float* app = g_apsum + n*GDc;
    float x1 = xip[lane]    + atp[lane]   *app[lane];
    float x2 = xip[lane+32] + atp[lane+32]*app[lane+32];
    float ss = x1*x1 + x2*x2;
    #pragma unroll
    for (int o = 16; o; o >>= 1) ss += __shfl_xor_sync(0xFFFFFFFFu, ss, o);
    float r = rsqrtf(ss / (float)GDc + EPSc);
    float* yp = g_y + (size_t)row*GDc;
    yp[lane] = x1*r; yp[lane+32] = x2*r;
}

__global__ void k_update(const float* __restrict__ router_w, const float* __restrict__ router_b, int step) {
    int bt = blockIdx.x;
    int e = threadIdx.x;
    __shared__ float sred[Ec];
    int gi = e >> 6, gd = e & 63;
    float fu = 0.f;
    #pragma unroll
    for (int l = 0; l < Lc; l++) {
        int n = l*Gc + gi;
        size_t row = (size_t)n*Bc*Tc + bt;
        float att = g_att[row*GDc + gd];
        float aps = g_apsum[n*GDc + gd];
        float fcs = g_fcsum[row];
        float mps = g_mpsum[n*GDc + gd];
        float w   = g_weff[step*NU + n];
        fu += (att*aps + fcs*mps) * w;
    }
    float pc = g_pcont[bt];
    float xv = g_x[(size_t)bt*Ec + e] + fu * pc;
    g_x[(size_t)bt*Ec + e] = xv;
    sred[e] = xv * router_w[e];
    __syncthreads();
    for (int s = 256; s > 0; s >>= 1) { if (e < s) sred[e] += sred[e+s]; __syncthreads(); }
    if (e == 0) {
        float ph = 1.f / (1.f + expf(-(sred[0] + router_b[0])));
        g_pcont[bt] = pc * (1.f - ph);
    }
}

__global__ void k_rmsfinal() {
    int bt = blockIdx.x;
    int tx = threadIdx.x;
    __shared__ float sred[256];
    float a = g_x[(size_t)bt*Ec + tx], b = g_x[(size_t)bt*Ec + tx + 256];
    sred[tx] = a*a + b*b;
    __syncthreads();
    for (int s = 128; s > 0; s >>= 1) { if (tx < s) sred[tx] += sred[tx+s]; __syncthreads(); }
    float r = rsqrtf(sred[0] / (float)Ec + EPSc);
    g_xn[(size_t)bt*Ec + tx]       = a*r;
    g_xn[(size_t)bt*Ec + tx + 256] = b*r;
}

// ---------------- launch ----------------
extern "C" void kernel_launch(void* const* d_in, const int* in_sizes, int n_in,
                              void* d_out, int out_size) {
    const int*   idx       = (const int*)  d_in[0];
    // d_in[1] = n_steps (always 8 by construction)
    const float* wte       = (const float*)d_in[2];
    const float* adapters  = (const float*)d_in[3];
    const float* qkv_w     = (const float*)d_in[4];
    const float* attn_proj = (const float*)d_in[5];
    const float* mlp_fc    = (const float*)d_in[6];
    const float* mlp_proj  = (const float*)d_in[7];
    const float* dep       = (const float*)d_in[8];
    const float* router_w  = (const float*)d_in[9];
    const float* router_b  = (const float*)d_in[10];
    const float* lm_head   = (const float*)d_in[11];
    float* out = (float*)d_out;

    float *px, *pxn, *padap, *pxi;
    __nv_bfloat16 *pah, *pal, *pfh, *pfl, *plh, *pll;
    cudaGetSymbolAddress((void**)&px,    g_x);
    cudaGetSymbolAddress((void**)&pxn,   g_xn);
    cudaGetSymbolAddress((void**)&padap, g_adap);
    cudaGetSymbolAddress((void**)&pxi,   g_xi);
    cudaGetSymbolAddress((void**)&pah,   g_adap_h);
    cudaGetSymbolAddress((void**)&pal,   g_adap_l);
    cudaGetSymbolAddress((void**)&pfh,   g_fcw_h);
    cudaGetSymbolAddress((void**)&pfl,   g_fcw_l);
    cudaGetSymbolAddress((void**)&plh,   g_lmh_h);
    cudaGetSymbolAddress((void**)&pll,   g_lmh_l);

    cudaFuncSetAttribute(mma_gemm<1>, cudaFuncAttributeMaxDynamicSharedMemorySize, SMEM_G);
    cudaFuncSetAttribute(mma_gemm<2>, cudaFuncAttributeMaxDynamicSharedMemorySize, SMEM_G);
    cudaFuncSetAttribute(k_fcmma,     cudaFuncAttributeMaxDynamicSharedMemorySize, SMEM_FC);

    k_tables<<<Tc, 32>>>();
    k_depths<<<1, NU>>>(dep);
    k_sums<<<(NU*GDc + 255)/256, 256>>>(attn_proj, mlp_proj);
    k_adap<<<(NU*GDc*Ec)/256, 256>>>(adapters);
    k_split<<<(NU*GDc*Ec + 255)/256, 256>>>(padap, pah, pal, NU*GDc*Ec, NU*GDc*Ec);
    k_split<<<(NU*256*GDc + 255)/256, 256>>>(mlp_fc, pfh, pfl, NU*256*GDc, NU*256*GDc);
    k_split<<<(VPAD*Ec + 255)/256, 256>>>(lm_head, plh, pll, Vc*Ec, VPAD*Ec);
    k_embed<<<Bc*Tc, 256>>>(idx, wte);

    for (int t = 0; t < Sc; t++) {
        // xi = x @ adap^T, scatter-stored n-major: M=512, N=4096, K=512
        mma_gemm<2><<<dim3(32, 4), 256, SMEM_G>>>(px, pah, pal, pxi, Bc*Tc, NU*GDc, Ec);
        k_qkvgemm<<<dim3(Bc*Tc/64, NU, 3), 256>>>(qkv_w);
        k_roperms<<<NU*Bc*Tc/8, 256>>>();
        k_scores<<<dim3(4, 4, Bc*NU), 256>>>();
        k_softmax<<<dim3(Tc, Bc*NU), 256>>>();
        k_av<<<dim3(4, Bc*NU), 256>>>();
        k_mid<<<NU*Bc*Tc/8, 256>>>();
        k_fcmma<<<dim3(Bc*Tc/128, NU), 256, SMEM_FC>>>(pfh, pfl);
        k_update<<<Bc*Tc, Ec>>>(router_w, router_b, t);
    }

    k_rmsfinal<<<Bc*Tc, 256>>>();
    // logits: M=512, N=50257 (padded 50304), K=512, 15*tanh(/15) epilogue
    mma_gemm<1><<<dim3(VPAD/128, 4), 256, SMEM_G>>>(pxn, plh, pll, out, Bc*Tc, Vc, Ec);
}

// round 7
// speedup vs baseline: 26.2015x; 1.0080x over previous
#include <cuda_runtime.h>
#include <cuda_bf16.h>
#include <math.h>
#include <stdint.h>

#define Bc 2
#define Tc 256
#define Ec 512
#define Gc 8
#define GDc 64
#define Lc 8
#define NU 64
#define Vc 50257
#define VPAD 50304
#define Sc 8
#define EPSc 1.1920929e-7f

// ---------------- device scratch (no allocations allowed) ----------------
__device__ float g_x[Bc*Tc*Ec];
__device__ float g_xn[Bc*Tc*Ec];
__device__ float g_pcont[Bc*Tc];
__device__ float g_cos[Tc*32];
__device__ float g_sin[Tc*32];
__device__ float g_weff[Sc*NU];
__device__ float g_apsum[NU*GDc];
__device__ float g_mpsum[NU*GDc];
__device__ float g_adap[NU*GDc*Ec];          // adapters + folded identity skip
// n-major activations: [n][bt][gd]
__device__ float g_xi [NU*Bc*Tc*GDc];
__device__ float g_q  [NU*Bc*Tc*GDc];
__device__ float g_k  [NU*Bc*Tc*GDc];
__device__ float g_att[NU*Bc*Tc*GDc];
__device__ float g_y  [NU*Bc*Tc*GDc];
__device__ float g_fcsum[NU*Bc*Tc];
// pre-split bf16 weights / activations (hi/lo), 16B-aligned for vector loads
__device__ __align__(16) __nv_bfloat16 g_adap_h[NU*GDc*Ec], g_adap_l[NU*GDc*Ec];
__device__ __align__(16) __nv_bfloat16 g_fcw_h[NU*256*GDc], g_fcw_l[NU*256*GDc];
__device__ __align__(16) __nv_bfloat16 g_lmh_h[VPAD*Ec],    g_lmh_l[VPAD*Ec];
__device__ __align__(16) __nv_bfloat16 g_qkvw_h[NU*192*GDc], g_qkvw_l[NU*192*GDc];
__device__ __align__(16) __nv_bfloat16 g_xih[NU*Bc*Tc*GDc],  g_xil[NU*Bc*Tc*GDc];
__device__ __align__(16) __nv_bfloat16 g_qsh[NU*Bc*Tc*GDc],  g_qsl[NU*Bc*Tc*GDc];
__device__ __align__(16) __nv_bfloat16 g_ksh[NU*Bc*Tc*GDc],  g_ksl[NU*Bc*Tc*GDc];
__device__ __align__(16) __nv_bfloat16 g_vTh[NU*GDc*Bc*Tc],  g_vTl[NU*GDc*Bc*Tc]; // [n][g][bt]

// ---------------- mma helper (baseline PTX, valid on sm_103 non-a) ----------------
__device__ __forceinline__ void mma_bf16(float* d, const uint32_t* a, uint32_t b0, uint32_t b1) {
    asm volatile("mma.sync.aligned.m16n8k16.row.col.f32.bf16.bf16.f32 "
        "{%0,%1,%2,%3}, {%4,%5,%6,%7}, {%8,%9}, {%0,%1,%2,%3};"
        : "+f"(d[0]), "+f"(d[1]), "+f"(d[2]), "+f"(d[3])
        : "r"(a[0]), "r"(a[1]), "r"(a[2]), "r"(a[3]), "r"(b0), "r"(b1));
}
__device__ __forceinline__ uint32_t packbf(float x, float y) {
    return (uint32_t)__bfloat16_as_ushort(__float2bfloat16(x)) |
           ((uint32_t)__bfloat16_as_ushort(__float2bfloat16(y)) << 16);
}

// ---------------- prep kernels ----------------
__global__ void k_tables() {
    int t = blockIdx.x, i = threadIdx.x;
    double invf = pow(10000.0, -((double)(2*i)) / (double)GDc);
    double f = (double)t * invf;
    g_cos[t*32+i] = (float)cos(f);
    g_sin[t*32+i] = (float)sin(f);
}

__global__ void k_depths(const float* __restrict__ dep) {
    int n = threadIdx.x;
    __shared__ float d0[NU], d1[NU];
    d0[n] = 0.f; __syncthreads();
    for (int it = 0; it < Lc; it++) {
        float acc = 0.f;
        for (int j = 0; j < NU; j++)
            acc += fmaxf(dep[n*NU+j], 0.f) * (d0[j] + 1.f);
        d1[n] = acc; __syncthreads();
        d0[n] = d1[n]; __syncthreads();
    }
    float dn = d0[n];
    for (int t = 0; t < Sc; t++) {
        float td = (float)t * ((float)Lc / (float)Sc);
        float w = expf(-fabsf(dn - td));
        g_weff[t*NU+n] = (w > 0.15f) ? w : 0.f;
    }
}

__global__ void k_sums(const float* __restrict__ ap, const float* __restrict__ mp) {
    int i = blockIdx.x*blockDim.x + threadIdx.x;
    if (i >= NU*GDc) return;
    float s = 0.f;
    for (int k = 0; k < GDc; k++) s += ap[i*GDc + k];
    g_apsum[i] = s;
    float s2 = 0.f;
    for (int k = 0; k < 4*GDc; k++) s2 += mp[i*4*GDc + k];
    g_mpsum[i] = s2;
}

__global__ void k_adap(const float* __restrict__ adapters) {
    int tid = blockIdx.x*blockDim.x + threadIdx.x;
    int row = tid >> 9;
    int e   = tid & 511;
    int n = row >> 6, g = row & 63;
    float add = (e == ((n & (Gc-1))*GDc + g)) ? 1.f : 0.f;
    g_adap[tid] = adapters[tid] + add;
}

__global__ void k_split(const float* __restrict__ src, __nv_bfloat16* __restrict__ h,
                        __nv_bfloat16* __restrict__ l, int n_src, int n_pad) {
    int i = blockIdx.x*blockDim.x + threadIdx.x;
    if (i >= n_pad) return;
    float v = (i < n_src) ? src[i] : 0.f;
    __nv_bfloat16 hv = __float2bfloat16(v);
    h[i] = hv;
    l[i] = __float2bfloat16(v - __bfloat162float(hv));
}

__global__ void k_embed(const int* __restrict__ idx, const float* __restrict__ wte) {
    int bt = blockIdx.x;
    int tx = threadIdx.x;
    __shared__ float sred[256];
    int row = idx[bt];
    const float* w = wte + (size_t)row * Ec;
    float a = w[tx], b = w[tx+256];
    sred[tx] = a*a + b*b;
    __syncthreads();
    for (int s = 128; s > 0; s >>= 1) { if (tx < s) sred[tx] += sred[tx+s]; __syncthreads(); }
    float r = rsqrtf(sred[0] / (float)Ec + EPSc);
    g_x[(size_t)bt*Ec + tx]       = a*r;
    g_x[(size_t)bt*Ec + tx + 256] = b*r;
    if (tx == 0) g_pcont[bt] = 1.f;
}

// ---------------- HMMA split-bf16 GEMM ----------------
// MODE 1: 15*tanh(c/15), scalar stores (N odd). MODE 2: scatter n-major xi + split bf16 xi.
#define SG_AH 0
#define SG_AL 18432
#define SG_BH 36864
#define SG_BL 55296
#define SMEM_G 73728

template<int MODE>
__global__ void __launch_bounds__(256) mma_gemm(
    const float* __restrict__ A, const __nv_bfloat16* __restrict__ Bh,
    const __nv_bfloat16* __restrict__ Bl, float* __restrict__ C,
    int M, int N, int K)
{
    extern __shared__ char sm[];
    int tx = threadIdx.x, wid = tx >> 5, lane = tx & 31;
    int wm = wid & 3, wn = wid >> 2;
    int bm = blockIdx.y * 128, bn = blockIdx.x * 128;

    float acc[2][8][4];
    #pragma unroll
    for (int i = 0; i < 2; i++)
        #pragma unroll
        for (int j = 0; j < 8; j++)
            #pragma unroll
            for (int q = 0; q < 4; q++) acc[i][j][q] = 0.f;

    int nchunks = K >> 6;
    for (int ch = 0; ch < nchunks; ch++) {
        int k0 = ch << 6;
        #pragma unroll
        for (int i = tx; i < 2048; i += 256) {
            int r = i >> 4, c4 = (i & 15) << 2;
            float4 v = *(const float4*)(A + (size_t)(bm + r) * K + k0 + c4);
            uint2 hw, lw;
            hw.x = packbf(v.x, v.y); hw.y = packbf(v.z, v.w);
            lw.x = packbf(v.x - __bfloat162float(__float2bfloat16(v.x)),
                          v.y - __bfloat162float(__float2bfloat16(v.y)));
            lw.y = packbf(v.z - __bfloat162float(__float2bfloat16(v.z)),
                          v.w - __bfloat162float(__float2bfloat16(v.w)));
            uint32_t off = (uint32_t)(r * 72 + c4) * 2;
            *(uint2*)(sm + SG_AH + off) = hw;
            *(uint2*)(sm + SG_AL + off) = lw;
        }
        #pragma unroll
        for (int i = tx; i < 2048; i += 256) {
            int r = i >> 4, c4 = (i & 15) << 2;
            size_t g = (size_t)(bn + r) * K + k0 + c4;
            uint32_t off = (uint32_t)(r * 72 + c4) * 2;
            *(uint2*)(sm + SG_BH + off) = *(const uint2*)(Bh + g);
            *(uint2*)(sm + SG_BL + off) = *(const uint2*)(Bl + g);
        }
        __syncthreads();
        #pragma unroll
        for (int ks = 0; ks < 4; ks++) {
            uint32_t ah[2][4], al[2][4];
            #pragma unroll
            for (int mi = 0; mi < 2; mi++) {
                uint32_t ro = (uint32_t)((wm*32 + mi*16 + (lane >> 2)) * 72 + ks*16 + (lane & 3)*2);
                ah[mi][0] = *(const uint32_t*)(sm + SG_AH + ro*2);
                ah[mi][1] = *(const uint32_t*)(sm + SG_AH + (ro + 8*72)*2);
                ah[mi][2] = *(const uint32_t*)(sm + SG_AH + (ro + 8)*2);
                ah[mi][3] = *(const uint32_t*)(sm + SG_AH + (ro + 8*72 + 8)*2);
                al[mi][0] = *(const uint32_t*)(sm + SG_AL + ro*2);
                al[mi][1] = *(const uint32_t*)(sm + SG_AL + (ro + 8*72)*2);
                al[mi][2] = *(const uint32_t*)(sm + SG_AL + (ro + 8)*2);
                al[mi][3] = *(const uint32_t*)(sm + SG_AL + (ro + 8*72 + 8)*2);
            }
            #pragma unroll
            for (int ni = 0; ni < 8; ni++) {
                uint32_t bo = (uint32_t)((wn*64 + ni*8 + (lane >> 2)) * 72 + ks*16 + (lane & 3)*2);
                uint32_t bh0 = *(const uint32_t*)(sm + SG_BH + bo*2);
                uint32_t bh1 = *(const uint32_t*)(sm + SG_BH + (bo + 8)*2);
                uint32_t bl0 = *(const uint32_t*)(sm + SG_BL + bo*2);
                uint32_t bl1 = *(const uint32_t*)(sm + SG_BL + (bo + 8)*2);
                #pragma unroll
                for (int mi = 0; mi < 2; mi++) {
                    mma_bf16(acc[mi][ni], ah[mi], bh0, bh1);
                    mma_bf16(acc[mi][ni], ah[mi], bl0, bl1);
                    mma_bf16(acc[mi][ni], al[mi], bh0, bh1);
                }
            }
        }
        __syncthreads();
    }

    #pragma unroll
    for (int mi = 0; mi < 2; mi++) {
        int m = bm + wm*32 + mi*16 + (lane >> 2);
        #pragma unroll
        for (int ni = 0; ni < 8; ni++) {
            int n = bn + wn*64 + ni*8 + (lane & 3)*2;
            float v0 = acc[mi][ni][0], v1 = acc[mi][ni][1];
            float v2 = acc[mi][ni][2], v3 = acc[mi][ni][3];
            if (MODE == 1) {
                if (n < N) {
                    C[(size_t)m*N + n]     = 15.f*tanhf(v0*(1.f/15.f));
                    C[(size_t)(m+8)*N + n] = 15.f*tanhf(v2*(1.f/15.f));
                }
                if (n + 1 < N) {
                    C[(size_t)m*N + n + 1]     = 15.f*tanhf(v1*(1.f/15.f));
                    C[(size_t)(m+8)*N + n + 1] = 15.f*tanhf(v3*(1.f/15.f));
                }
            } else {
                size_t b0 = ((size_t)(n >> 6) * M + m) * GDc + (n & 63);
                size_t b2 = ((size_t)(n >> 6) * M + m + 8) * GDc + (n & 63);
                *(float2*)(C + b0) = make_float2(v0, v1);
                *(float2*)(C + b2) = make_float2(v2, v3);
                // split bf16 xi for qkv GEMM
                *(uint32_t*)(g_xih + b0) = packbf(v0, v1);
                *(uint32_t*)(g_xih + b2) = packbf(v2, v3);
                *(uint32_t*)(g_xil + b0) = packbf(
                    v0 - __bfloat162float(__float2bfloat16(v0)),
                    v1 - __bfloat162float(__float2bfloat16(v1)));
                *(uint32_t*)(g_xil + b2) = packbf(
                    v2 - __bfloat162float(__float2bfloat16(v2)),
                    v3 - __bfloat162float(__float2bfloat16(v3)));
            }
        }
    }
}

// ---------------- qkv via HMMA: [q|k|v] = xi @ Wz^T per unit ----------------
// grid (4 btiles, 64 units), 256 thr. M=128, K=64, 3 chunks of N=64.
#define SQ_AH 0
#define SQ_AL 18432
#define SQ_BH 36864
#define SQ_BL 46080
#define SMEM_QKV 55296

__global__ void __launch_bounds__(256) k_qkvmma() {
    extern __shared__ char sm[];
    int tx = threadIdx.x, wid = tx >> 5, lane = tx & 31;
    int wm = wid & 3, wn = wid >> 2;
    int btile = blockIdx.x, n = blockIdx.y;
    size_t abase = ((size_t)n * Bc*Tc + btile*128) * GDc;

    #pragma unroll
    for (int i = tx; i < 2048; i += 256) {
        int r = i >> 4, c4 = (i & 15) << 2;
        uint32_t off = (uint32_t)(r * 72 + c4) * 2;
        *(uint2*)(sm + SQ_AH + off) = *(const uint2*)(g_xih + abase + (size_t)r*GDc + c4);
        *(uint2*)(sm + SQ_AL + off) = *(const uint2*)(g_xil + abase + (size_t)r*GDc + c4);
    }

    for (int z = 0; z < 3; z++) {
        #pragma unroll
        for (int i = tx; i < 1024; i += 256) {
            int r = i >> 4, c4 = (i & 15) << 2;
            size_t g = ((size_t)n*192 + z*64 + r) * GDc + c4;
            uint32_t off = (uint32_t)(r * 72 + c4) * 2;
            *(uint2*)(sm + SQ_BH + off) = *(const uint2*)(g_qkvw_h + g);
            *(uint2*)(sm + SQ_BL + off) = *(const uint2*)(g_qkvw_l + g);
        }
        __syncthreads();
        float acc[2][4][4];
        #pragma unroll
        for (int i = 0; i < 2; i++)
            #pragma unroll
            for (int j = 0; j < 4; j++)
                #pragma unroll
                for (int q = 0; q < 4; q++) acc[i][j][q] = 0.f;
        #pragma unroll
        for (int ks = 0; ks < 4; ks++) {
            uint32_t ah[2][4], al[2][4];
            #pragma unroll
            for (int mi = 0; mi < 2; mi++) {
                uint32_t ro = (uint32_t)((wm*32 + mi*16 + (lane >> 2)) * 72 + ks*16 + (lane & 3)*2);
                ah[mi][0] = *(const uint32_t*)(sm + SQ_AH + ro*2);
                ah[mi][1] = *(const uint32_t*)(sm + SQ_AH + (ro + 8*72)*2);
                ah[mi][2] = *(const uint32_t*)(sm + SQ_AH + (ro + 8)*2);
                ah[mi][3] = *(const uint32_t*)(sm + SQ_AH + (ro + 8*72 + 8)*2);
                al[mi][0] = *(const uint32_t*)(sm + SQ_AL + ro*2);
                al[mi][1] = *(const uint32_t*)(sm + SQ_AL + (ro + 8*72)*2);
                al[mi][2] = *(const uint32_t*)(sm + SQ_AL + (ro + 8)*2);
                al[mi][3] = *(const uint32_t*)(sm + SQ_AL + (ro + 8*72 + 8)*2);
            }
            #pragma unroll
            for (int ni = 0; ni < 4; ni++) {
                uint32_t bo = (uint32_t)((wn*32 + ni*8 + (lane >> 2)) * 72 + ks*16 + (lane & 3)*2);
                uint32_t bh0 = *(const uint32_t*)(sm + SQ_BH + bo*2);
                uint32_t bh1 = *(const uint32_t*)(sm + SQ_BH + (bo + 8)*2);
                uint32_t bl0 = *(const uint32_t*)(sm + SQ_BL + bo*2);
                uint32_t bl1 = *(const uint32_t*)(sm + SQ_BL + (bo + 8)*2);
                #pragma unroll
                for (int mi = 0; mi < 2; mi++) {
                    mma_bf16(acc[mi][ni], ah[mi], bh0, bh1);
                    mma_bf16(acc[mi][ni], ah[mi], bl0, bl1);
                    mma_bf16(acc[mi][ni], al[mi], bh0, bh1);
                }
            }
        }
        // epilogue
        #pragma unroll
        for (int mi = 0; mi < 2; mi++) {
            int m = btile*128 + wm*32 + mi*16 + (lane >> 2);
            #pragma unroll
            for (int ni = 0; ni < 4; ni++) {
                int g = wn*32 + ni*8 + (lane & 3)*2;
                float v0 = acc[mi][ni][0], v1 = acc[mi][ni][1];
                float v2 = acc[mi][ni][2], v3 = acc[mi][ni][3];
                if (z < 2) {
                    float* O = (z == 0 ? g_q : g_k);
                    *(float2*)(O + ((size_t)n*Bc*Tc + m)*GDc + g)     = make_float2(v0, v1);
                    *(float2*)(O + ((size_t)n*Bc*Tc + m + 8)*GDc + g) = make_float2(v2, v3);
                } else {
                    // V: split + store transposed [n][g][bt]
                    size_t t0 = ((size_t)n*GDc + g)*(Bc*Tc) + m;
                    size_t t1 = ((size_t)n*GDc + g + 1)*(Bc*Tc) + m;
                    __nv_bfloat16 h;
                    h = __float2bfloat16(v0); g_vTh[t0] = h;   g_vTl[t0]   = __float2bfloat16(v0 - __bfloat162float(h));
                    h = __float2bfloat16(v1); g_vTh[t1] = h;   g_vTl[t1]   = __float2bfloat16(v1 - __bfloat162float(h));
                    h = __float2bfloat16(v2); g_vTh[t0+8] = h; g_vTl[t0+8] = __float2bfloat16(v2 - __bfloat162float(h));
                    h = __float2bfloat16(v3); g_vTh[t1+8] = h; g_vTl[t1+8] = __float2bfloat16(v3 - __bfloat162float(h));
                }
            }
        }
        __syncthreads();
    }
}

// ---------------- rope + rms -> split bf16 q,k ----------------
__global__ void k_roperms() {
    int lane = threadIdx.x & 31;
    int row  = blockIdx.x * 8 + (threadIdx.x >> 5);   // row = n*512 + bt
    int t = row & (Tc-1);
    float c = g_cos[t*32 + lane], s = g_sin[t*32 + lane];
    {
        const float* qp = g_q + (size_t)row*GDc;
        float x1 = qp[lane], x2 = qp[lane+32];
        float n1 = x1*c + x2*s, n2 = -x1*s + x2*c;
        float ss = n1*n1 + n2*n2;
        #pragma unroll
        for (int o = 16; o; o >>= 1) ss += __shfl_xor_sync(0xFFFFFFFFu, ss, o);
        float r = rsqrtf(ss / (float)GDc + EPSc);
        n1 *= r; n2 *= r;
        __nv_bfloat16 h1 = __float2bfloat16(n1), h2 = __float2bfloat16(n2);
        g_qsh[(size_t)row*GDc + lane]    = h1;
        g_qsh[(size_t)row*GDc + lane+32] = h2;
        g_qsl[(size_t)row*GDc + lane]    = __float2bfloat16(n1 - __bfloat162float(h1));
        g_qsl[(size_t)row*GDc + lane+32] = __float2bfloat16(n2 - __bfloat162float(h2));
    }
    {
        const float* kp = g_k + (size_t)row*GDc;
        float x1 = kp[lane], x2 = kp[lane+32];
        float n1 = x1*c + x2*s, n2 = -x1*s + x2*c;
        float ss = n1*n1 + n2*n2;
        #pragma unroll
        for (int o = 16; o; o >>= 1) ss += __shfl_xor_sync(0xFFFFFFFFu, ss, o);
        float r = rsqrtf(ss / (float)GDc + EPSc);
        n1 *= r; n2 *= r;
        __nv_bfloat16 h1 = __float2bfloat16(n1), h2 = __float2bfloat16(n2);
        g_ksh[(size_t)row*GDc + lane]    = h1;
        g_ksh[(size_t)row*GDc + lane+32] = h2;
        g_ksl[(size_t)row*GDc + lane]    = __float2bfloat16(n1 - __bfloat162float(h1));
        g_ksl[(size_t)row*GDc + lane+32] = __float2bfloat16(n2 - __bfloat162float(h2));
    }
}

// ---------------- fused flash attention ----------------
// grid (tq=4, n=64, b=2), 128 threads (4 warps x 16 rows).
__global__ void __launch_bounds__(128) k_attn() {
    __shared__ __align__(16) char sQh[9216], sQl[9216], sKh[9216], sKl[9216];
    int tx = threadIdx.x, wid = tx >> 5, lane = tx & 31;
    int tq = blockIdx.x, n = blockIdx.y, b = blockIdx.z;
    size_t qbase = ((size_t)n*Bc*Tc + b*Tc + tq*64) * GDc;

    // stage Q tile split
    #pragma unroll
    for (int i = tx; i < 1024; i += 128) {
        int r = i >> 4, c4 = (i & 15) << 2;
        uint32_t off = (uint32_t)(r * 72 + c4) * 2;
        *(uint2*)(sQh + off) = *(const uint2*)(g_qsh + qbase + (size_t)r*GDc + c4);
        *(uint2*)(sQl + off) = *(const uint2*)(g_qsl + qbase + (size_t)r*GDc + c4);
    }

    float S[32][4];
    #pragma unroll
    for (int j = 0; j < 32; j++) {
        float init = (j < (tq+1)*8) ? 0.f : -1e30f;
        S[j][0] = init; S[j][1] = init; S[j][2] = init; S[j][3] = init;
    }

    // ---- scores ----
    #pragma unroll
    for (int ts = 0; ts < 4; ts++) {
        if (ts <= tq) {
            __syncthreads();
            size_t kbase = ((size_t)n*Bc*Tc + b*Tc + ts*64) * GDc;
            #pragma unroll
            for (int i = tx; i < 1024; i += 128) {
                int r = i >> 4, c4 = (i & 15) << 2;
                uint32_t off = (uint32_t)(r * 72 + c4) * 2;
                *(uint2*)(sKh + off) = *(const uint2*)(g_ksh + kbase + (size_t)r*GDc + c4);
                *(uint2*)(sKl + off) = *(const uint2*)(g_ksl + kbase + (size_t)r*GDc + c4);
            }
            __syncthreads();
            #pragma unroll
            for (int ks = 0; ks < 4; ks++) {
                uint32_t ah[4], al[4];
                uint32_t ro = (uint32_t)((wid*16 + (lane >> 2)) * 72 + ks*16 + (lane & 3)*2);
                ah[0] = *(const uint32_t*)(sQh + ro*2);
                ah[1] = *(const uint32_t*)(sQh + (ro + 8*72)*2);
                ah[2] = *(const uint32_t*)(sQh + (ro + 8)*2);
                ah[3] = *(const uint32_t*)(sQh + (ro + 8*72 + 8)*2);
                al[0] = *(const uint32_t*)(sQl + ro*2);
                al[1] = *(const uint32_t*)(sQl + (ro + 8*72)*2);
                al[2] = *(const uint32_t*)(sQl + (ro + 8)*2);
                al[3] = *(const uint32_t*)(sQl + (ro + 8*72 + 8)*2);
                #pragma unroll
                for (int ni = 0; ni < 8; ni++) {
                    uint32_t bo = (uint32_t)((ni*8 + (lane >> 2)) * 72 + ks*16 + (lane & 3)*2);
                    uint32_t bh0 = *(const uint32_t*)(sKh + bo*2);
                    uint32_t bh1 = *(const uint32_t*)(sKh + (bo + 8)*2);
                    uint32_t bl0 = *(const uint32_t*)(sKl + bo*2);
                    uint32_t bl1 = *(const uint32_t*)(sKl + (bo + 8)*2);
                    mma_bf16(S[ts*8+ni], ah, bh0, bh1);
                    mma_bf16(S[ts*8+ni], ah, bl0, bl1);
                    mma_bf16(S[ts*8+ni], al, bh0, bh1);
                }
            }
        }
    }

    // ---- scale + causal mask ----
    int tA = tq*64 + wid*16 + (lane >> 2);   // rows for c0,c1
    int tB = tA + 8;                          // rows for c2,c3
    #pragma unroll
    for (int j = 0; j < 32; j++) {
        int s0 = j*8 + (lane & 3)*2, s1 = s0 + 1;
        S[j][0] = (s0 <= tA) ? S[j][0]*0.125f : -1e30f;
        S[j][1] = (s1 <= tA) ? S[j][1]*0.125f : -1e30f;
        S[j][2] = (s0 <= tB) ? S[j][2]*0.125f : -1e30f;
        S[j][3] = (s1 <= tB) ? S[j][3]*0.125f : -1e30f;
    }
    // ---- softmax (rows fully in-warp: quad shuffles) ----
    float mA = -1e30f, mB = -1e30f;
    #pragma unroll
    for (int j = 0; j < 32; j++) {
        mA = fmaxf(mA, fmaxf(S[j][0], S[j][1]));
        mB = fmaxf(mB, fmaxf(S[j][2], S[j][3]));
    }
    mA = fmaxf(mA, __shfl_xor_sync(0xFFFFFFFFu, mA, 1));
    mA = fmaxf(mA, __shfl_xor_sync(0xFFFFFFFFu, mA, 2));
    mB = fmaxf(mB, __shfl_xor_sync(0xFFFFFFFFu, mB, 1));
    mB = fmaxf(mB, __shfl_xor_sync(0xFFFFFFFFu, mB, 2));
    float sA = 0.f, sB = 0.f;
    #pragma unroll
    for (int j = 0; j < 32; j++) {
        S[j][0] = expf(S[j][0] - mA); S[j][1] = expf(S[j][1] - mA);
        S[j][2] = expf(S[j][2] - mB); S[j][3] = expf(S[j][3] - mB);
        sA += S[j][0] + S[j][1];
        sB += S[j][2] + S[j][3];
    }
    sA += __shfl_xor_sync(0xFFFFFFFFu, sA, 1);
    sA += __shfl_xor_sync(0xFFFFFFFFu, sA, 2);
    sB += __shfl_xor_sync(0xFFFFFFFFu, sB, 1);
    sB += __shfl_xor_sync(0xFFFFFFFFu, sB, 2);
    float iA = 1.f / sA, iB = 1.f / sB;

    // ---- pack P as A-frags (hi/lo) ----
    uint32_t Ph[16][4], Pl[16][4];
    #pragma unroll
    for (int kc = 0; kc < 16; kc++) {
        float e0 = S[2*kc][0]*iA,   e1 = S[2*kc][1]*iA;
        float e2 = S[2*kc][2]*iB,   e3 = S[2*kc][3]*iB;
        float f0 = S[2*kc+1][0]*iA, f1 = S[2*kc+1][1]*iA;
        float f2 = S[2*kc+1][2]*iB, f3 = S[2*kc+1][3]*iB;
        Ph[kc][0] = packbf(e0, e1); Ph[kc][1] = packbf(e2, e3);
        Ph[kc][2] = packbf(f0, f1); Ph[kc][3] = packbf(f2, f3);
        Pl[kc][0] = packbf(e0 - __bfloat162float(__float2bfloat16(e0)),
                           e1 - __bfloat162float(__float2bfloat16(e1)));
        Pl[kc][1] = packbf(e2 - __bfloat162float(__float2bfloat16(e2)),
                           e3 - __bfloat162float(__float2bfloat16(e3)));
        Pl[kc][2] = packbf(f0 - __bfloat162float(__float2bfloat16(f0)),
                           f1 - __bfloat162float(__float2bfloat16(f1)));
        Pl[kc][3] = packbf(f2 - __bfloat162float(__float2bfloat16(f2)),
                           f3 - __bfloat162float(__float2bfloat16(f3)));
    }

    // ---- O = P @ V  (V tiles staged from transposed split V) ----
    float O[8][4];
    #pragma unroll
    for (int j = 0; j < 8; j++) { O[j][0]=0.f; O[j][1]=0.f; O[j][2]=0.f; O[j][3]=0.f; }
    #pragma unroll
    for (int ts = 0; ts < 4; ts++) {
        if (ts <= tq) {
            __syncthreads();
            #pragma unroll
            for (int i = tx; i < 1024; i += 128) {
                int g = i >> 4, c4 = (i & 15) << 2;
                size_t src = ((size_t)n*GDc + g)*(Bc*Tc) + b*Tc + ts*64 + c4;
                uint32_t off = (uint32_t)(g * 72 + c4) * 2;
                *(uint2*)(sKh + off) = *(const uint2*)(g_vTh + src);
                *(uint2*)(sKl + off) = *(const uint2*)(g_vTl + src);
            }
            __syncthreads();
            #pragma unroll
            for (int kc = 0; kc < 4; kc++) {
                #pragma unroll
                for (int ni = 0; ni < 8; ni++) {
                    uint32_t bo = (uint32_t)((ni*8 + (lane >> 2)) * 72 + kc*16 + (lane & 3)*2);
                    uint32_t bh0 = *(const uint32_t*)(sKh + bo*2);
                    uint32_t bh1 = *(const uint32_t*)(sKh + (bo + 8)*2);
                    uint32_t bl0 = *(const uint32_t*)(sKl + bo*2);
                    uint32_t bl1 = *(const uint32_t*)(sKl + (bo + 8)*2);
                    mma_bf16(O[ni], Ph[ts*4+kc], bh0, bh1);
                    mma_bf16(O[ni], Ph[ts*4+kc], bl0, bl1);
                    mma_bf16(O[ni], Pl[ts*4+kc], bh0, bh1);
                }
            }
        }
    }
    // write att fp32 [n][bt][g]
    #pragma unroll
    for (int ni = 0; ni < 8; ni++) {
        int g = ni*8 + (lane & 3)*2;
        size_t r0 = ((size_t)n*Bc*Tc + b*Tc + tA)*GDc + g;
        size_t r1 = ((size_t)n*Bc*Tc + b*Tc + tB)*GDc + g;
        *(float2*)(g_att + r0) = make_float2(O[ni][0], O[ni][1]);
        *(float2*)(g_att + r1) = make_float2(O[ni][2], O[ni][3]);
    }
}

// ---------------- fc via HMMA: fcsum = sum_o relu(y @ W^T)^2 ----------------
#define SF_AH 0
#define SF_AL 18432
#define SF_BH 36864
#define SF_BL 46080
#define SF_RS 55296
#define SMEM_FC 56320

__global__ void __launch_bounds__(256) k_fcmma(
    const __nv_bfloat16* __restrict__ Wh, const __nv_bfloat16* __restrict__ Wl)
{
    extern __shared__ char sm[];
    int tx = threadIdx.x, wid = tx >> 5, lane = tx & 31;
    int wm = wid & 3, wn = wid >> 2;
    int btile = blockIdx.x, n = blockIdx.y;
    const float* A = g_y + ((size_t)n * Bc*Tc + btile*128) * GDc;

    #pragma unroll
    for (int i = tx; i < 2048; i += 256) {
        int r = i >> 4, c4 = (i & 15) << 2;
        float4 v = *(const float4*)(A + (size_t)r * GDc + c4);
        uint2 hw, lw;
        hw.x = packbf(v.x, v.y); hw.y = packbf(v.z, v.w);
        lw.x = packbf(v.x - __bfloat162float(__float2bfloat16(v.x)),
                      v.y - __bfloat162float(__float2bfloat16(v.y)));
        lw.y = packbf(v.z - __bfloat162float(__float2bfloat16(v.z)),
                      v.w - __bfloat162float(__float2bfloat16(v.w)));
        uint32_t off = (uint32_t)(r * 72 + c4) * 2;
        *(uint2*)(sm + SF_AH + off) = hw;
        *(uint2*)(sm + SF_AL + off) = lw;
    }

    float rs[4] = {0.f, 0.f, 0.f, 0.f};
    for (int nc = 0; nc < 4; nc++) {
        #pragma unroll
        for (int i = tx; i < 1024; i += 256) {
            int r = i >> 4, c4 = (i & 15) << 2;
            size_t g = ((size_t)n * 256 + nc*64 + r) * GDc + c4;
            uint32_t off = (uint32_t)(r * 72 + c4) * 2;
            *(uint2*)(sm + SF_BH + off) = *(const uint2*)(Wh + g);
            *(uint2*)(sm + SF_BL + off) = *(const uint2*)(Wl + g);
        }
        __syncthreads();
        float acc[2][4][4];
        #pragma unroll
        for (int i = 0; i < 2; i++)
            #pragma unroll
            for (int j = 0; j < 4; j++)
                #pragma unroll
                for (int q = 0; q < 4; q++) acc[i][j][q] = 0.f;
        #pragma unroll
        for (int ks = 0; ks < 4; ks++) {
            uint32_t ah[2][4], al[2][4];
            #pragma unroll
            for (int mi = 0; mi < 2; mi++) {
                uint32_t ro = (uint32_t)((wm*32 + mi*16 + (lane >> 2)) * 72 + ks*16 + (lane & 3)*2);
                ah[mi][0] = *(const uint32_t*)(sm + SF_AH + ro*2);
                ah[mi][1] = *(const uint32_t*)(sm + SF_AH + (ro + 8*72)*2);
                ah[mi][2] = *(const uint32_t*)(sm + SF_AH + (ro + 8)*2);
                ah[mi][3] = *(const uint32_t*)(sm + SF_AH + (ro + 8*72 + 8)*2);
                al[mi][0] = *(const uint32_t*)(sm + SF_AL + ro*2);
                al[mi][1] = *(const uint32_t*)(sm + SF_AL + (ro + 8*72)*2);
                al[mi][2] = *(const uint32_t*)(sm + SF_AL + (ro + 8)*2);
                al[mi][3] = *(const uint32_t*)(sm + SF_AL + (ro + 8*72 + 8)*2);
            }
            #pragma unroll
            for (int ni = 0; ni < 4; ni++) {
                uint32_t bo = (uint32_t)((wn*32 + ni*8 + (lane >> 2)) * 72 + ks*16 + (lane & 3)*2);
                uint32_t bh0 = *(const uint32_t*)(sm + SF_BH + bo*2);
                uint32_t bh1 = *(const uint32_t*)(sm + SF_BH + (bo + 8)*2);
                uint32_t bl0 = *(const uint32_t*)(sm + SF_BL + bo*2);
                uint32_t bl1 = *(const uint32_t*)(sm + SF_BL + (bo + 8)*2);
                #pragma unroll
                for (int mi = 0; mi < 2; mi++) {
                    mma_bf16(acc[mi][ni], ah[mi], bh0, bh1);
                    mma_bf16(acc[mi][ni], ah[mi], bl0, bl1);
                    mma_bf16(acc[mi][ni], al[mi], bh0, bh1);
                }
            }
        }
        #pragma unroll
        for (int mi = 0; mi < 2; mi++)
            #pragma unroll
            for (int ni = 0; ni < 4; ni++) {
                float f0 = fmaxf(acc[mi][ni][0], 0.f), f1 = fmaxf(acc[mi][ni][1], 0.f);
                float f2 = fmaxf(acc[mi][ni][2], 0.f), f3 = fmaxf(acc[mi][ni][3], 0.f);
                rs[mi*2+0] += f0*f0 + f1*f1;
                rs[mi*2+1] += f2*f2 + f3*f3;
            }
        __syncthreads();
    }
    #pragma unroll
    for (int j = 0; j < 4; j++) {
        rs[j] += __shfl_xor_sync(0xFFFFFFFFu, rs[j], 1);
        rs[j] += __shfl_xor_sync(0xFFFFFFFFu, rs[j], 2);
    }
    float* srs = (float*)(sm + SF_RS);
    if ((lane & 3) == 0) {
        int rr = lane >> 2;
        #pragma unroll
        for (int mi = 0; mi < 2; mi++) {
            srs[wn*128 + wm*32 + mi*16 + rr]     = rs[mi*2+0];
            srs[wn*128 + wm*32 + mi*16 + rr + 8] = rs[mi*2+1];
        }
    }
    __syncthreads();
    if (tx < 128)
        g_fcsum[(size_t)n * Bc*Tc + btile*128 + tx] = srs[tx] + srs[128 + tx];
}

// ---------------- elementwise per-step kernels ----------------
__global__ void k_mid() {
    int lane = threadIdx.x & 31;
    int row  = blockIdx.x * 8 + (threadIdx.x >> 5);
    int n = row >> 9;
    const float* xip = g_xi + (size_t)row*GDc;
    const float* atp = g_att + (size_t)row*GDc;
    const float* app = g_apsum + n*GDc;
    float x1 = xip[lane]    + atp[lane]   *app[lane];
    float x2 = xip[lane+32] + atp[lane+32]*app[lane+32];
    float ss = x1*x1 + x2*x2;
    #pragma unroll
    for (int o = 16; o; o >>= 1) ss += __shfl_xor_sync(0xFFFFFFFFu, ss, o);
    float r = rsqrtf(ss / (float)GDc + EPSc);
    float* yp = g_y + (size_t)row*GDc;
    yp[lane] = x1*r; yp[lane+32] = x2*r;
}

__global__ void k_update(const float* __restrict__ router_w, const float* __restrict__ router_b, int step) {
    int bt = blockIdx.x;
    int e = threadIdx.x;
    __shared__ float sred[Ec];
    int gi = e >> 6, gd = e & 63;
    float fu = 0.f;
    #pragma unroll
    for (int l = 0; l < Lc; l++) {
        int n = l*Gc + gi;
        size_t row = (size_t)n*Bc*Tc + bt;
        float att = g_att[row*GDc + gd];
        float aps = g_apsum[n*GDc + gd];
        float fcs = g_fcsum[row];
        float mps = g_mpsum[n*GDc + gd];
        float w   = g_weff[step*NU + n];
        fu += (att*aps + fcs*mps) * w;
    }
    float pc = g_pcont[bt];
    float xv = g_x[(size_t)bt*Ec + e] + fu * pc;
    g_x[(size_t)bt*Ec + e] = xv;
    sred[e] = xv * router_w[e];
    __syncthreads();
    for (int s = 256; s > 0; s >>= 1) { if (e < s) sred[e] += sred[e+s]; __syncthreads(); }
    if (e == 0) {
        float ph = 1.f / (1.f + expf(-(sred[0] + router_b[0])));
        g_pcont[bt] = pc * (1.f - ph);
    }
}

__global__ void k_rmsfinal() {
    int bt = blockIdx.x;
    int tx = threadIdx.x;
    __shared__ float sred[256];
    float a = g_x[(size_t)bt*Ec + tx], b = g_x[(size_t)bt*Ec + tx + 256];
    sred[tx] = a*a + b*b;
    __syncthreads();
    for (int s = 128; s > 0; s >>= 1) { if (tx < s) sred[tx] += sred[tx+s]; __syncthreads(); }
    float r = rsqrtf(sred[0] / (float)Ec + EPSc);
    g_xn[(size_t)bt*Ec + tx]       = a*r;
    g_xn[(size_t)bt*Ec + tx + 256] = b*r;
}

// ---------------- launch ----------------
extern "C" void kernel_launch(void* const* d_in, const int* in_sizes, int n_in,
                              void* d_out, int out_size) {
    const int*   idx       = (const int*)  d_in[0];
    const float* wte       = (const float*)d_in[2];
    const float* adapters  = (const float*)d_in[3];
    const float* qkv_w     = (const float*)d_in[4];
    const float* attn_proj = (const float*)d_in[5];
    const float* mlp_fc    = (const float*)d_in[6];
    const float* mlp_proj  = (const float*)d_in[7];
    const float* dep       = (const float*)d_in[8];
    const float* router_w  = (const float*)d_in[9];
    const float* router_b  = (const float*)d_in[10];
    const float* lm_head   = (const float*)d_in[11];
    float* out = (float*)d_out;

    float *px, *pxn, *padap, *pxi;
    __nv_bfloat16 *pah, *pal, *pfh, *pfl, *plh, *pll, *pqh, *pql;
    cudaGetSymbolAddress((void**)&px,    g_x);
    cudaGetSymbolAddress((void**)&pxn,   g_xn);
    cudaGetSymbolAddress((void**)&padap, g_adap);
    cudaGetSymbolAddress((void**)&pxi,   g_xi);
    cudaGetSymbolAddress((void**)&pah,   g_adap_h);
    cudaGetSymbolAddress((void**)&pal,   g_adap_l);
    cudaGetSymbolAddress((void**)&pfh,   g_fcw_h);
    cudaGetSymbolAddress((void**)&pfl,   g_fcw_l);
    cudaGetSymbolAddress((void**)&plh,   g_lmh_h);
    cudaGetSymbolAddress((void**)&pll,   g_lmh_l);
    cudaGetSymbolAddress((void**)&pqh,   g_qkvw_h);
    cudaGetSymbolAddress((void**)&pql,   g_qkvw_l);

    cudaFuncSetAttribute(mma_gemm<1>, cudaFuncAttributeMaxDynamicSharedMemorySize, SMEM_G);
    cudaFuncSetAttribute(mma_gemm<2>, cudaFuncAttributeMaxDynamicSharedMemorySize, SMEM_G);
    cudaFuncSetAttribute(k_fcmma,     cudaFuncAttributeMaxDynamicSharedMemorySize, SMEM_FC);
    cudaFuncSetAttribute(k_qkvmma,    cudaFuncAttributeMaxDynamicSharedMemorySize, SMEM_QKV);

    k_tables<<<Tc, 32>>>();
    k_depths<<<1, NU>>>(dep);
    k_sums<<<(NU*GDc + 255)/256, 256>>>(attn_proj, mlp_proj);
    k_adap<<<(NU*GDc*Ec)/256, 256>>>(adapters);
    k_split<<<(NU*GDc*Ec + 255)/256, 256>>>(padap, pah, pal, NU*GDc*Ec, NU*GDc*Ec);
    k_split<<<(NU*256*GDc + 255)/256, 256>>>(mlp_fc, pfh, pfl, NU*256*GDc, NU*256*GDc);
    k_split<<<(NU*192*GDc + 255)/256, 256>>>(qkv_w, pqh, pql, NU*192*GDc, NU*192*GDc);
    k_split<<<(VPAD*Ec + 255)/256, 256>>>(lm_head, plh, pll, Vc*Ec, VPAD*Ec);
    k_embed<<<Bc*Tc, 256>>>(idx, wte);

    for (int t = 0; t < Sc; t++) {
        mma_gemm<2><<<dim3(32, 4), 256, SMEM_G>>>(px, pah, pal, pxi, Bc*Tc, NU*GDc, Ec);
        k_qkvmma<<<dim3(Bc*Tc/128, NU), 256, SMEM_QKV>>>();
        k_roperms<<<NU*Bc*Tc/8, 256>>>();
        k_attn<<<dim3(4, NU, Bc), 128>>>();
        k_mid<<<NU*Bc*Tc/8, 256>>>();
        k_fcmma<<<dim3(Bc*Tc/128, NU), 256, SMEM_FC>>>(pfh, pfl);
        k_update<<<Bc*Tc, Ec>>>(router_w, router_b, t);
    }

    k_rmsfinal<<<Bc*Tc, 256>>>();
    mma_gemm<1><<<dim3(VPAD/128, 4), 256, SMEM_G>>>(pxn, plh, pll, out, Bc*Tc, Vc, Ec);
}

// round 8
// speedup vs baseline: 41.2952x; 1.5761x over previous
#include <cuda_runtime.h>
#include <cuda_bf16.h>
#include <math.h>
#include <stdint.h>

#define Bc 2
#define Tc 256
#define Ec 512
#define Gc 8
#define GDc 64
#define Lc 8
#define NU 64
#define Vc 50257
#define VPAD 50304
#define Sc 8
#define EPSc 1.1920929e-7f

// ---------------- device scratch (no allocations allowed) ----------------
__device__ float g_x[Bc*Tc*Ec];
__device__ float g_xn[Bc*Tc*Ec];
__device__ float g_pcont[Bc*Tc];
__device__ float g_cos[Tc*32];
__device__ float g_sin[Tc*32];
__device__ float g_weff[Sc*NU];
__device__ float g_apsum[NU*GDc];
__device__ float g_mpsum[NU*GDc];
__device__ float g_adap[NU*GDc*Ec];          // adapters + folded identity skip
// n-major activations: [n][bt][gd]
__device__ float g_xi [NU*Bc*Tc*GDc];
__device__ float g_q  [NU*Bc*Tc*GDc];
__device__ float g_k  [NU*Bc*Tc*GDc];
__device__ float g_att[NU*Bc*Tc*GDc];
__device__ float g_y  [NU*Bc*Tc*GDc];
__device__ float g_fcsum[NU*Bc*Tc];
// pre-split bf16 weights / activations (hi/lo), 16B-aligned for vector loads
__device__ __align__(16) __nv_bfloat16 g_adap_h[NU*GDc*Ec], g_adap_l[NU*GDc*Ec];
__device__ __align__(16) __nv_bfloat16 g_fcw_h[NU*256*GDc], g_fcw_l[NU*256*GDc];
__device__ __align__(16) __nv_bfloat16 g_lmh_h[VPAD*Ec],    g_lmh_l[VPAD*Ec];
__device__ __align__(16) __nv_bfloat16 g_qkvw_h[NU*192*GDc], g_qkvw_l[NU*192*GDc];
__device__ __align__(16) __nv_bfloat16 g_xih[NU*Bc*Tc*GDc],  g_xil[NU*Bc*Tc*GDc];
__device__ __align__(16) __nv_bfloat16 g_qsh[NU*Bc*Tc*GDc],  g_qsl[NU*Bc*Tc*GDc];
__device__ __align__(16) __nv_bfloat16 g_ksh[NU*Bc*Tc*GDc],  g_ksl[NU*Bc*Tc*GDc];
__device__ __align__(16) __nv_bfloat16 g_vTh[NU*GDc*Bc*Tc],  g_vTl[NU*GDc*Bc*Tc]; // [n][g][bt]

// ---------------- mma helper (baseline PTX, valid on sm_103 non-a) ----------------
__device__ __forceinline__ void mma_bf16(float* d, const uint32_t* a, uint32_t b0, uint32_t b1) {
    asm volatile("mma.sync.aligned.m16n8k16.row.col.f32.bf16.bf16.f32 "
        "{%0,%1,%2,%3}, {%4,%5,%6,%7}, {%8,%9}, {%0,%1,%2,%3};"
        : "+f"(d[0]), "+f"(d[1]), "+f"(d[2]), "+f"(d[3])
        : "r"(a[0]), "r"(a[1]), "r"(a[2]), "r"(a[3]), "r"(b0), "r"(b1));
}
__device__ __forceinline__ uint32_t packbf(float x, float y) {
    return (uint32_t)__bfloat16_as_ushort(__float2bfloat16(x)) |
           ((uint32_t)__bfloat16_as_ushort(__float2bfloat16(y)) << 16);
}
__device__ __forceinline__ float bfhi(float x) {
    return __bfloat162float(__float2bfloat16(x));
}

// ---------------- prep kernels ----------------
__global__ void k_tables() {
    int t = blockIdx.x, i = threadIdx.x;
    double invf = pow(10000.0, -((double)(2*i)) / (double)GDc);
    double f = (double)t * invf;
    g_cos[t*32+i] = (float)cos(f);
    g_sin[t*32+i] = (float)sin(f);
}

__global__ void k_depths(const float* __restrict__ dep) {
    int n = threadIdx.x;
    __shared__ float d0[NU], d1[NU];
    d0[n] = 0.f; __syncthreads();
    for (int it = 0; it < Lc; it++) {
        float acc = 0.f;
        for (int j = 0; j < NU; j++)
            acc += fmaxf(dep[n*NU+j], 0.f) * (d0[j] + 1.f);
        d1[n] = acc; __syncthreads();
        d0[n] = d1[n]; __syncthreads();
    }
    float dn = d0[n];
    for (int t = 0; t < Sc; t++) {
        float td = (float)t * ((float)Lc / (float)Sc);
        float w = expf(-fabsf(dn - td));
        g_weff[t*NU+n] = (w > 0.15f) ? w : 0.f;
    }
}

__global__ void k_sums(const float* __restrict__ ap, const float* __restrict__ mp) {
    int i = blockIdx.x*blockDim.x + threadIdx.x;
    if (i >= NU*GDc) return;
    float s = 0.f;
    for (int k = 0; k < GDc; k++) s += ap[i*GDc + k];
    g_apsum[i] = s;
    float s2 = 0.f;
    for (int k = 0; k < 4*GDc; k++) s2 += mp[i*4*GDc + k];
    g_mpsum[i] = s2;
}

__global__ void k_adap(const float* __restrict__ adapters) {
    int tid = blockIdx.x*blockDim.x + threadIdx.x;
    int row = tid >> 9;
    int e   = tid & 511;
    int n = row >> 6, g = row & 63;
    float add = (e == ((n & (Gc-1))*GDc + g)) ? 1.f : 0.f;
    g_adap[tid] = adapters[tid] + add;
}

__global__ void k_split(const float* __restrict__ src, __nv_bfloat16* __restrict__ h,
                        __nv_bfloat16* __restrict__ l, int n_src, int n_pad) {
    int i = blockIdx.x*blockDim.x + threadIdx.x;
    if (i >= n_pad) return;
    float v = (i < n_src) ? src[i] : 0.f;
    __nv_bfloat16 hv = __float2bfloat16(v);
    h[i] = hv;
    l[i] = __float2bfloat16(v - __bfloat162float(hv));
}

__global__ void k_embed(const int* __restrict__ idx, const float* __restrict__ wte) {
    int bt = blockIdx.x;
    int tx = threadIdx.x;
    __shared__ float sred[256];
    int row = idx[bt];
    const float* w = wte + (size_t)row * Ec;
    float a = w[tx], b = w[tx+256];
    sred[tx] = a*a + b*b;
    __syncthreads();
    for (int s = 128; s > 0; s >>= 1) { if (tx < s) sred[tx] += sred[tx+s]; __syncthreads(); }
    float r = rsqrtf(sred[0] / (float)Ec + EPSc);
    g_x[(size_t)bt*Ec + tx]       = a*r;
    g_x[(size_t)bt*Ec + tx + 256] = b*r;
    if (tx == 0) g_pcont[bt] = 1.f;
}

// ---------------- HMMA split-bf16 GEMM ----------------
// MODE 1: 15*tanh(c/15), scalar stores (N odd). MODE 2: scatter n-major xi + split bf16 xi.
// DM: number of 128-row M sub-tiles per block (amortizes B staging across M).
#define SMEM_G1 73728
#define SMEM_G2 110592

template<int MODE, int DM>
__global__ void __launch_bounds__(256) mma_gemm(
    const float* __restrict__ A, const __nv_bfloat16* __restrict__ Bh,
    const __nv_bfloat16* __restrict__ Bl, float* __restrict__ C,
    int M, int N, int K)
{
    extern __shared__ char sm[];
    const int oAH = 0, oAL = DM*18432, oBH = 2*DM*18432, oBL = 2*DM*18432 + 18432;
    int tx = threadIdx.x, wid = tx >> 5, lane = tx & 31;
    int wm = wid & 3, wn = wid >> 2;
    int bm = blockIdx.y * (128*DM), bn = blockIdx.x * 128;

    float acc[DM][2][8][4];
    #pragma unroll
    for (int mt = 0; mt < DM; mt++)
        #pragma unroll
        for (int i = 0; i < 2; i++)
            #pragma unroll
            for (int j = 0; j < 8; j++)
                #pragma unroll
                for (int q = 0; q < 4; q++) acc[mt][i][j][q] = 0.f;

    int nchunks = K >> 6;
    for (int ch = 0; ch < nchunks; ch++) {
        int k0 = ch << 6;
        #pragma unroll
        for (int i = tx; i < DM*2048; i += 256) {
            int r = i >> 4, c4 = (i & 15) << 2;
            float4 v = *(const float4*)(A + (size_t)(bm + r) * K + k0 + c4);
            uint2 hw, lw;
            hw.x = packbf(v.x, v.y); hw.y = packbf(v.z, v.w);
            lw.x = packbf(v.x - bfhi(v.x), v.y - bfhi(v.y));
            lw.y = packbf(v.z - bfhi(v.z), v.w - bfhi(v.w));
            uint32_t off = (uint32_t)(r * 72 + c4) * 2;
            *(uint2*)(sm + oAH + off) = hw;
            *(uint2*)(sm + oAL + off) = lw;
        }
        #pragma unroll
        for (int i = tx; i < 2048; i += 256) {
            int r = i >> 4, c4 = (i & 15) << 2;
            size_t g = (size_t)(bn + r) * K + k0 + c4;
            uint32_t off = (uint32_t)(r * 72 + c4) * 2;
            *(uint2*)(sm + oBH + off) = *(const uint2*)(Bh + g);
            *(uint2*)(sm + oBL + off) = *(const uint2*)(Bl + g);
        }
        __syncthreads();
        #pragma unroll
        for (int ks = 0; ks < 4; ks++) {
            uint32_t ah[DM][2][4], al[DM][2][4];
            #pragma unroll
            for (int mt = 0; mt < DM; mt++)
                #pragma unroll
                for (int mi = 0; mi < 2; mi++) {
                    uint32_t ro = (uint32_t)((mt*128 + wm*32 + mi*16 + (lane >> 2)) * 72 + ks*16 + (lane & 3)*2);
                    ah[mt][mi][0] = *(const uint32_t*)(sm + oAH + ro*2);
                    ah[mt][mi][1] = *(const uint32_t*)(sm + oAH + (ro + 8*72)*2);
                    ah[mt][mi][2] = *(const uint32_t*)(sm + oAH + (ro + 8)*2);
                    ah[mt][mi][3] = *(const uint32_t*)(sm + oAH + (ro + 8*72 + 8)*2);
                    al[mt][mi][0] = *(const uint32_t*)(sm + oAL + ro*2);
                    al[mt][mi][1] = *(const uint32_t*)(sm + oAL + (ro + 8*72)*2);
                    al[mt][mi][2] = *(const uint32_t*)(sm + oAL + (ro + 8)*2);
                    al[mt][mi][3] = *(const uint32_t*)(sm + oAL + (ro + 8*72 + 8)*2);
                }
            #pragma unroll
            for (int ni = 0; ni < 8; ni++) {
                uint32_t bo = (uint32_t)((wn*64 + ni*8 + (lane >> 2)) * 72 + ks*16 + (lane & 3)*2);
                uint32_t bh0 = *(const uint32_t*)(sm + oBH + bo*2);
                uint32_t bh1 = *(const uint32_t*)(sm + oBH + (bo + 8)*2);
                uint32_t bl0 = *(const uint32_t*)(sm + oBL + bo*2);
                uint32_t bl1 = *(const uint32_t*)(sm + oBL + (bo + 8)*2);
                #pragma unroll
                for (int mt = 0; mt < DM; mt++)
                    #pragma unroll
                    for (int mi = 0; mi < 2; mi++) {
                        mma_bf16(acc[mt][mi][ni], ah[mt][mi], bh0, bh1);
                        mma_bf16(acc[mt][mi][ni], ah[mt][mi], bl0, bl1);
                        mma_bf16(acc[mt][mi][ni], al[mt][mi], bh0, bh1);
                    }
            }
        }
        __syncthreads();
    }

    #pragma unroll
    for (int mt = 0; mt < DM; mt++)
        #pragma unroll
        for (int mi = 0; mi < 2; mi++) {
            int m = bm + mt*128 + wm*32 + mi*16 + (lane >> 2);
            #pragma unroll
            for (int ni = 0; ni < 8; ni++) {
                int n = bn + wn*64 + ni*8 + (lane & 3)*2;
                float v0 = acc[mt][mi][ni][0], v1 = acc[mt][mi][ni][1];
                float v2 = acc[mt][mi][ni][2], v3 = acc[mt][mi][ni][3];
                if (MODE == 1) {
                    if (n < N) {
                        C[(size_t)m*N + n]     = 15.f*tanhf(v0*(1.f/15.f));
                        C[(size_t)(m+8)*N + n] = 15.f*tanhf(v2*(1.f/15.f));
                    }
                    if (n + 1 < N) {
                        C[(size_t)m*N + n + 1]     = 15.f*tanhf(v1*(1.f/15.f));
                        C[(size_t)(m+8)*N + n + 1] = 15.f*tanhf(v3*(1.f/15.f));
                    }
                } else {
                    size_t b0 = ((size_t)(n >> 6) * M + m) * GDc + (n & 63);
                    size_t b2 = ((size_t)(n >> 6) * M + m + 8) * GDc + (n & 63);
                    *(float2*)(C + b0) = make_float2(v0, v1);
                    *(float2*)(C + b2) = make_float2(v2, v3);
                    *(uint32_t*)(g_xih + b0) = packbf(v0, v1);
                    *(uint32_t*)(g_xih + b2) = packbf(v2, v3);
                    *(uint32_t*)(g_xil + b0) = packbf(v0 - bfhi(v0), v1 - bfhi(v1));
                    *(uint32_t*)(g_xil + b2) = packbf(v2 - bfhi(v2), v3 - bfhi(v3));
                }
            }
        }
}

// ---------------- qkv via HMMA: [q|k|v] = xi @ Wz^T per unit ----------------
#define SQ_AH 0
#define SQ_AL 18432
#define SQ_BH 36864
#define SQ_BL 46080
#define SMEM_QKV 55296

__global__ void __launch_bounds__(256) k_qkvmma() {
    extern __shared__ char sm[];
    int tx = threadIdx.x, wid = tx >> 5, lane = tx & 31;
    int wm = wid & 3, wn = wid >> 2;
    int btile = blockIdx.x, n = blockIdx.y;
    size_t abase = ((size_t)n * Bc*Tc + btile*128) * GDc;

    #pragma unroll
    for (int i = tx; i < 2048; i += 256) {
        int r = i >> 4, c4 = (i & 15) << 2;
        uint32_t off = (uint32_t)(r * 72 + c4) * 2;
        *(uint2*)(sm + SQ_AH + off) = *(const uint2*)(g_xih + abase + (size_t)r*GDc + c4);
        *(uint2*)(sm + SQ_AL + off) = *(const uint2*)(g_xil + abase + (size_t)r*GDc + c4);
    }

    for (int z = 0; z < 3; z++) {
        #pragma unroll
        for (int i = tx; i < 1024; i += 256) {
            int r = i >> 4, c4 = (i & 15) << 2;
            size_t g = ((size_t)n*192 + z*64 + r) * GDc + c4;
            uint32_t off = (uint32_t)(r * 72 + c4) * 2;
            *(uint2*)(sm + SQ_BH + off) = *(const uint2*)(g_qkvw_h + g);
            *(uint2*)(sm + SQ_BL + off) = *(const uint2*)(g_qkvw_l + g);
        }
        __syncthreads();
        float acc[2][4][4];
        #pragma unroll
        for (int i = 0; i < 2; i++)
            #pragma unroll
            for (int j = 0; j < 4; j++)
                #pragma unroll
                for (int q = 0; q < 4; q++) acc[i][j][q] = 0.f;
        #pragma unroll
        for (int ks = 0; ks < 4; ks++) {
            uint32_t ah[2][4], al[2][4];
            #pragma unroll
            for (int mi = 0; mi < 2; mi++) {
                uint32_t ro = (uint32_t)((wm*32 + mi*16 + (lane >> 2)) * 72 + ks*16 + (lane & 3)*2);
                ah[mi][0] = *(const uint32_t*)(sm + SQ_AH + ro*2);
                ah[mi][1] = *(const uint32_t*)(sm + SQ_AH + (ro + 8*72)*2);
                ah[mi][2] = *(const uint32_t*)(sm + SQ_AH + (ro + 8)*2);
                ah[mi][3] = *(const uint32_t*)(sm + SQ_AH + (ro + 8*72 + 8)*2);
                al[mi][0] = *(const uint32_t*)(sm + SQ_AL + ro*2);
                al[mi][1] = *(const uint32_t*)(sm + SQ_AL + (ro + 8*72)*2);
                al[mi][2] = *(const uint32_t*)(sm + SQ_AL + (ro + 8)*2);
                al[mi][3] = *(const uint32_t*)(sm + SQ_AL + (ro + 8*72 + 8)*2);
            }
            #pragma unroll
            for (int ni = 0; ni < 4; ni++) {
                uint32_t bo = (uint32_t)((wn*32 + ni*8 + (lane >> 2)) * 72 + ks*16 + (lane & 3)*2);
                uint32_t bh0 = *(const uint32_t*)(sm + SQ_BH + bo*2);
                uint32_t bh1 = *(const uint32_t*)(sm + SQ_BH + (bo + 8)*2);
                uint32_t bl0 = *(const uint32_t*)(sm + SQ_BL + bo*2);
                uint32_t bl1 = *(const uint32_t*)(sm + SQ_BL + (bo + 8)*2);
                #pragma unroll
                for (int mi = 0; mi < 2; mi++) {
                    mma_bf16(acc[mi][ni], ah[mi], bh0, bh1);
                    mma_bf16(acc[mi][ni], ah[mi], bl0, bl1);
                    mma_bf16(acc[mi][ni], al[mi], bh0, bh1);
                }
            }
        }
        #pragma unroll
        for (int mi = 0; mi < 2; mi++) {
            int m = btile*128 + wm*32 + mi*16 + (lane >> 2);
            #pragma unroll
            for (int ni = 0; ni < 4; ni++) {
                int g = wn*32 + ni*8 + (lane & 3)*2;
                float v0 = acc[mi][ni][0], v1 = acc[mi][ni][1];
                float v2 = acc[mi][ni][2], v3 = acc[mi][ni][3];
                if (z < 2) {
                    float* O = (z == 0 ? g_q : g_k);
                    *(float2*)(O + ((size_t)n*Bc*Tc + m)*GDc + g)     = make_float2(v0, v1);
                    *(float2*)(O + ((size_t)n*Bc*Tc + m + 8)*GDc + g) = make_float2(v2, v3);
                } else {
                    size_t t0 = ((size_t)n*GDc + g)*(Bc*Tc) + m;
                    size_t t1 = ((size_t)n*GDc + g + 1)*(Bc*Tc) + m;
                    __nv_bfloat16 h;
                    h = __float2bfloat16(v0); g_vTh[t0] = h;   g_vTl[t0]   = __float2bfloat16(v0 - __bfloat162float(h));
                    h = __float2bfloat16(v1); g_vTh[t1] = h;   g_vTl[t1]   = __float2bfloat16(v1 - __bfloat162float(h));
                    h = __float2bfloat16(v2); g_vTh[t0+8] = h; g_vTl[t0+8] = __float2bfloat16(v2 - __bfloat162float(h));
                    h = __float2bfloat16(v3); g_vTh[t1+8] = h; g_vTl[t1+8] = __float2bfloat16(v3 - __bfloat162float(h));
                }
            }
        }
        __syncthreads();
    }
}

// ---------------- rope + rms -> split bf16 q,k ----------------
__global__ void k_roperms() {
    int lane = threadIdx.x & 31;
    int row  = blockIdx.x * 8 + (threadIdx.x >> 5);   // row = n*512 + bt
    int t = row & (Tc-1);
    float c = g_cos[t*32 + lane], s = g_sin[t*32 + lane];
    {
        const float* qp = g_q + (size_t)row*GDc;
        float x1 = qp[lane], x2 = qp[lane+32];
        float n1 = x1*c + x2*s, n2 = -x1*s + x2*c;
        float ss = n1*n1 + n2*n2;
        #pragma unroll
        for (int o = 16; o; o >>= 1) ss += __shfl_xor_sync(0xFFFFFFFFu, ss, o);
        float r = rsqrtf(ss / (float)GDc + EPSc);
        n1 *= r; n2 *= r;
        __nv_bfloat16 h1 = __float2bfloat16(n1), h2 = __float2bfloat16(n2);
        g_qsh[(size_t)row*GDc + lane]    = h1;
        g_qsh[(size_t)row*GDc + lane+32] = h2;
        g_qsl[(size_t)row*GDc + lane]    = __float2bfloat16(n1 - __bfloat162float(h1));
        g_qsl[(size_t)row*GDc + lane+32] = __float2bfloat16(n2 - __bfloat162float(h2));
    }
    {
        const float* kp = g_k + (size_t)row*GDc;
        float x1 = kp[lane], x2 = kp[lane+32];
        float n1 = x1*c + x2*s, n2 = -x1*s + x2*c;
        float ss = n1*n1 + n2*n2;
        #pragma unroll
        for (int o = 16; o; o >>= 1) ss += __shfl_xor_sync(0xFFFFFFFFu, ss, o);
        float r = rsqrtf(ss / (float)GDc + EPSc);
        n1 *= r; n2 *= r;
        __nv_bfloat16 h1 = __float2bfloat16(n1), h2 = __float2bfloat16(n2);
        g_ksh[(size_t)row*GDc + lane]    = h1;
        g_ksh[(size_t)row*GDc + lane+32] = h2;
        g_ksl[(size_t)row*GDc + lane]    = __float2bfloat16(n1 - __bfloat162float(h1));
        g_ksl[(size_t)row*GDc + lane+32] = __float2bfloat16(n2 - __bfloat162float(h2));
    }
}

// ---------------- fused flash attention (+ mid/rms epilogue) ----------------
// grid (tq=4, n=64, b=2), 128 threads (4 warps x 16 rows).
__global__ void __launch_bounds__(128) k_attn() {
    __shared__ __align__(16) char sQh[9216], sQl[9216], sKh[9216], sKl[9216];
    int tx = threadIdx.x, wid = tx >> 5, lane = tx & 31;
    int tq = blockIdx.x, n = blockIdx.y, b = blockIdx.z;
    size_t qbase = ((size_t)n*Bc*Tc + b*Tc + tq*64) * GDc;

    #pragma unroll
    for (int i = tx; i < 1024; i += 128) {
        int r = i >> 4, c4 = (i & 15) << 2;
        uint32_t off = (uint32_t)(r * 72 + c4) * 2;
        *(uint2*)(sQh + off) = *(const uint2*)(g_qsh + qbase + (size_t)r*GDc + c4);
        *(uint2*)(sQl + off) = *(const uint2*)(g_qsl + qbase + (size_t)r*GDc + c4);
    }

    float S[32][4];
    #pragma unroll
    for (int j = 0; j < 32; j++) {
        float init = (j < (tq+1)*8) ? 0.f : -1e30f;
        S[j][0] = init; S[j][1] = init; S[j][2] = init; S[j][3] = init;
    }

    // ---- scores ----
    #pragma unroll
    for (int ts = 0; ts < 4; ts++) {
        if (ts <= tq) {
            __syncthreads();
            size_t kbase = ((size_t)n*Bc*Tc + b*Tc + ts*64) * GDc;
            #pragma unroll
            for (int i = tx; i < 1024; i += 128) {
                int r = i >> 4, c4 = (i & 15) << 2;
                uint32_t off = (uint32_t)(r * 72 + c4) * 2;
                *(uint2*)(sKh + off) = *(const uint2*)(g_ksh + kbase + (size_t)r*GDc + c4);
                *(uint2*)(sKl + off) = *(const uint2*)(g_ksl + kbase + (size_t)r*GDc + c4);
            }
            __syncthreads();
            #pragma unroll
            for (int ks = 0; ks < 4; ks++) {
                uint32_t ah[4], al[4];
                uint32_t ro = (uint32_t)((wid*16 + (lane >> 2)) * 72 + ks*16 + (lane & 3)*2);
                ah[0] = *(const uint32_t*)(sQh + ro*2);
                ah[1] = *(const uint32_t*)(sQh + (ro + 8*72)*2);
                ah[2] = *(const uint32_t*)(sQh + (ro + 8)*2);
                ah[3] = *(const uint32_t*)(sQh + (ro + 8*72 + 8)*2);
                al[0] = *(const uint32_t*)(sQl + ro*2);
                al[1] = *(const uint32_t*)(sQl + (ro + 8*72)*2);
                al[2] = *(const uint32_t*)(sQl + (ro + 8)*2);
                al[3] = *(const uint32_t*)(sQl + (ro + 8*72 + 8)*2);
                #pragma unroll
                for (int ni = 0; ni < 8; ni++) {
                    uint32_t bo = (uint32_t)((ni*8 + (lane >> 2)) * 72 + ks*16 + (lane & 3)*2);
                    uint32_t bh0 = *(const uint32_t*)(sKh + bo*2);
                    uint32_t bh1 = *(const uint32_t*)(sKh + (bo + 8)*2);
                    uint32_t bl0 = *(const uint32_t*)(sKl + bo*2);
                    uint32_t bl1 = *(const uint32_t*)(sKl + (bo + 8)*2);
                    mma_bf16(S[ts*8+ni], ah, bh0, bh1);
                    mma_bf16(S[ts*8+ni], ah, bl0, bl1);
                    mma_bf16(S[ts*8+ni], al, bh0, bh1);
                }
            }
        }
    }

    // ---- scale + causal mask ----
    int tA = tq*64 + wid*16 + (lane >> 2);
    int tB = tA + 8;
    #pragma unroll
    for (int j = 0; j < 32; j++) {
        int s0 = j*8 + (lane & 3)*2, s1 = s0 + 1;
        S[j][0] = (s0 <= tA) ? S[j][0]*0.125f : -1e30f;
        S[j][1] = (s1 <= tA) ? S[j][1]*0.125f : -1e30f;
        S[j][2] = (s0 <= tB) ? S[j][2]*0.125f : -1e30f;
        S[j][3] = (s1 <= tB) ? S[j][3]*0.125f : -1e30f;
    }
    // ---- softmax (rows fully in-quad) ----
    float mA = -1e30f, mB = -1e30f;
    #pragma unroll
    for (int j = 0; j < 32; j++) {
        mA = fmaxf(mA, fmaxf(S[j][0], S[j][1]));
        mB = fmaxf(mB, fmaxf(S[j][2], S[j][3]));
    }
    mA = fmaxf(mA, __shfl_xor_sync(0xFFFFFFFFu, mA, 1));
    mA = fmaxf(mA, __shfl_xor_sync(0xFFFFFFFFu, mA, 2));
    mB = fmaxf(mB, __shfl_xor_sync(0xFFFFFFFFu, mB, 1));
    mB = fmaxf(mB, __shfl_xor_sync(0xFFFFFFFFu, mB, 2));
    float sA = 0.f, sB = 0.f;
    #pragma unroll
    for (int j = 0; j < 32; j++) {
        S[j][0] = expf(S[j][0] - mA); S[j][1] = expf(S[j][1] - mA);
        S[j][2] = expf(S[j][2] - mB); S[j][3] = expf(S[j][3] - mB);
        sA += S[j][0] + S[j][1];
        sB += S[j][2] + S[j][3];
    }
    sA += __shfl_xor_sync(0xFFFFFFFFu, sA, 1);
    sA += __shfl_xor_sync(0xFFFFFFFFu, sA, 2);
    sB += __shfl_xor_sync(0xFFFFFFFFu, sB, 1);
    sB += __shfl_xor_sync(0xFFFFFFFFu, sB, 2);
    float iA = 1.f / sA, iB = 1.f / sB;
    // fold normalization into S (P = S)
    #pragma unroll
    for (int j = 0; j < 32; j++) {
        S[j][0] *= iA; S[j][1] *= iA; S[j][2] *= iB; S[j][3] *= iB;
    }

    // ---- O = P @ V (pack A-frags on the fly; no persistent P arrays) ----
    float O[8][4];
    #pragma unroll
    for (int j = 0; j < 8; j++) { O[j][0]=0.f; O[j][1]=0.f; O[j][2]=0.f; O[j][3]=0.f; }
    #pragma unroll
    for (int ts = 0; ts < 4; ts++) {
        if (ts <= tq) {
            __syncthreads();
            #pragma unroll
            for (int i = tx; i < 1024; i += 128) {
                int g = i >> 4, c4 = (i & 15) << 2;
                size_t src = ((size_t)n*GDc + g)*(Bc*Tc) + b*Tc + ts*64 + c4;
                uint32_t off = (uint32_t)(g * 72 + c4) * 2;
                *(uint2*)(sKh + off) = *(const uint2*)(g_vTh + src);
                *(uint2*)(sKl + off) = *(const uint2*)(g_vTl + src);
            }
            __syncthreads();
            #pragma unroll
            for (int kc = 0; kc < 4; kc++) {
                int j0 = ts*8 + 2*kc, j1 = j0 + 1;
                uint32_t ph[4], pl[4];
                ph[0] = packbf(S[j0][0], S[j0][1]);
                ph[1] = packbf(S[j0][2], S[j0][3]);
                ph[2] = packbf(S[j1][0], S[j1][1]);
                ph[3] = packbf(S[j1][2], S[j1][3]);
                pl[0] = packbf(S[j0][0] - bfhi(S[j0][0]), S[j0][1] - bfhi(S[j0][1]));
                pl[1] = packbf(S[j0][2] - bfhi(S[j0][2]), S[j0][3] - bfhi(S[j0][3]));
                pl[2] = packbf(S[j1][0] - bfhi(S[j1][0]), S[j1][1] - bfhi(S[j1][1]));
                pl[3] = packbf(S[j1][2] - bfhi(S[j1][2]), S[j1][3] - bfhi(S[j1][3]));
                #pragma unroll
                for (int ni = 0; ni < 8; ni++) {
                    uint32_t bo = (uint32_t)((ni*8 + (lane >> 2)) * 72 + kc*16 + (lane & 3)*2);
                    uint32_t bh0 = *(const uint32_t*)(sKh + bo*2);
                    uint32_t bh1 = *(const uint32_t*)(sKh + (bo + 8)*2);
                    uint32_t bl0 = *(const uint32_t*)(sKl + bo*2);
                    uint32_t bl1 = *(const uint32_t*)(sKl + (bo + 8)*2);
                    mma_bf16(O[ni], ph, bh0, bh1);
                    mma_bf16(O[ni], ph, bl0, bl1);
                    mma_bf16(O[ni], pl, bh0, bh1);
                }
            }
        }
    }

    // ---- fused epilogue: write att; y = rms(xi + att*apsum) ----
    size_t rowA = (size_t)n*Bc*Tc + b*Tc + tA;
    size_t rowB = rowA + 8;
    float ssA = 0.f, ssB = 0.f;
    #pragma unroll
    for (int ni = 0; ni < 8; ni++) {
        int g = ni*8 + (lane & 3)*2;
        *(float2*)(g_att + rowA*GDc + g) = make_float2(O[ni][0], O[ni][1]);
        *(float2*)(g_att + rowB*GDc + g) = make_float2(O[ni][2], O[ni][3]);
        float2 xA = *(const float2*)(g_xi + rowA*GDc + g);
        float2 xB = *(const float2*)(g_xi + rowB*GDc + g);
        float2 ap = *(const float2*)(g_apsum + n*GDc + g);
        float m0 = xA.x + O[ni][0]*ap.x, m1 = xA.y + O[ni][1]*ap.y;
        float m2 = xB.x + O[ni][2]*ap.x, m3 = xB.y + O[ni][3]*ap.y;
        O[ni][0] = m0; O[ni][1] = m1; O[ni][2] = m2; O[ni][3] = m3;
        ssA += m0*m0 + m1*m1;
        ssB += m2*m2 + m3*m3;
    }
    ssA += __shfl_xor_sync(0xFFFFFFFFu, ssA, 1);
    ssA += __shfl_xor_sync(0xFFFFFFFFu, ssA, 2);
    ssB += __shfl_xor_sync(0xFFFFFFFFu, ssB, 1);
    ssB += __shfl_xor_sync(0xFFFFFFFFu, ssB, 2);
    float rA = rsqrtf(ssA / (float)GDc + EPSc);
    float rB = rsqrtf(ssB / (float)GDc + EPSc);
    #pragma unroll
    for (int ni = 0; ni < 8; ni++) {
        int g = ni*8 + (lane & 3)*2;
        *(float2*)(g_y + rowA*GDc + g) = make_float2(O[ni][0]*rA, O[ni][1]*rA);
        *(float2*)(g_y + rowB*GDc + g) = make_float2(O[ni][2]*rB, O[ni][3]*rB);
    }
}

// ---------------- fc via HMMA: fcsum = sum_o relu(y @ W^T)^2 ----------------
#define SF_AH 0
#define SF_AL 18432
#define SF_BH 36864
#define SF_BL 46080
#define SF_RS 55296
#define SMEM_FC 56320

__global__ void __launch_bounds__(256) k_fcmma(
    const __nv_bfloat16* __restrict__ Wh, const __nv_bfloat16* __restrict__ Wl)
{
    extern __shared__ char sm[];
    int tx = threadIdx.x, wid = tx >> 5, lane = tx & 31;
    int wm = wid & 3, wn = wid >> 2;
    int btile = blockIdx.x, n = blockIdx.y;
    const float* A = g_y + ((size_t)n * Bc*Tc + btile*128) * GDc;

    #pragma unroll
    for (int i = tx; i < 2048; i += 256) {
        int r = i >> 4, c4 = (i & 15) << 2;
        float4 v = *(const float4*)(A + (size_t)r * GDc + c4);
        uint2 hw, lw;
        hw.x = packbf(v.x, v.y); hw.y = packbf(v.z, v.w);
        lw.x = packbf(v.x - bfhi(v.x), v.y - bfhi(v.y));
        lw.y = packbf(v.z - bfhi(v.z), v.w - bfhi(v.w));
        uint32_t off = (uint32_t)(r * 72 + c4) * 2;
        *(uint2*)(sm + SF_AH + off) = hw;
        *(uint2*)(sm + SF_AL + off) = lw;
    }

    float rs[4] = {0.f, 0.f, 0.f, 0.f};
    for (int nc = 0; nc < 4; nc++) {
        #pragma unroll
        for (int i = tx; i < 1024; i += 256) {
            int r = i >> 4, c4 = (i & 15) << 2;
            size_t g = ((size_t)n * 256 + nc*64 + r) * GDc + c4;
            uint32_t off = (uint32_t)(r * 72 + c4) * 2;
            *(uint2*)(sm + SF_BH + off) = *(const uint2*)(Wh + g);
            *(uint2*)(sm + SF_BL + off) = *(const uint2*)(Wl + g);
        }
        __syncthreads();
        float acc[2][4][4];
        #pragma unroll
        for (int i = 0; i < 2; i++)
            #pragma unroll
            for (int j = 0; j < 4; j++)
                #pragma unroll
                for (int q = 0; q < 4; q++) acc[i][j][q] = 0.f;
        #pragma unroll
        for (int ks = 0; ks < 4; ks++) {
            uint32_t ah[2][4], al[2][4];
            #pragma unroll
            for (int mi = 0; mi < 2; mi++) {
                uint32_t ro = (uint32_t)((wm*32 + mi*16 + (lane >> 2)) * 72 + ks*16 + (lane & 3)*2);
                ah[mi][0] = *(const uint32_t*)(sm + SF_AH + ro*2);
                ah[mi][1] = *(const uint32_t*)(sm + SF_AH + (ro + 8*72)*2);
                ah[mi][2] = *(const uint32_t*)(sm + SF_AH + (ro + 8)*2);
                ah[mi][3] = *(const uint32_t*)(sm + SF_AH + (ro + 8*72 + 8)*2);
                al[mi][0] = *(const uint32_t*)(sm + SF_AL + ro*2);
                al[mi][1] = *(const uint32_t*)(sm + SF_AL + (ro + 8*72)*2);
                al[mi][2] = *(const uint32_t*)(sm + SF_AL + (ro + 8)*2);
                al[mi][3] = *(const uint32_t*)(sm + SF_AL + (ro + 8*72 + 8)*2);
            }
            #pragma unroll
            for (int ni = 0; ni < 4; ni++) {
                uint32_t bo = (uint32_t)((wn*32 + ni*8 + (lane >> 2)) * 72 + ks*16 + (lane & 3)*2);
                uint32_t bh0 = *(const uint32_t*)(sm + SF_BH + bo*2);
                uint32_t bh1 = *(const uint32_t*)(sm + SF_BH + (bo + 8)*2);
                uint32_t bl0 = *(const uint32_t*)(sm + SF_BL + bo*2);
                uint32_t bl1 = *(const uint32_t*)(sm + SF_BL + (bo + 8)*2);
                #pragma unroll
                for (int mi = 0; mi < 2; mi++) {
                    mma_bf16(acc[mi][ni], ah[mi], bh0, bh1);
                    mma_bf16(acc[mi][ni], ah[mi], bl0, bl1);
                    mma_bf16(acc[mi][ni], al[mi], bh0, bh1);
                }
            }
        }
        #pragma unroll
        for (int mi = 0; mi < 2; mi++)
            #pragma unroll
            for (int ni = 0; ni < 4; ni++) {
                float f0 = fmaxf(acc[mi][ni][0], 0.f), f1 = fmaxf(acc[mi][ni][1], 0.f);
                float f2 = fmaxf(acc[mi][ni][2], 0.f), f3 = fmaxf(acc[mi][ni][3], 0.f);
                rs[mi*2+0] += f0*f0 + f1*f1;
                rs[mi*2+1] += f2*f2 + f3*f3;
            }
        __syncthreads();
    }
    #pragma unroll
    for (int j = 0; j < 4; j++) {
        rs[j] += __shfl_xor_sync(0xFFFFFFFFu, rs[j], 1);
        rs[j] += __shfl_xor_sync(0xFFFFFFFFu, rs[j], 2);
    }
    float* srs = (float*)(sm + SF_RS);
    if ((lane & 3) == 0) {
        int rr = lane >> 2;
        #pragma unroll
        for (int mi = 0; mi < 2; mi++) {
            srs[wn*128 + wm*32 + mi*16 + rr]     = rs[mi*2+0];
            srs[wn*128 + wm*32 + mi*16 + rr + 8] = rs[mi*2+1];
        }
    }
    __syncthreads();
    if (tx < 128)
        g_fcsum[(size_t)n * Bc*Tc + btile*128 + tx] = srs[tx] + srs[128 + tx];
}

// ---------------- elementwise per-step kernels ----------------
__global__ void k_update(const float* __restrict__ router_w, const float* __restrict__ router_b, int step) {
    int bt = blockIdx.x;
    int e = threadIdx.x;
    __shared__ float sred[Ec];
    int gi = e >> 6, gd = e & 63;
    float fu = 0.f;
    #pragma unroll
    for (int l = 0; l < Lc; l++) {
        int n = l*Gc + gi;
        size_t row = (size_t)n*Bc*Tc + bt;
        float att = g_att[row*GDc + gd];
        float aps = g_apsum[n*GDc + gd];
        float fcs = g_fcsum[row];
        float mps = g_mpsum[n*GDc + gd];
        float w   = g_weff[step*NU + n];
        fu += (att*aps + fcs*mps) * w;
    }
    float pc = g_pcont[bt];
    float xv = g_x[(size_t)bt*Ec + e] + fu * pc;
    g_x[(size_t)bt*Ec + e] = xv;
    sred[e] = xv * router_w[e];
    __syncthreads();
    for (int s = 256; s > 0; s >>= 1) { if (e < s) sred[e] += sred[e+s]; __syncthreads(); }
    if (e == 0) {
        float ph = 1.f / (1.f + expf(-(sred[0] + router_b[0])));
        g_pcont[bt] = pc * (1.f - ph);
    }
}

__global__ void k_rmsfinal() {
    int bt = blockIdx.x;
    int tx = threadIdx.x;
    __shared__ float sred[256];
    float a = g_x[(size_t)bt*Ec + tx], b = g_x[(size_t)bt*Ec + tx + 256];
    sred[tx] = a*a + b*b;
    __syncthreads();
    for (int s = 128; s > 0; s >>= 1) { if (tx < s) sred[tx] += sred[tx+s]; __syncthreads(); }
    float r = rsqrtf(sred[0] / (float)Ec + EPSc);
    g_xn[(size_t)bt*Ec + tx]       = a*r;
    g_xn[(size_t)bt*Ec + tx + 256] = b*r;
}

// ---------------- launch ----------------
extern "C" void kernel_launch(void* const* d_in, const int* in_sizes, int n_in,
                              void* d_out, int out_size) {
    const int*   idx       = (const int*)  d_in[0];
    const float* wte       = (const float*)d_in[2];
    const float* adapters  = (const float*)d_in[3];
    const float* qkv_w     = (const float*)d_in[4];
    const float* attn_proj = (const float*)d_in[5];
    const float* mlp_fc    = (const float*)d_in[6];
    const float* mlp_proj  = (const float*)d_in[7];
    const float* dep       = (const float*)d_in[8];
    const float* router_w  = (const float*)d_in[9];
    const float* router_b  = (const float*)d_in[10];
    const float* lm_head   = (const float*)d_in[11];
    float* out = (float*)d_out;

    float *px, *pxn, *padap, *pxi;
    __nv_bfloat16 *pah, *pal, *pfh, *pfl, *plh, *pll, *pqh, *pql;
    cudaGetSymbolAddress((void**)&px,    g_x);
    cudaGetSymbolAddress((void**)&pxn,   g_xn);
    cudaGetSymbolAddress((void**)&padap, g_adap);
    cudaGetSymbolAddress((void**)&pxi,   g_xi);
    cudaGetSymbolAddress((void**)&pah,   g_adap_h);
    cudaGetSymbolAddress((void**)&pal,   g_adap_l);
    cudaGetSymbolAddress((void**)&pfh,   g_fcw_h);
    cudaGetSymbolAddress((void**)&pfl,   g_fcw_l);
    cudaGetSymbolAddress((void**)&plh,   g_lmh_h);
    cudaGetSymbolAddress((void**)&pll,   g_lmh_l);
    cudaGetSymbolAddress((void**)&pqh,   g_qkvw_h);
    cudaGetSymbolAddress((void**)&pql,   g_qkvw_l);

    cudaFuncSetAttribute((const void*)mma_gemm<1,2>, cudaFuncAttributeMaxDynamicSharedMemorySize, SMEM_G2);
    cudaFuncSetAttribute((const void*)mma_gemm<2,1>, cudaFuncAttributeMaxDynamicSharedMemorySize, SMEM_G1);
    cudaFuncSetAttribute(k_fcmma,  cudaFuncAttributeMaxDynamicSharedMemorySize, SMEM_FC);
    cudaFuncSetAttribute(k_qkvmma, cudaFuncAttributeMaxDynamicSharedMemorySize, SMEM_QKV);

    k_tables<<<Tc, 32>>>();
    k_depths<<<1, NU>>>(dep);
    k_sums<<<(NU*GDc + 255)/256, 256>>>(attn_proj, mlp_proj);
    k_adap<<<(NU*GDc*Ec)/256, 256>>>(adapters);
    k_split<<<(NU*GDc*Ec + 255)/256, 256>>>(padap, pah, pal, NU*GDc*Ec, NU*GDc*Ec);
    k_split<<<(NU*256*GDc + 255)/256, 256>>>(mlp_fc, pfh, pfl, NU*256*GDc, NU*256*GDc);
    k_split<<<(NU*192*GDc + 255)/256, 256>>>(qkv_w, pqh, pql, NU*192*GDc, NU*192*GDc);
    k_split<<<(VPAD*Ec + 255)/256, 256>>>(lm_head, plh, pll, Vc*Ec, VPAD*Ec);
    k_embed<<<Bc*Tc, 256>>>(idx, wte);

    for (int t = 0; t < Sc; t++) {
        mma_gemm<2,1><<<dim3(32, 4), 256, SMEM_G1>>>(px, pah, pal, pxi, Bc*Tc, NU*GDc, Ec);
        k_qkvmma<<<dim3(Bc*Tc/128, NU), 256, SMEM_QKV>>>();
        k_roperms<<<NU*Bc*Tc/8, 256>>>();
        k_attn<<<dim3(4, NU, Bc), 128>>>();
        k_fcmma<<<dim3(Bc*Tc/128, NU), 256, SMEM_FC>>>(pfh, pfl);
        k_update<<<Bc*Tc, Ec>>>(router_w, router_b, t);
    }

    k_rmsfinal<<<Bc*Tc, 256>>>();
    // logits: M=512 (2 x 256-row blocks), N=50257 (padded 50304), K=512
    mma_gemm<1,2><<<dim3(VPAD/128, 2), 256, SMEM_G2>>>(pxn, plh, pll, out, Bc*Tc, Vc, Ec);
}

// round 9
// speedup vs baseline: 44.3728x; 1.0745x over previous
#include <cuda_runtime.h>
#include <cuda_bf16.h>
#include <math.h>
#include <stdint.h>

#define Bc 2
#define Tc 256
#define Ec 512
#define Gc 8
#define GDc 64
#define Lc 8
#define NU 64
#define Vc 50257
#define VPAD 50304
#define Sc 8
#define EPSc 1.1920929e-7f

// ---------------- device scratch (no allocations allowed) ----------------
__device__ float g_x[Bc*Tc*Ec];
__device__ float g_xn[Bc*Tc*Ec];
__device__ float g_pcont[Bc*Tc];
__device__ float g_cos[Tc*32];
__device__ float g_sin[Tc*32];
__device__ float g_weff[Sc*NU];
__device__ float g_apsum[NU*GDc];
__device__ float g_mpsum[NU*GDc];
__device__ float g_adap[NU*GDc*Ec];          // adapters + folded identity skip
// n-major activations: [n][bt][gd]
__device__ float g_xi [NU*Bc*Tc*GDc];
__device__ float g_att[NU*Bc*Tc*GDc];
__device__ float g_y  [NU*Bc*Tc*GDc];
__device__ float g_fcsum[NU*Bc*Tc];
// pre-split bf16 weights / activations (hi/lo), 16B-aligned for vector loads
__device__ __align__(16) __nv_bfloat16 g_adap_h[NU*GDc*Ec], g_adap_l[NU*GDc*Ec];
__device__ __align__(16) __nv_bfloat16 g_fcw_h[NU*256*GDc], g_fcw_l[NU*256*GDc];
__device__ __align__(16) __nv_bfloat16 g_lmh_h[VPAD*Ec],    g_lmh_l[VPAD*Ec];
__device__ __align__(16) __nv_bfloat16 g_qkvw_h[NU*192*GDc];
__device__ __align__(16) __nv_bfloat16 g_xih[NU*Bc*Tc*GDc];
__device__ __align__(16) __nv_bfloat16 g_qsh[NU*Bc*Tc*GDc];
__device__ __align__(16) __nv_bfloat16 g_ksh[NU*Bc*Tc*GDc];
__device__ __align__(16) __nv_bfloat16 g_vTh[NU*GDc*Bc*Tc];   // [n][g][bt]

// ---------------- mma helper (baseline PTX, valid on sm_103 non-a) ----------------
__device__ __forceinline__ void mma_bf16(float* d, const uint32_t* a, uint32_t b0, uint32_t b1) {
    asm volatile("mma.sync.aligned.m16n8k16.row.col.f32.bf16.bf16.f32 "
        "{%0,%1,%2,%3}, {%4,%5,%6,%7}, {%8,%9}, {%0,%1,%2,%3};"
        : "+f"(d[0]), "+f"(d[1]), "+f"(d[2]), "+f"(d[3])
        : "r"(a[0]), "r"(a[1]), "r"(a[2]), "r"(a[3]), "r"(b0), "r"(b1));
}
__device__ __forceinline__ uint32_t packbf(float x, float y) {
    return (uint32_t)__bfloat16_as_ushort(__float2bfloat16(x)) |
           ((uint32_t)__bfloat16_as_ushort(__float2bfloat16(y)) << 16);
}
__device__ __forceinline__ float bfhi(float x) {
    return __bfloat162float(__float2bfloat16(x));
}

// ---------------- prep kernels ----------------
__global__ void k_tables() {
    int t = blockIdx.x, i = threadIdx.x;
    double invf = pow(10000.0, -((double)(2*i)) / (double)GDc);
    double f = (double)t * invf;
    g_cos[t*32+i] = (float)cos(f);
    g_sin[t*32+i] = (float)sin(f);
}

__global__ void k_depths(const float* __restrict__ dep) {
    int n = threadIdx.x;
    __shared__ float d0[NU], d1[NU];
    d0[n] = 0.f; __syncthreads();
    for (int it = 0; it < Lc; it++) {
        float acc = 0.f;
        for (int j = 0; j < NU; j++)
            acc += fmaxf(dep[n*NU+j], 0.f) * (d0[j] + 1.f);
        d1[n] = acc; __syncthreads();
        d0[n] = d1[n]; __syncthreads();
    }
    float dn = d0[n];
    for (int t = 0; t < Sc; t++) {
        float td = (float)t * ((float)Lc / (float)Sc);
        float w = expf(-fabsf(dn - td));
        g_weff[t*NU+n] = (w > 0.15f) ? w : 0.f;
    }
}

__global__ void k_sums(const float* __restrict__ ap, const float* __restrict__ mp) {
    int i = blockIdx.x*blockDim.x + threadIdx.x;
    if (i >= NU*GDc) return;
    float s = 0.f;
    for (int k = 0; k < GDc; k++) s += ap[i*GDc + k];
    g_apsum[i] = s;
    float s2 = 0.f;
    for (int k = 0; k < 4*GDc; k++) s2 += mp[i*4*GDc + k];
    g_mpsum[i] = s2;
}

__global__ void k_adap(const float* __restrict__ adapters) {
    int tid = blockIdx.x*blockDim.x + threadIdx.x;
    int row = tid >> 9;
    int e   = tid & 511;
    int n = row >> 6, g = row & 63;
    float add = (e == ((n & (Gc-1))*GDc + g)) ? 1.f : 0.f;
    g_adap[tid] = adapters[tid] + add;
}

__global__ void k_split(const float* __restrict__ src, __nv_bfloat16* __restrict__ h,
                        __nv_bfloat16* __restrict__ l, int n_src, int n_pad) {
    int i = blockIdx.x*blockDim.x + threadIdx.x;
    if (i >= n_pad) return;
    float v = (i < n_src) ? src[i] : 0.f;
    __nv_bfloat16 hv = __float2bfloat16(v);
    h[i] = hv;
    if (l) l[i] = __float2bfloat16(v - __bfloat162float(hv));
}

__global__ void k_embed(const int* __restrict__ idx, const float* __restrict__ wte) {
    int bt = blockIdx.x;
    int tx = threadIdx.x;
    __shared__ float sred[256];
    int row = idx[bt];
    const float* w = wte + (size_t)row * Ec;
    float a = w[tx], b = w[tx+256];
    sred[tx] = a*a + b*b;
    __syncthreads();
    for (int s = 128; s > 0; s >>= 1) { if (tx < s) sred[tx] += sred[tx+s]; __syncthreads(); }
    float r = rsqrtf(sred[0] / (float)Ec + EPSc);
    g_x[(size_t)bt*Ec + tx]       = a*r;
    g_x[(size_t)bt*Ec + tx + 256] = b*r;
    if (tx == 0) g_pcont[bt] = 1.f;
}

// ---------------- HMMA split-bf16 GEMM ----------------
// MODE 1: 15*tanh(c/15), scalar stores (N odd). MODE 2: scatter n-major xi + bf16-hi xi.
// DM: number of 128-row M sub-tiles per block.
#define SMEM_G1 73728
#define SMEM_G2 110592

template<int MODE, int DM>
__global__ void __launch_bounds__(256) mma_gemm(
    const float* __restrict__ A, const __nv_bfloat16* __restrict__ Bh,
    const __nv_bfloat16* __restrict__ Bl, float* __restrict__ C,
    int M, int N, int K)
{
    extern __shared__ char sm[];
    const int oAH = 0, oAL = DM*18432, oBH = 2*DM*18432, oBL = 2*DM*18432 + 18432;
    int tx = threadIdx.x, wid = tx >> 5, lane = tx & 31;
    int wm = wid & 3, wn = wid >> 2;
    int bm = blockIdx.y * (128*DM), bn = blockIdx.x * 128;

    float acc[DM][2][8][4];
    #pragma unroll
    for (int mt = 0; mt < DM; mt++)
        #pragma unroll
        for (int i = 0; i < 2; i++)
            #pragma unroll
            for (int j = 0; j < 8; j++)
                #pragma unroll
                for (int q = 0; q < 4; q++) acc[mt][i][j][q] = 0.f;

    int nchunks = K >> 6;
    for (int ch = 0; ch < nchunks; ch++) {
        int k0 = ch << 6;
        #pragma unroll
        for (int i = tx; i < DM*2048; i += 256) {
            int r = i >> 4, c4 = (i & 15) << 2;
            float4 v = *(const float4*)(A + (size_t)(bm + r) * K + k0 + c4);
            uint2 hw, lw;
            hw.x = packbf(v.x, v.y); hw.y = packbf(v.z, v.w);
            lw.x = packbf(v.x - bfhi(v.x), v.y - bfhi(v.y));
            lw.y = packbf(v.z - bfhi(v.z), v.w - bfhi(v.w));
            uint32_t off = (uint32_t)(r * 72 + c4) * 2;
            *(uint2*)(sm + oAH + off) = hw;
            *(uint2*)(sm + oAL + off) = lw;
        }
        #pragma unroll
        for (int i = tx; i < 2048; i += 256) {
            int r = i >> 4, c4 = (i & 15) << 2;
            size_t g = (size_t)(bn + r) * K + k0 + c4;
            uint32_t off = (uint32_t)(r * 72 + c4) * 2;
            *(uint2*)(sm + oBH + off) = *(const uint2*)(Bh + g);
            *(uint2*)(sm + oBL + off) = *(const uint2*)(Bl + g);
        }
        __syncthreads();
        #pragma unroll
        for (int ks = 0; ks < 4; ks++) {
            uint32_t ah[DM][2][4], al[DM][2][4];
            #pragma unroll
            for (int mt = 0; mt < DM; mt++)
                #pragma unroll
                for (int mi = 0; mi < 2; mi++) {
                    uint32_t ro = (uint32_t)((mt*128 + wm*32 + mi*16 + (lane >> 2)) * 72 + ks*16 + (lane & 3)*2);
                    ah[mt][mi][0] = *(const uint32_t*)(sm + oAH + ro*2);
                    ah[mt][mi][1] = *(const uint32_t*)(sm + oAH + (ro + 8*72)*2);
                    ah[mt][mi][2] = *(const uint32_t*)(sm + oAH + (ro + 8)*2);
                    ah[mt][mi][3] = *(const uint32_t*)(sm + oAH + (ro + 8*72 + 8)*2);
                    al[mt][mi][0] = *(const uint32_t*)(sm + oAL + ro*2);
                    al[mt][mi][1] = *(const uint32_t*)(sm + oAL + (ro + 8*72)*2);
                    al[mt][mi][2] = *(const uint32_t*)(sm + oAL + (ro + 8)*2);
                    al[mt][mi][3] = *(const uint32_t*)(sm + oAL + (ro + 8*72 + 8)*2);
                }
            #pragma unroll
            for (int ni = 0; ni < 8; ni++) {
                uint32_t bo = (uint32_t)((wn*64 + ni*8 + (lane >> 2)) * 72 + ks*16 + (lane & 3)*2);
                uint32_t bh0 = *(const uint32_t*)(sm + oBH + bo*2);
                uint32_t bh1 = *(const uint32_t*)(sm + oBH + (bo + 8)*2);
                uint32_t bl0 = *(const uint32_t*)(sm + oBL + bo*2);
                uint32_t bl1 = *(const uint32_t*)(sm + oBL + (bo + 8)*2);
                #pragma unroll
                for (int mt = 0; mt < DM; mt++)
                    #pragma unroll
                    for (int mi = 0; mi < 2; mi++) {
                        mma_bf16(acc[mt][mi][ni], ah[mt][mi], bh0, bh1);
                        mma_bf16(acc[mt][mi][ni], ah[mt][mi], bl0, bl1);
                        mma_bf16(acc[mt][mi][ni], al[mt][mi], bh0, bh1);
                    }
            }
        }
        __syncthreads();
    }

    #pragma unroll
    for (int mt = 0; mt < DM; mt++)
        #pragma unroll
        for (int mi = 0; mi < 2; mi++) {
            int m = bm + mt*128 + wm*32 + mi*16 + (lane >> 2);
            #pragma unroll
            for (int ni = 0; ni < 8; ni++) {
                int n = bn + wn*64 + ni*8 + (lane & 3)*2;
                float v0 = acc[mt][mi][ni][0], v1 = acc[mt][mi][ni][1];
                float v2 = acc[mt][mi][ni][2], v3 = acc[mt][mi][ni][3];
                if (MODE == 1) {
                    if (n < N) {
                        C[(size_t)m*N + n]     = 15.f*tanhf(v0*(1.f/15.f));
                        C[(size_t)(m+8)*N + n] = 15.f*tanhf(v2*(1.f/15.f));
                    }
                    if (n + 1 < N) {
                        C[(size_t)m*N + n + 1]     = 15.f*tanhf(v1*(1.f/15.f));
                        C[(size_t)(m+8)*N + n + 1] = 15.f*tanhf(v3*(1.f/15.f));
                    }
                } else {
                    size_t b0 = ((size_t)(n >> 6) * M + m) * GDc + (n & 63);
                    size_t b2 = ((size_t)(n >> 6) * M + m + 8) * GDc + (n & 63);
                    *(float2*)(C + b0) = make_float2(v0, v1);
                    *(float2*)(C + b2) = make_float2(v2, v3);
                    *(uint32_t*)(g_xih + b0) = packbf(v0, v1);
                    *(uint32_t*)(g_xih + b2) = packbf(v2, v3);
                }
            }
        }
}

// ---------------- qkv via HMMA (bf16-only) + fused rope/rms ----------------
// grid (4 btiles, 64 units), 256 thr. q,k: rope+rms -> bf16; v: bf16 transposed.
#define SQ2_A 0          // xi hi: 128x72 bf16 = 18432
#define SQ2_B 18432      // W  hi:  64x72 bf16 = 9216
#define SQ2_F 27648      // fp32 buf: 128x66 = 33792
#define SMEM_QKV2 61440

__global__ void __launch_bounds__(256) k_qkvmma() {
    extern __shared__ char sm[];
    float* sf = (float*)(sm + SQ2_F);
    int tx = threadIdx.x, wid = tx >> 5, lane = tx & 31;
    int wm = wid & 3, wn = wid >> 2;
    int btile = blockIdx.x, n = blockIdx.y;
    size_t abase = ((size_t)n * Bc*Tc + btile*128) * GDc;

    #pragma unroll
    for (int i = tx; i < 2048; i += 256) {
        int r = i >> 4, c4 = (i & 15) << 2;
        uint32_t off = (uint32_t)(r * 72 + c4) * 2;
        *(uint2*)(sm + SQ2_A + off) = *(const uint2*)(g_xih + abase + (size_t)r*GDc + c4);
    }

    for (int z = 0; z < 3; z++) {
        #pragma unroll
        for (int i = tx; i < 1024; i += 256) {
            int r = i >> 4, c4 = (i & 15) << 2;
            size_t g = ((size_t)n*192 + z*64 + r) * GDc + c4;
            uint32_t off = (uint32_t)(r * 72 + c4) * 2;
            *(uint2*)(sm + SQ2_B + off) = *(const uint2*)(g_qkvw_h + g);
        }
        __syncthreads();
        float acc[2][4][4];
        #pragma unroll
        for (int i = 0; i < 2; i++)
            #pragma unroll
            for (int j = 0; j < 4; j++)
                #pragma unroll
                for (int q = 0; q < 4; q++) acc[i][j][q] = 0.f;
        #pragma unroll
        for (int ks = 0; ks < 4; ks++) {
            uint32_t ah[2][4];
            #pragma unroll
            for (int mi = 0; mi < 2; mi++) {
                uint32_t ro = (uint32_t)((wm*32 + mi*16 + (lane >> 2)) * 72 + ks*16 + (lane & 3)*2);
                ah[mi][0] = *(const uint32_t*)(sm + SQ2_A + ro*2);
                ah[mi][1] = *(const uint32_t*)(sm + SQ2_A + (ro + 8*72)*2);
                ah[mi][2] = *(const uint32_t*)(sm + SQ2_A + (ro + 8)*2);
                ah[mi][3] = *(const uint32_t*)(sm + SQ2_A + (ro + 8*72 + 8)*2);
            }
            #pragma unroll
            for (int ni = 0; ni < 4; ni++) {
                uint32_t bo = (uint32_t)((wn*32 + ni*8 + (lane >> 2)) * 72 + ks*16 + (lane & 3)*2);
                uint32_t bh0 = *(const uint32_t*)(sm + SQ2_B + bo*2);
                uint32_t bh1 = *(const uint32_t*)(sm + SQ2_B + (bo + 8)*2);
                #pragma unroll
                for (int mi = 0; mi < 2; mi++)
                    mma_bf16(acc[mi][ni], ah[mi], bh0, bh1);
            }
        }
        // frags -> fp32 smem
        #pragma unroll
        for (int mi = 0; mi < 2; mi++) {
            int m = wm*32 + mi*16 + (lane >> 2);
            #pragma unroll
            for (int ni = 0; ni < 4; ni++) {
                int g = wn*32 + ni*8 + (lane & 3)*2;
                sf[m*66 + g]     = acc[mi][ni][0];
                sf[m*66 + g + 1] = acc[mi][ni][1];
                sf[(m+8)*66 + g]     = acc[mi][ni][2];
                sf[(m+8)*66 + g + 1] = acc[mi][ni][3];
            }
        }
        __syncthreads();
        if (z < 2) {
            // rope + rms: warp wid handles rows wid, wid+8, ... (16 rows)
            __nv_bfloat16* dst = (z == 0 ? g_qsh : g_ksh);
            #pragma unroll
            for (int rr = 0; rr < 16; rr++) {
                int row = rr*8 + wid;
                int t = (btile*128 + row) & (Tc-1);
                float c = g_cos[t*32 + lane], s = g_sin[t*32 + lane];
                float x1 = sf[row*66 + lane], x2 = sf[row*66 + lane + 32];
                float n1 = x1*c + x2*s, n2 = -x1*s + x2*c;
                float ss = n1*n1 + n2*n2;
                #pragma unroll
                for (int o = 16; o; o >>= 1) ss += __shfl_xor_sync(0xFFFFFFFFu, ss, o);
                float r_ = rsqrtf(ss / (float)GDc + EPSc);
                __nv_bfloat16* dp = dst + ((size_t)n*Bc*Tc + btile*128 + row)*GDc;
                dp[lane]      = __float2bfloat16(n1*r_);
                dp[lane + 32] = __float2bfloat16(n2*r_);
            }
        } else {
            // v: bf16 transposed [n][g][bt]
            for (int i = tx; i < 8192; i += 256) {
                int g = i >> 7, row = i & 127;
                g_vTh[((size_t)n*GDc + g)*(Bc*Tc) + btile*128 + row] =
                    __float2bfloat16(sf[row*66 + g]);
            }
        }
        __syncthreads();
    }
}

// ---------------- fused flash attention (bf16-only) + mid/rms epilogue ----------------
// grid (tq=4, n=64, b=2), 128 threads (4 warps x 16 rows).
__global__ void __launch_bounds__(128) k_attn() {
    __shared__ __align__(16) char sQ[9216], sK[9216];
    int tx = threadIdx.x, wid = tx >> 5, lane = tx & 31;
    int tq = blockIdx.x, n = blockIdx.y, b = blockIdx.z;
    size_t qbase = ((size_t)n*Bc*Tc + b*Tc + tq*64) * GDc;

    #pragma unroll
    for (int i = tx; i < 1024; i += 128) {
        int r = i >> 4, c4 = (i & 15) << 2;
        uint32_t off = (uint32_t)(r * 72 + c4) * 2;
        *(uint2*)(sQ + off) = *(const uint2*)(g_qsh + qbase + (size_t)r*GDc + c4);
    }

    float S[32][4];
    #pragma unroll
    for (int j = 0; j < 32; j++) {
        float init = (j < (tq+1)*8) ? 0.f : -1e30f;
        S[j][0] = init; S[j][1] = init; S[j][2] = init; S[j][3] = init;
    }

    // ---- scores ----
    #pragma unroll
    for (int ts = 0; ts < 4; ts++) {
        if (ts <= tq) {
            __syncthreads();
            size_t kbase = ((size_t)n*Bc*Tc + b*Tc + ts*64) * GDc;
            #pragma unroll
            for (int i = tx; i < 1024; i += 128) {
                int r = i >> 4, c4 = (i & 15) << 2;
                uint32_t off = (uint32_t)(r * 72 + c4) * 2;
                *(uint2*)(sK + off) = *(const uint2*)(g_ksh + kbase + (size_t)r*GDc + c4);
            }
            __syncthreads();
            #pragma unroll
            for (int ks = 0; ks < 4; ks++) {
                uint32_t ah[4];
                uint32_t ro = (uint32_t)((wid*16 + (lane >> 2)) * 72 + ks*16 + (lane & 3)*2);
                ah[0] = *(const uint32_t*)(sQ + ro*2);
                ah[1] = *(const uint32_t*)(sQ + (ro + 8*72)*2);
                ah[2] = *(const uint32_t*)(sQ + (ro + 8)*2);
                ah[3] = *(const uint32_t*)(sQ + (ro + 8*72 + 8)*2);
                #pragma unroll
                for (int ni = 0; ni < 8; ni++) {
                    uint32_t bo = (uint32_t)((ni*8 + (lane >> 2)) * 72 + ks*16 + (lane & 3)*2);
                    uint32_t b0 = *(const uint32_t*)(sK + bo*2);
                    uint32_t b1 = *(const uint32_t*)(sK + (bo + 8)*2);
                    mma_bf16(S[ts*8+ni], ah, b0, b1);
                }
            }
        }
    }

    // ---- scale + causal mask ----
    int tA = tq*64 + wid*16 + (lane >> 2);
    int tB = tA + 8;
    #pragma unroll
    for (int j = 0; j < 32; j++) {
        int s0 = j*8 + (lane & 3)*2, s1 = s0 + 1;
        S[j][0] = (s0 <= tA) ? S[j][0]*0.125f : -1e30f;
        S[j][1] = (s1 <= tA) ? S[j][1]*0.125f : -1e30f;
        S[j][2] = (s0 <= tB) ? S[j][2]*0.125f : -1e30f;
        S[j][3] = (s1 <= tB) ? S[j][3]*0.125f : -1e30f;
    }
    // ---- softmax (rows fully in-quad) ----
    float mA = -1e30f, mB = -1e30f;
    #pragma unroll
    for (int j = 0; j < 32; j++) {
        mA = fmaxf(mA, fmaxf(S[j][0], S[j][1]));
        mB = fmaxf(mB, fmaxf(S[j][2], S[j][3]));
    }
    mA = fmaxf(mA, __shfl_xor_sync(0xFFFFFFFFu, mA, 1));
    mA = fmaxf(mA, __shfl_xor_sync(0xFFFFFFFFu, mA, 2));
    mB = fmaxf(mB, __shfl_xor_sync(0xFFFFFFFFu, mB, 1));
    mB = fmaxf(mB, __shfl_xor_sync(0xFFFFFFFFu, mB, 2));
    float sA = 0.f, sB = 0.f;
    #pragma unroll
    for (int j = 0; j < 32; j++) {
        S[j][0] = expf(S[j][0] - mA); S[j][1] = expf(S[j][1] - mA);
        S[j][2] = expf(S[j][2] - mB); S[j][3] = expf(S[j][3] - mB);
        sA += S[j][0] + S[j][1];
        sB += S[j][2] + S[j][3];
    }
    sA += __shfl_xor_sync(0xFFFFFFFFu, sA, 1);
    sA += __shfl_xor_sync(0xFFFFFFFFu, sA, 2);
    sB += __shfl_xor_sync(0xFFFFFFFFu, sB, 1);
    sB += __shfl_xor_sync(0xFFFFFFFFu, sB, 2);
    float iA = 1.f / sA, iB = 1.f / sB;
    #pragma unroll
    for (int j = 0; j < 32; j++) {
        S[j][0] *= iA; S[j][1] *= iA; S[j][2] *= iB; S[j][3] *= iB;
    }

    // ---- O = P @ V (bf16 P packed on the fly) ----
    float O[8][4];
    #pragma unroll
    for (int j = 0; j < 8; j++) { O[j][0]=0.f; O[j][1]=0.f; O[j][2]=0.f; O[j][3]=0.f; }
    #pragma unroll
    for (int ts = 0; ts < 4; ts++) {
        if (ts <= tq) {
            __syncthreads();
            #pragma unroll
            for (int i = tx; i < 1024; i += 128) {
                int g = i >> 4, c4 = (i & 15) << 2;
                size_t src = ((size_t)n*GDc + g)*(Bc*Tc) + b*Tc + ts*64 + c4;
                uint32_t off = (uint32_t)(g * 72 + c4) * 2;
                *(uint2*)(sK + off) = *(const uint2*)(g_vTh + src);
            }
            __syncthreads();
            #pragma unroll
            for (int kc = 0; kc < 4; kc++) {
                int j0 = ts*8 + 2*kc, j1 = j0 + 1;
                uint32_t ph[4];
                ph[0] = packbf(S[j0][0], S[j0][1]);
                ph[1] = packbf(S[j0][2], S[j0][3]);
                ph[2] = packbf(S[j1][0], S[j1][1]);
                ph[3] = packbf(S[j1][2], S[j1][3]);
                #pragma unroll
                for (int ni = 0; ni < 8; ni++) {
                    uint32_t bo = (uint32_t)((ni*8 + (lane >> 2)) * 72 + kc*16 + (lane & 3)*2);
                    uint32_t b0 = *(const uint32_t*)(sK + bo*2);
                    uint32_t b1 = *(const uint32_t*)(sK + (bo + 8)*2);
                    mma_bf16(O[ni], ph, b0, b1);
                }
            }
        }
    }

    // ---- fused epilogue: write att; y = rms(xi + att*apsum) ----
    size_t rowA = (size_t)n*Bc*Tc + b*Tc + tA;
    size_t rowB = rowA + 8;
    float ssA = 0.f, ssB = 0.f;
    #pragma unroll
    for (int ni = 0; ni < 8; ni++) {
        int g = ni*8 + (lane & 3)*2;
        *(float2*)(g_att + rowA*GDc + g) = make_float2(O[ni][0], O[ni][1]);
        *(float2*)(g_att + rowB*GDc + g) = make_float2(O[ni][2], O[ni][3]);
        float2 xA = *(const float2*)(g_xi + rowA*GDc + g);
        float2 xB = *(const float2*)(g_xi + rowB*GDc + g);
        float2 ap = *(const float2*)(g_apsum + n*GDc + g);
        float m0 = xA.x + O[ni][0]*ap.x, m1 = xA.y + O[ni][1]*ap.y;
        float m2 = xB.x + O[ni][2]*ap.x, m3 = xB.y + O[ni][3]*ap.y;
        O[ni][0] = m0; O[ni][1] = m1; O[ni][2] = m2; O[ni][3] = m3;
        ssA += m0*m0 + m1*m1;
        ssB += m2*m2 + m3*m3;
    }
    ssA += __shfl_xor_sync(0xFFFFFFFFu, ssA, 1);
    ssA += __shfl_xor_sync(0xFFFFFFFFu, ssA, 2);
    ssB += __shfl_xor_sync(0xFFFFFFFFu, ssB, 1);
    ssB += __shfl_xor_sync(0xFFFFFFFFu, ssB, 2);
    float rA = rsqrtf(ssA / (float)GDc + EPSc);
    float rB = rsqrtf(ssB / (float)GDc + EPSc);
    #pragma unroll
    for (int ni = 0; ni < 8; ni++) {
        int g = ni*8 + (lane & 3)*2;
        *(float2*)(g_y + rowA*GDc + g) = make_float2(O[ni][0]*rA, O[ni][1]*rA);
        *(float2*)(g_y + rowB*GDc + g) = make_float2(O[ni][2]*rB, O[ni][3]*rB);
    }
}

// ---------------- fc via HMMA (3-term split): fcsum = sum_o relu(y @ W^T)^2 ----------------
#define SF_AH 0
#define SF_AL 18432
#define SF_BH 36864
#define SF_BL 46080
#define SF_RS 55296
#define SMEM_FC 56320

__global__ void __launch_bounds__(256) k_fcmma(
    const __nv_bfloat16* __restrict__ Wh, const __nv_bfloat16* __restrict__ Wl)
{
    extern __shared__ char sm[];
    int tx = threadIdx.x, wid = tx >> 5, lane = tx & 31;
    int wm = wid & 3, wn = wid >> 2;
    int btile = blockIdx.x, n = blockIdx.y;
    const float* A = g_y + ((size_t)n * Bc*Tc + btile*128) * GDc;

    #pragma unroll
    for (int i = tx; i < 2048; i += 256) {
        int r = i >> 4, c4 = (i & 15) << 2;
        float4 v = *(const float4*)(A + (size_t)r * GDc + c4);
        uint2 hw, lw;
        hw.x = packbf(v.x, v.y); hw.y = packbf(v.z, v.w);
        lw.x = packbf(v.x - bfhi(v.x), v.y - bfhi(v.y));
        lw.y = packbf(v.z - bfhi(v.z), v.w - bfhi(v.w));
        uint32_t off = (uint32_t)(r * 72 + c4) * 2;
        *(uint2*)(sm + SF_AH + off) = hw;
        *(uint2*)(sm + SF_AL + off) = lw;
    }

    float rs[4] = {0.f, 0.f, 0.f, 0.f};
    for (int nc = 0; nc < 4; nc++) {
        #pragma unroll
        for (int i = tx; i < 1024; i += 256) {
            int r = i >> 4, c4 = (i & 15) << 2;
            size_t g = ((size_t)n * 256 + nc*64 + r) * GDc + c4;
            uint32_t off = (uint32_t)(r * 72 + c4) * 2;
            *(uint2*)(sm + SF_BH + off) = *(const uint2*)(Wh + g);
            *(uint2*)(sm + SF_BL + off) = *(const uint2*)(Wl + g);
        }
        __syncthreads();
        float acc[2][4][4];
        #pragma unroll
        for (int i = 0; i < 2; i++)
            #pragma unroll
            for (int j = 0; j < 4; j++)
                #pragma unroll
                for (int q = 0; q < 4; q++) acc[i][j][q] = 0.f;
        #pragma unroll
        for (int ks = 0; ks < 4; ks++) {
            uint32_t ah[2][4], al[2][4];
            #pragma unroll
            for (int mi = 0; mi < 2; mi++) {
                uint32_t ro = (uint32_t)((wm*32 + mi*16 + (lane >> 2)) * 72 + ks*16 + (lane & 3)*2);
                ah[mi][0] = *(const uint32_t*)(sm + SF_AH + ro*2);
                ah[mi][1] = *(const uint32_t*)(sm + SF_AH + (ro + 8*72)*2);
                ah[mi][2] = *(const uint32_t*)(sm + SF_AH + (ro + 8)*2);
                ah[mi][3] = *(const uint32_t*)(sm + SF_AH + (ro + 8*72 + 8)*2);
                al[mi][0] = *(const uint32_t*)(sm + SF_AL + ro*2);
                al[mi][1] = *(const uint32_t*)(sm + SF_AL + (ro + 8*72)*2);
                al[mi][2] = *(const uint32_t*)(sm + SF_AL + (ro + 8)*2);
                al[mi][3] = *(const uint32_t*)(sm + SF_AL + (ro + 8*72 + 8)*2);
            }
            #pragma unroll
            for (int ni = 0; ni < 4; ni++) {
                uint32_t bo = (uint32_t)((wn*32 + ni*8 + (lane >> 2)) * 72 + ks*16 + (lane & 3)*2);
                uint32_t bh0 = *(const uint32_t*)(sm + SF_BH + bo*2);
                uint32_t bh1 = *(const uint32_t*)(sm + SF_BH + (bo + 8)*2);
                uint32_t bl0 = *(const uint32_t*)(sm + SF_BL + bo*2);
                uint32_t bl1 = *(const uint32_t*)(sm + SF_BL + (bo + 8)*2);
                #pragma unroll
                for (int mi = 0; mi < 2; mi++) {
                    mma_bf16(acc[mi][ni], ah[mi], bh0, bh1);
                    mma_bf16(acc[mi][ni], ah[mi], bl0, bl1);
                    mma_bf16(acc[mi][ni], al[mi], bh0, bh1);
                }
            }
        }
        #pragma unroll
        for (int mi = 0; mi < 2; mi++)
            #pragma unroll
            for (int ni = 0; ni < 4; ni++) {
                float f0 = fmaxf(acc[mi][ni][0], 0.f), f1 = fmaxf(acc[mi][ni][1], 0.f);
                float f2 = fmaxf(acc[mi][ni][2], 0.f), f3 = fmaxf(acc[mi][ni][3], 0.f);
                rs[mi*2+0] += f0*f0 + f1*f1;
                rs[mi*2+1] += f2*f2 + f3*f3;
            }
        __syncthreads();
    }
    #pragma unroll
    for (int j = 0; j < 4; j++) {
        rs[j] += __shfl_xor_sync(0xFFFFFFFFu, rs[j], 1);
        rs[j] += __shfl_xor_sync(0xFFFFFFFFu, rs[j], 2);
    }
    float* srs = (float*)(sm + SF_RS);
    if ((lane & 3) == 0) {
        int rr = lane >> 2;
        #pragma unroll
        for (int mi = 0; mi < 2; mi++) {
            srs[wn*128 + wm*32 + mi*16 + rr]     = rs[mi*2+0];
            srs[wn*128 + wm*32 + mi*16 + rr + 8] = rs[mi*2+1];
        }
    }
    __syncthreads();
    if (tx < 128)
        g_fcsum[(size_t)n * Bc*Tc + btile*128 + tx] = srs[tx] + srs[128 + tx];
}

// ---------------- elementwise per-step kernels ----------------
__global__ void k_update(const float* __restrict__ router_w, const float* __restrict__ router_b, int step) {
    int bt = blockIdx.x;
    int e = threadIdx.x;
    __shared__ float sred[Ec];
    int gi = e >> 6, gd = e & 63;
    float fu = 0.f;
    #pragma unroll
    for (int l = 0; l < Lc; l++) {
        int n = l*Gc + gi;
        size_t row = (size_t)n*Bc*Tc + bt;
        float att = g_att[row*GDc + gd];
        float aps = g_apsum[n*GDc + gd];
        float fcs = g_fcsum[row];
        float mps = g_mpsum[n*GDc + gd];
        float w   = g_weff[step*NU + n];
        fu += (att*aps + fcs*mps) * w;
    }
    float pc = g_pcont[bt];
    float xv = g_x[(size_t)bt*Ec + e] + fu * pc;
    g_x[(size_t)bt*Ec + e] = xv;
    sred[e] = xv * router_w[e];
    __syncthreads();
    for (int s = 256; s > 0; s >>= 1) { if (e < s) sred[e] += sred[e+s]; __syncthreads(); }
    if (e == 0) {
        float ph = 1.f / (1.f + expf(-(sred[0] + router_b[0])));
        g_pcont[bt] = pc * (1.f - ph);
    }
}

__global__ void k_rmsfinal() {
    int bt = blockIdx.x;
    int tx = threadIdx.x;
    __shared__ float sred[256];
    float a = g_x[(size_t)bt*Ec + tx], b = g_x[(size_t)bt*Ec + tx + 256];
    sred[tx] = a*a + b*b;
    __syncthreads();
    for (int s = 128; s > 0; s >>= 1) { if (tx < s) sred[tx] += sred[tx+s]; __syncthreads(); }
    float r = rsqrtf(sred[0] / (float)Ec + EPSc);
    g_xn[(size_t)bt*Ec + tx]       = a*r;
    g_xn[(size_t)bt*Ec + tx + 256] = b*r;
}

// ---------------- launch ----------------
extern "C" void kernel_launch(void* const* d_in, const int* in_sizes, int n_in,
                              void* d_out, int out_size) {
    const int*   idx       = (const int*)  d_in[0];
    const float* wte       = (const float*)d_in[2];
    const float* adapters  = (const float*)d_in[3];
    const float* qkv_w     = (const float*)d_in[4];
    const float* attn_proj = (const float*)d_in[5];
    const float* mlp_fc    = (const float*)d_in[6];
    const float* mlp_proj  = (const float*)d_in[7];
    const float* dep       = (const float*)d_in[8];
    const float* router_w  = (const float*)d_in[9];
    const float* router_b  = (const float*)d_in[10];
    const float* lm_head   = (const float*)d_in[11];
    float* out = (float*)d_out;

    float *px, *pxn, *padap, *pxi;
    __nv_bfloat16 *pah, *pal, *pfh, *pfl, *plh, *pll, *pqh;
    cudaGetSymbolAddress((void**)&px,    g_x);
    cudaGetSymbolAddress((void**)&pxn,   g_xn);
    cudaGetSymbolAddress((void**)&padap, g_adap);
    cudaGetSymbolAddress((void**)&pxi,   g_xi);
    cudaGetSymbolAddress((void**)&pah,   g_adap_h);
    cudaGetSymbolAddress((void**)&pal,   g_adap_l);
    cudaGetSymbolAddress((void**)&pfh,   g_fcw_h);
    cudaGetSymbolAddress((void**)&pfl,   g_fcw_l);
    cudaGetSymbolAddress((void**)&plh,   g_lmh_h);
    cudaGetSymbolAddress((void**)&pll,   g_lmh_l);
    cudaGetSymbolAddress((void**)&pqh,   g_qkvw_h);

    cudaFuncSetAttribute((const void*)mma_gemm<1,2>, cudaFuncAttributeMaxDynamicSharedMemorySize, SMEM_G2);
    cudaFuncSetAttribute((const void*)mma_gemm<2,1>, cudaFuncAttributeMaxDynamicSharedMemorySize, SMEM_G1);
    cudaFuncSetAttribute(k_fcmma,  cudaFuncAttributeMaxDynamicSharedMemorySize, SMEM_FC);
    cudaFuncSetAttribute(k_qkvmma, cudaFuncAttributeMaxDynamicSharedMemorySize, SMEM_QKV2);

    k_tables<<<Tc, 32>>>();
    k_depths<<<1, NU>>>(dep);
    k_sums<<<(NU*GDc + 255)/256, 256>>>(attn_proj, mlp_proj);
    k_adap<<<(NU*GDc*Ec)/256, 256>>>(adapters);
    k_split<<<(NU*GDc*Ec + 255)/256, 256>>>(padap, pah, pal, NU*GDc*Ec, NU*GDc*Ec);
    k_split<<<(NU*256*GDc + 255)/256, 256>>>(mlp_fc, pfh, pfl, NU*256*GDc, NU*256*GDc);
    k_split<<<(NU*192*GDc + 255)/256, 256>>>(qkv_w, pqh, (__nv_bfloat16*)nullptr, NU*192*GDc, NU*192*GDc);
    k_split<<<(VPAD*Ec + 255)/256, 256>>>(lm_head, plh, pll, Vc*Ec, VPAD*Ec);
    k_embed<<<Bc*Tc, 256>>>(idx, wte);

    for (int t = 0; t < Sc; t++) {
        mma_gemm<2,1><<<dim3(32, 4), 256, SMEM_G1>>>(px, pah, pal, pxi, Bc*Tc, NU*GDc, Ec);
        k_qkvmma<<<dim3(Bc*Tc/128, NU), 256, SMEM_QKV2>>>();
        k_attn<<<dim3(4, NU, Bc), 128>>>();
        k_fcmma<<<dim3(Bc*Tc/128, NU), 256, SMEM_FC>>>(pfh, pfl);
        k_update<<<Bc*Tc, Ec>>>(router_w, router_b, t);
    }

    k_rmsfinal<<<Bc*Tc, 256>>>();
    // logits: M=512 (2 x 256-row blocks), N=50257 (padded 50304), K=512
    mma_gemm<1,2><<<dim3(VPAD/128, 2), 256, SMEM_G2>>>(pxn, plh, pll, out, Bc*Tc, Vc, Ec);
}

// round 10
// speedup vs baseline: 50.9879x; 1.1491x over previous
#include <cuda_runtime.h>
#include <cuda_bf16.h>
#include <math.h>
#include <stdint.h>

#define Bc 2
#define Tc 256
#define Ec 512
#define Gc 8
#define GDc 64
#define Lc 8
#define NU 64
#define Vc 50257
#define VPAD 50304
#define Sc 8
#define EPSc 1.1920929e-7f

// ---------------- device scratch (no allocations allowed) ----------------
__device__ float g_x[Bc*Tc*Ec];
__device__ float g_xn[Bc*Tc*Ec];
__device__ float g_pcont[Bc*Tc];
__device__ float g_cos[Tc*32];
__device__ float g_sin[Tc*32];
__device__ float g_weff[Sc*NU];
__device__ float g_apsum[NU*GDc];
__device__ float g_mpsum[NU*GDc];
__device__ float g_adap[NU*GDc*Ec];          // adapters + folded identity skip
__device__ float g_att[NU*Bc*Tc*GDc];        // [n][bt][gd]
__device__ float g_fcsum[NU*Bc*Tc];
// bf16 weights / activations, 16B-aligned for vector loads
__device__ __align__(16) __nv_bfloat16 g_adap_h[NU*GDc*Ec], g_adap_l[NU*GDc*Ec];
__device__ __align__(16) __nv_bfloat16 g_fcw_h[NU*256*GDc];
__device__ __align__(16) __nv_bfloat16 g_lmh_h[VPAD*Ec],    g_lmh_l[VPAD*Ec];
__device__ __align__(16) __nv_bfloat16 g_qkvw_h[NU*192*GDc];
__device__ __align__(16) __nv_bfloat16 g_xih[NU*Bc*Tc*GDc];
__device__ __align__(16) __nv_bfloat16 g_qsh[NU*Bc*Tc*GDc];
__device__ __align__(16) __nv_bfloat16 g_ksh[NU*Bc*Tc*GDc];
__device__ __align__(16) __nv_bfloat16 g_vTh[NU*GDc*Bc*Tc];   // [n][g][bt]
__device__ __align__(16) __nv_bfloat16 g_ysh[NU*Bc*Tc*GDc];

// ---------------- helpers ----------------
__device__ __forceinline__ void mma_bf16(float* d, const uint32_t* a, uint32_t b0, uint32_t b1) {
    asm volatile("mma.sync.aligned.m16n8k16.row.col.f32.bf16.bf16.f32 "
        "{%0,%1,%2,%3}, {%4,%5,%6,%7}, {%8,%9}, {%0,%1,%2,%3};"
        : "+f"(d[0]), "+f"(d[1]), "+f"(d[2]), "+f"(d[3])
        : "r"(a[0]), "r"(a[1]), "r"(a[2]), "r"(a[3]), "r"(b0), "r"(b1));
}
__device__ __forceinline__ uint32_t packbf(float x, float y) {
    return (uint32_t)__bfloat16_as_ushort(__float2bfloat16(x)) |
           ((uint32_t)__bfloat16_as_ushort(__float2bfloat16(y)) << 16);
}
__device__ __forceinline__ float bfhi(float x) {
    return __bfloat162float(__float2bfloat16(x));
}
__device__ __forceinline__ float2 unpackbf(uint32_t v) {
    return make_float2(
        __bfloat162float(__ushort_as_bfloat16((unsigned short)(v & 0xFFFF))),
        __bfloat162float(__ushort_as_bfloat16((unsigned short)(v >> 16))));
}
__device__ __forceinline__ uint32_t smem_u32(const void* p) {
    uint32_t a;
    asm("{ .reg .u64 t; cvta.to.shared.u64 t, %1; cvt.u32.u64 %0, t; }" : "=r"(a) : "l"(p));
    return a;
}
__device__ __forceinline__ void cp_async16(uint32_t saddr, const void* gaddr) {
    asm volatile("cp.async.ca.shared.global [%0], [%1], 16;" :: "r"(saddr), "l"(gaddr));
}
#define CP_COMMIT() asm volatile("cp.async.commit_group;" ::: "memory")
#define CP_WAIT0()  asm volatile("cp.async.wait_group 0;" ::: "memory")

// ---------------- prep kernels ----------------
__global__ void k_tables() {
    int t = blockIdx.x, i = threadIdx.x;
    double invf = pow(10000.0, -((double)(2*i)) / (double)GDc);
    double f = (double)t * invf;
    g_cos[t*32+i] = (float)cos(f);
    g_sin[t*32+i] = (float)sin(f);
}

__global__ void k_depths(const float* __restrict__ dep) {
    int n = threadIdx.x;
    __shared__ float d0[NU], d1[NU];
    d0[n] = 0.f; __syncthreads();
    for (int it = 0; it < Lc; it++) {
        float acc = 0.f;
        for (int j = 0; j < NU; j++)
            acc += fmaxf(dep[n*NU+j], 0.f) * (d0[j] + 1.f);
        d1[n] = acc; __syncthreads();
        d0[n] = d1[n]; __syncthreads();
    }
    float dn = d0[n];
    for (int t = 0; t < Sc; t++) {
        float td = (float)t * ((float)Lc / (float)Sc);
        float w = expf(-fabsf(dn - td));
        g_weff[t*NU+n] = (w > 0.15f) ? w : 0.f;
    }
}

__global__ void k_sums(const float* __restrict__ ap, const float* __restrict__ mp) {
    int i = blockIdx.x*blockDim.x + threadIdx.x;
    if (i >= NU*GDc) return;
    float s = 0.f;
    for (int k = 0; k < GDc; k++) s += ap[i*GDc + k];
    g_apsum[i] = s;
    float s2 = 0.f;
    for (int k = 0; k < 4*GDc; k++) s2 += mp[i*4*GDc + k];
    g_mpsum[i] = s2;
}

__global__ void k_adap(const float* __restrict__ adapters) {
    int tid = blockIdx.x*blockDim.x + threadIdx.x;
    int row = tid >> 9;
    int e   = tid & 511;
    int n = row >> 6, g = row & 63;
    float add = (e == ((n & (Gc-1))*GDc + g)) ? 1.f : 0.f;
    g_adap[tid] = adapters[tid] + add;
}

__global__ void k_split(const float* __restrict__ src, __nv_bfloat16* __restrict__ h,
                        __nv_bfloat16* __restrict__ l, int n_src, int n_pad) {
    int i = blockIdx.x*blockDim.x + threadIdx.x;
    if (i >= n_pad) return;
    float v = (i < n_src) ? src[i] : 0.f;
    __nv_bfloat16 hv = __float2bfloat16(v);
    h[i] = hv;
    if (l) l[i] = __float2bfloat16(v - __bfloat162float(hv));
}

__global__ void k_embed(const int* __restrict__ idx, const float* __restrict__ wte) {
    int bt = blockIdx.x;
    int tx = threadIdx.x;
    __shared__ float sred[256];
    int row = idx[bt];
    const float* w = wte + (size_t)row * Ec;
    float a = w[tx], b = w[tx+256];
    sred[tx] = a*a + b*b;
    __syncthreads();
    for (int s = 128; s > 0; s >>= 1) { if (tx < s) sred[tx] += sred[tx+s]; __syncthreads(); }
    float r = rsqrtf(sred[0] / (float)Ec + EPSc);
    g_x[(size_t)bt*Ec + tx]       = a*r;
    g_x[(size_t)bt*Ec + tx + 256] = b*r;
    if (tx == 0) g_pcont[bt] = 1.f;
}

// ---------------- HMMA split-bf16 GEMM ----------------
// MODE 1: 15*tanh(c/15), scalar stores (N odd). MODE 2: bf16-hi xi n-major scatter only.
// DM: 128-row M sub-tiles per block. SPLIT: 3 = AhBh+AhBl+AlBh; 2 = (Ah+Al)Bh (no Bl).
#define SMEM_XI 55296     // DM=1, SPLIT=2
#define SMEM_LM 110592    // DM=2, SPLIT=3

template<int MODE, int DM, int SPLIT>
__global__ void __launch_bounds__(256) mma_gemm(
    const float* __restrict__ A, const __nv_bfloat16* __restrict__ Bh,
    const __nv_bfloat16* __restrict__ Bl, float* __restrict__ C,
    int M, int N, int K)
{
    extern __shared__ char sm[];
    const int oAH = 0, oAL = DM*18432, oBH = 2*DM*18432, oBL = 2*DM*18432 + 18432;
    uint32_t sb = smem_u32(sm);
    int tx = threadIdx.x, wid = tx >> 5, lane = tx & 31;
    int wm = wid & 3, wn = wid >> 2;
    int bm = blockIdx.y * (128*DM), bn = blockIdx.x * 128;

    float acc[DM][2][8][4];
    #pragma unroll
    for (int mt = 0; mt < DM; mt++)
        #pragma unroll
        for (int i = 0; i < 2; i++)
            #pragma unroll
            for (int j = 0; j < 8; j++)
                #pragma unroll
                for (int q = 0; q < 4; q++) acc[mt][i][j][q] = 0.f;

    int nchunks = K >> 6;
    for (int ch = 0; ch < nchunks; ch++) {
        int k0 = ch << 6;
        // issue async B loads first (latency hidden behind A conversion)
        #pragma unroll
        for (int i = tx; i < 1024; i += 256) {
            int r = i >> 3, c8 = (i & 7) << 3;
            size_t g = (size_t)(bn + r) * K + k0 + c8;
            uint32_t off = (uint32_t)(r * 72 + c8) * 2;
            cp_async16(sb + oBH + off, Bh + g);
            if (SPLIT == 3) cp_async16(sb + oBL + off, Bl + g);
        }
        CP_COMMIT();
        // stage + split A (fp32 -> bf16 hi/lo)
        #pragma unroll
        for (int i = tx; i < DM*2048; i += 256) {
            int r = i >> 4, c4 = (i & 15) << 2;
            float4 v = *(const float4*)(A + (size_t)(bm + r) * K + k0 + c4);
            uint2 hw, lw;
            hw.x = packbf(v.x, v.y); hw.y = packbf(v.z, v.w);
            lw.x = packbf(v.x - bfhi(v.x), v.y - bfhi(v.y));
            lw.y = packbf(v.z - bfhi(v.z), v.w - bfhi(v.w));
            uint32_t off = (uint32_t)(r * 72 + c4) * 2;
            *(uint2*)(sm + oAH + off) = hw;
            *(uint2*)(sm + oAL + off) = lw;
        }
        CP_WAIT0();
        __syncthreads();
        #pragma unroll
        for (int ks = 0; ks < 4; ks++) {
            uint32_t ah[DM][2][4], al[DM][2][4];
            #pragma unroll
            for (int mt = 0; mt < DM; mt++)
                #pragma unroll
                for (int mi = 0; mi < 2; mi++) {
                    uint32_t ro = (uint32_t)((mt*128 + wm*32 + mi*16 + (lane >> 2)) * 72 + ks*16 + (lane & 3)*2);
                    ah[mt][mi][0] = *(const uint32_t*)(sm + oAH + ro*2);
                    ah[mt][mi][1] = *(const uint32_t*)(sm + oAH + (ro + 8*72)*2);
                    ah[mt][mi][2] = *(const uint32_t*)(sm + oAH + (ro + 8)*2);
                    ah[mt][mi][3] = *(const uint32_t*)(sm + oAH + (ro + 8*72 + 8)*2);
                    al[mt][mi][0] = *(const uint32_t*)(sm + oAL + ro*2);
                    al[mt][mi][1] = *(const uint32_t*)(sm + oAL + (ro + 8*72)*2);
                    al[mt][mi][2] = *(const uint32_t*)(sm + oAL + (ro + 8)*2);
                    al[mt][mi][3] = *(const uint32_t*)(sm + oAL + (ro + 8*72 + 8)*2);
                }
            #pragma unroll
            for (int ni = 0; ni < 8; ni++) {
                uint32_t bo = (uint32_t)((wn*64 + ni*8 + (lane >> 2)) * 72 + ks*16 + (lane & 3)*2);
                uint32_t bh0 = *(const uint32_t*)(sm + oBH + bo*2);
                uint32_t bh1 = *(const uint32_t*)(sm + oBH + (bo + 8)*2);
                uint32_t bl0 = 0, bl1 = 0;
                if (SPLIT == 3) {
                    bl0 = *(const uint32_t*)(sm + oBL + bo*2);
                    bl1 = *(const uint32_t*)(sm + oBL + (bo + 8)*2);
                }
                #pragma unroll
                for (int mt = 0; mt < DM; mt++)
                    #pragma unroll
                    for (int mi = 0; mi < 2; mi++) {
                        mma_bf16(acc[mt][mi][ni], ah[mt][mi], bh0, bh1);
                        if (SPLIT == 3) mma_bf16(acc[mt][mi][ni], ah[mt][mi], bl0, bl1);
                        mma_bf16(acc[mt][mi][ni], al[mt][mi], bh0, bh1);
                    }
            }
        }
        __syncthreads();
    }

    #pragma unroll
    for (int mt = 0; mt < DM; mt++)
        #pragma unroll
        for (int mi = 0; mi < 2; mi++) {
            int m = bm + mt*128 + wm*32 + mi*16 + (lane >> 2);
            #pragma unroll
            for (int ni = 0; ni < 8; ni++) {
                int n = bn + wn*64 + ni*8 + (lane & 3)*2;
                float v0 = acc[mt][mi][ni][0], v1 = acc[mt][mi][ni][1];
                float v2 = acc[mt][mi][ni][2], v3 = acc[mt][mi][ni][3];
                if (MODE == 1) {
                    if (n < N) {
                        C[(size_t)m*N + n]     = 15.f*tanhf(v0*(1.f/15.f));
                        C[(size_t)(m+8)*N + n] = 15.f*tanhf(v2*(1.f/15.f));
                    }
                    if (n + 1 < N) {
                        C[(size_t)m*N + n + 1]     = 15.f*tanhf(v1*(1.f/15.f));
                        C[(size_t)(m+8)*N + n + 1] = 15.f*tanhf(v3*(1.f/15.f));
                    }
                } else {
                    size_t b0 = ((size_t)(n >> 6) * M + m) * GDc + (n & 63);
                    size_t b2 = ((size_t)(n >> 6) * M + m + 8) * GDc + (n & 63);
                    *(uint32_t*)(g_xih + b0) = packbf(v0, v1);
                    *(uint32_t*)(g_xih + b2) = packbf(v2, v3);
                }
            }
        }
}

// ---------------- qkv via HMMA (bf16-only) + fused rope/rms ----------------
#define SQ2_A 0          // xi hi: 128x72 bf16 = 18432
#define SQ2_B 18432      // W  hi:  64x72 bf16 = 9216
#define SQ2_F 27648      // fp32 buf: 128x66 = 33792
#define SMEM_QKV2 61440

__global__ void __launch_bounds__(256) k_qkvmma() {
    extern __shared__ char sm[];
    float* sf = (float*)(sm + SQ2_F);
    int tx = threadIdx.x, wid = tx >> 5, lane = tx & 31;
    int wm = wid & 3, wn = wid >> 2;
    int btile = blockIdx.x, n = blockIdx.y;
    size_t abase = ((size_t)n * Bc*Tc + btile*128) * GDc;

    #pragma unroll
    for (int i = tx; i < 2048; i += 256) {
        int r = i >> 4, c4 = (i & 15) << 2;
        uint32_t off = (uint32_t)(r * 72 + c4) * 2;
        *(uint2*)(sm + SQ2_A + off) = *(const uint2*)(g_xih + abase + (size_t)r*GDc + c4);
    }

    for (int z = 0; z < 3; z++) {
        #pragma unroll
        for (int i = tx; i < 1024; i += 256) {
            int r = i >> 4, c4 = (i & 15) << 2;
            size_t g = ((size_t)n*192 + z*64 + r) * GDc + c4;
            uint32_t off = (uint32_t)(r * 72 + c4) * 2;
            *(uint2*)(sm + SQ2_B + off) = *(const uint2*)(g_qkvw_h + g);
        }
        __syncthreads();
        float acc[2][4][4];
        #pragma unroll
        for (int i = 0; i < 2; i++)
            #pragma unroll
            for (int j = 0; j < 4; j++)
                #pragma unroll
                for (int q = 0; q < 4; q++) acc[i][j][q] = 0.f;
        #pragma unroll
        for (int ks = 0; ks < 4; ks++) {
            uint32_t ah[2][4];
            #pragma unroll
            for (int mi = 0; mi < 2; mi++) {
                uint32_t ro = (uint32_t)((wm*32 + mi*16 + (lane >> 2)) * 72 + ks*16 + (lane & 3)*2);
                ah[mi][0] = *(const uint32_t*)(sm + SQ2_A + ro*2);
                ah[mi][1] = *(const uint32_t*)(sm + SQ2_A + (ro + 8*72)*2);
                ah[mi][2] = *(const uint32_t*)(sm + SQ2_A + (ro + 8)*2);
                ah[mi][3] = *(const uint32_t*)(sm + SQ2_A + (ro + 8*72 + 8)*2);
            }
            #pragma unroll
            for (int ni = 0; ni < 4; ni++) {
                uint32_t bo = (uint32_t)((wn*32 + ni*8 + (lane >> 2)) * 72 + ks*16 + (lane & 3)*2);
                uint32_t bh0 = *(const uint32_t*)(sm + SQ2_B + bo*2);
                uint32_t bh1 = *(const uint32_t*)(sm + SQ2_B + (bo + 8)*2);
                #pragma unroll
                for (int mi = 0; mi < 2; mi++)
                    mma_bf16(acc[mi][ni], ah[mi], bh0, bh1);
            }
        }
        #pragma unroll
        for (int mi = 0; mi < 2; mi++) {
            int m = wm*32 + mi*16 + (lane >> 2);
            #pragma unroll
            for (int ni = 0; ni < 4; ni++) {
                int g = wn*32 + ni*8 + (lane & 3)*2;
                sf[m*66 + g]     = acc[mi][ni][0];
                sf[m*66 + g + 1] = acc[mi][ni][1];
                sf[(m+8)*66 + g]     = acc[mi][ni][2];
                sf[(m+8)*66 + g + 1] = acc[mi][ni][3];
            }
        }
        __syncthreads();
        if (z < 2) {
            __nv_bfloat16* dst = (z == 0 ? g_qsh : g_ksh);
            #pragma unroll
            for (int rr = 0; rr < 16; rr++) {
                int row = rr*8 + wid;
                int t = (btile*128 + row) & (Tc-1);
                float c = g_cos[t*32 + lane], s = g_sin[t*32 + lane];
                float x1 = sf[row*66 + lane], x2 = sf[row*66 + lane + 32];
                float n1 = x1*c + x2*s, n2 = -x1*s + x2*c;
                float ss = n1*n1 + n2*n2;
                #pragma unroll
                for (int o = 16; o; o >>= 1) ss += __shfl_xor_sync(0xFFFFFFFFu, ss, o);
                float r_ = rsqrtf(ss / (float)GDc + EPSc);
                __nv_bfloat16* dp = dst + ((size_t)n*Bc*Tc + btile*128 + row)*GDc;
                dp[lane]      = __float2bfloat16(n1*r_);
                dp[lane + 32] = __float2bfloat16(n2*r_);
            }
        } else {
            for (int i = tx; i < 8192; i += 256) {
                int g = i >> 7, row = i & 127;
                g_vTh[((size_t)n*GDc + g)*(Bc*Tc) + btile*128 + row] =
                    __float2bfloat16(sf[row*66 + g]);
            }
        }
        __syncthreads();
    }
}

// ---------------- fused flash attention (bf16) + mid/rms epilogue ----------------
// grid (tq=4, n=64, b=2), 128 threads (4 warps x 16 rows).
__global__ void __launch_bounds__(128) k_attn() {
    __shared__ __align__(16) char sQ[9216], sK[9216];
    int tx = threadIdx.x, wid = tx >> 5, lane = tx & 31;
    int tq = blockIdx.x, n = blockIdx.y, b = blockIdx.z;
    size_t qbase = ((size_t)n*Bc*Tc + b*Tc + tq*64) * GDc;

    #pragma unroll
    for (int i = tx; i < 1024; i += 128) {
        int r = i >> 4, c4 = (i & 15) << 2;
        uint32_t off = (uint32_t)(r * 72 + c4) * 2;
        *(uint2*)(sQ + off) = *(const uint2*)(g_qsh + qbase + (size_t)r*GDc + c4);
    }

    float S[32][4];
    #pragma unroll
    for (int j = 0; j < 32; j++) {
        float init = (j < (tq+1)*8) ? 0.f : -1e30f;
        S[j][0] = init; S[j][1] = init; S[j][2] = init; S[j][3] = init;
    }

    #pragma unroll
    for (int ts = 0; ts < 4; ts++) {
        if (ts <= tq) {
            __syncthreads();
            size_t kbase = ((size_t)n*Bc*Tc + b*Tc + ts*64) * GDc;
            #pragma unroll
            for (int i = tx; i < 1024; i += 128) {
                int r = i >> 4, c4 = (i & 15) << 2;
                uint32_t off = (uint32_t)(r * 72 + c4) * 2;
                *(uint2*)(sK + off) = *(const uint2*)(g_ksh + kbase + (size_t)r*GDc + c4);
            }
            __syncthreads();
            #pragma unroll
            for (int ks = 0; ks < 4; ks++) {
                uint32_t ah[4];
                uint32_t ro = (uint32_t)((wid*16 + (lane >> 2)) * 72 + ks*16 + (lane & 3)*2);
                ah[0] = *(const uint32_t*)(sQ + ro*2);
                ah[1] = *(const uint32_t*)(sQ + (ro + 8*72)*2);
                ah[2] = *(const uint32_t*)(sQ + (ro + 8)*2);
                ah[3] = *(const uint32_t*)(sQ + (ro + 8*72 + 8)*2);
                #pragma unroll
                for (int ni = 0; ni < 8; ni++) {
                    uint32_t bo = (uint32_t)((ni*8 + (lane >> 2)) * 72 + ks*16 + (lane & 3)*2);
                    uint32_t b0 = *(const uint32_t*)(sK + bo*2);
                    uint32_t b1 = *(const uint32_t*)(sK + (bo + 8)*2);
                    mma_bf16(S[ts*8+ni], ah, b0, b1);
                }
            }
        }
    }

    int tA = tq*64 + wid*16 + (lane >> 2);
    int tB = tA + 8;
    #pragma unroll
    for (int j = 0; j < 32; j++) {
        int s0 = j*8 + (lane & 3)*2, s1 = s0 + 1;
        S[j][0] = (s0 <= tA) ? S[j][0]*0.125f : -1e30f;
        S[j][1] = (s1 <= tA) ? S[j][1]*0.125f : -1e30f;
        S[j][2] = (s0 <= tB) ? S[j][2]*0.125f : -1e30f;
        S[j][3] = (s1 <= tB) ? S[j][3]*0.125f : -1e30f;
    }
    float mA = -1e30f, mB = -1e30f;
    #pragma unroll
    for (int j = 0; j < 32; j++) {
        mA = fmaxf(mA, fmaxf(S[j][0], S[j][1]));
        mB = fmaxf(mB, fmaxf(S[j][2], S[j][3]));
    }
    mA = fmaxf(mA, __shfl_xor_sync(0xFFFFFFFFu, mA, 1));
    mA = fmaxf(mA, __shfl_xor_sync(0xFFFFFFFFu, mA, 2));
    mB = fmaxf(mB, __shfl_xor_sync(0xFFFFFFFFu, mB, 1));
    mB = fmaxf(mB, __shfl_xor_sync(0xFFFFFFFFu, mB, 2));
    float sA = 0.f, sB = 0.f;
    #pragma unroll
    for (int j = 0; j < 32; j++) {
        S[j][0] = expf(S[j][0] - mA); S[j][1] = expf(S[j][1] - mA);
        S[j][2] = expf(S[j][2] - mB); S[j][3] = expf(S[j][3] - mB);
        sA += S[j][0] + S[j][1];
        sB += S[j][2] + S[j][3];
    }
    sA += __shfl_xor_sync(0xFFFFFFFFu, sA, 1);
    sA += __shfl_xor_sync(0xFFFFFFFFu, sA, 2);
    sB += __shfl_xor_sync(0xFFFFFFFFu, sB, 1);
    sB += __shfl_xor_sync(0xFFFFFFFFu, sB, 2);
    float iA = 1.f / sA, iB = 1.f / sB;
    #pragma unroll
    for (int j = 0; j < 32; j++) {
        S[j][0] *= iA; S[j][1] *= iA; S[j][2] *= iB; S[j][3] *= iB;
    }

    float O[8][4];
    #pragma unroll
    for (int j = 0; j < 8; j++) { O[j][0]=0.f; O[j][1]=0.f; O[j][2]=0.f; O[j][3]=0.f; }
    #pragma unroll
    for (int ts = 0; ts < 4; ts++) {
        if (ts <= tq) {
            __syncthreads();
            #pragma unroll
            for (int i = tx; i < 1024; i += 128) {
                int g = i >> 4, c4 = (i & 15) << 2;
                size_t src = ((size_t)n*GDc + g)*(Bc*Tc) + b*Tc + ts*64 + c4;
                uint32_t off = (uint32_t)(g * 72 + c4) * 2;
                *(uint2*)(sK + off) = *(const uint2*)(g_vTh + src);
            }
            __syncthreads();
            #pragma unroll
            for (int kc = 0; kc < 4; kc++) {
                int j0 = ts*8 + 2*kc, j1 = j0 + 1;
                uint32_t ph[4];
                ph[0] = packbf(S[j0][0], S[j0][1]);
                ph[1] = packbf(S[j0][2], S[j0][3]);
                ph[2] = packbf(S[j1][0], S[j1][1]);
                ph[3] = packbf(S[j1][2], S[j1][3]);
                #pragma unroll
                for (int ni = 0; ni < 8; ni++) {
                    uint32_t bo = (uint32_t)((ni*8 + (lane >> 2)) * 72 + kc*16 + (lane & 3)*2);
                    uint32_t b0 = *(const uint32_t*)(sK + bo*2);
                    uint32_t b1 = *(const uint32_t*)(sK + (bo + 8)*2);
                    mma_bf16(O[ni], ph, b0, b1);
                }
            }
        }
    }

    // ---- fused epilogue: write att; y = rms(xi + att*apsum) -> bf16 ----
    size_t rowA = (size_t)n*Bc*Tc + b*Tc + tA;
    size_t rowB = rowA + 8;
    float ssA = 0.f, ssB = 0.f;
    #pragma unroll
    for (int ni = 0; ni < 8; ni++) {
        int g = ni*8 + (lane & 3)*2;
        *(float2*)(g_att + rowA*GDc + g) = make_float2(O[ni][0], O[ni][1]);
        *(float2*)(g_att + rowB*GDc + g) = make_float2(O[ni][2], O[ni][3]);
        float2 xA = unpackbf(*(const uint32_t*)(g_xih + rowA*GDc + g));
        float2 xB = unpackbf(*(const uint32_t*)(g_xih + rowB*GDc + g));
        float2 ap = *(const float2*)(g_apsum + n*GDc + g);
        float m0 = xA.x + O[ni][0]*ap.x, m1 = xA.y + O[ni][1]*ap.y;
        float m2 = xB.x + O[ni][2]*ap.x, m3 = xB.y + O[ni][3]*ap.y;
        O[ni][0] = m0; O[ni][1] = m1; O[ni][2] = m2; O[ni][3] = m3;
        ssA += m0*m0 + m1*m1;
        ssB += m2*m2 + m3*m3;
    }
    ssA += __shfl_xor_sync(0xFFFFFFFFu, ssA, 1);
    ssA += __shfl_xor_sync(0xFFFFFFFFu, ssA, 2);
    ssB += __shfl_xor_sync(0xFFFFFFFFu, ssB, 1);
    ssB += __shfl_xor_sync(0xFFFFFFFFu, ssB, 2);
    float rA = rsqrtf(ssA / (float)GDc + EPSc);
    float rB = rsqrtf(ssB / (float)GDc + EPSc);
    #pragma unroll
    for (int ni = 0; ni < 8; ni++) {
        int g = ni*8 + (lane & 3)*2;
        *(uint32_t*)(g_ysh + rowA*GDc + g) = packbf(O[ni][0]*rA, O[ni][1]*rA);
        *(uint32_t*)(g_ysh + rowB*GDc + g) = packbf(O[ni][2]*rB, O[ni][3]*rB);
    }
}

// ---------------- fc via HMMA (plain bf16): fcsum = sum_o relu(y @ W^T)^2 ----------------
#define SFC_A 0          // y bf16: 128x72 = 18432
#define SFC_B 18432      // W bf16:  64x72 = 9216
#define SFC_RS 27648     // 256 floats
#define SMEM_FC2 28672

__global__ void __launch_bounds__(256) k_fcmma(const __nv_bfloat16* __restrict__ Wh) {
    extern __shared__ char sm[];
    int tx = threadIdx.x, wid = tx >> 5, lane = tx & 31;
    int wm = wid & 3, wn = wid >> 2;
    int btile = blockIdx.x, n = blockIdx.y;
    size_t abase = ((size_t)n * Bc*Tc + btile*128) * GDc;

    #pragma unroll
    for (int i = tx; i < 1024; i += 256) {
        int r = i >> 3, c8 = (i & 7) << 3;
        *(uint4*)(sm + SFC_A + (uint32_t)(r*72 + c8)*2) =
            *(const uint4*)(g_ysh + abase + (size_t)r*GDc + c8);
    }

    float rs[4] = {0.f, 0.f, 0.f, 0.f};
    for (int nc = 0; nc < 4; nc++) {
        #pragma unroll
        for (int i = tx; i < 512; i += 256) {
            int r = i >> 3, c8 = (i & 7) << 3;
            *(uint4*)(sm + SFC_B + (uint32_t)(r*72 + c8)*2) =
                *(const uint4*)(Wh + ((size_t)n*256 + nc*64 + r)*GDc + c8);
        }
        __syncthreads();
        float acc[2][4][4];
        #pragma unroll
        for (int i = 0; i < 2; i++)
            #pragma unroll
            for (int j = 0; j < 4; j++)
                #pragma unroll
                for (int q = 0; q < 4; q++) acc[i][j][q] = 0.f;
        #pragma unroll
        for (int ks = 0; ks < 4; ks++) {
            uint32_t ah[2][4];
            #pragma unroll
            for (int mi = 0; mi < 2; mi++) {
                uint32_t ro = (uint32_t)((wm*32 + mi*16 + (lane >> 2)) * 72 + ks*16 + (lane & 3)*2);
                ah[mi][0] = *(const uint32_t*)(sm + SFC_A + ro*2);
                ah[mi][1] = *(const uint32_t*)(sm + SFC_A + (ro + 8*72)*2);
                ah[mi][2] = *(const uint32_t*)(sm + SFC_A + (ro + 8)*2);
                ah[mi][3] = *(const uint32_t*)(sm + SFC_A + (ro + 8*72 + 8)*2);
            }
            #pragma unroll
            for (int ni = 0; ni < 4; ni++) {
                uint32_t bo = (uint32_t)((wn*32 + ni*8 + (lane >> 2)) * 72 + ks*16 + (lane & 3)*2);
                uint32_t b0 = *(const uint32_t*)(sm + SFC_B + bo*2);
                uint32_t b1 = *(const uint32_t*)(sm + SFC_B + (bo + 8)*2);
                #pragma unroll
                for (int mi = 0; mi < 2; mi++)
                    mma_bf16(acc[mi][ni], ah[mi], b0, b1);
            }
        }
        #pragma unroll
        for (int mi = 0; mi < 2; mi++)
            #pragma unroll
            for (int ni = 0; ni < 4; ni++) {
                float f0 = fmaxf(acc[mi][ni][0], 0.f), f1 = fmaxf(acc[mi][ni][1], 0.f);
                float f2 = fmaxf(acc[mi][ni][2], 0.f), f3 = fmaxf(acc[mi][ni][3], 0.f);
                rs[mi*2+0] += f0*f0 + f1*f1;
                rs[mi*2+1] += f2*f2 + f3*f3;
            }
        __syncthreads();
    }
    #pragma unroll
    for (int j = 0; j < 4; j++) {
        rs[j] += __shfl_xor_sync(0xFFFFFFFFu, rs[j], 1);
        rs[j] += __shfl_xor_sync(0xFFFFFFFFu, rs[j], 2);
    }
    float* srs = (float*)(sm + SFC_RS);
    if ((lane & 3) == 0) {
        int rr = lane >> 2;
        #pragma unroll
        for (int mi = 0; mi < 2; mi++) {
            srs[wn*128 + wm*32 + mi*16 + rr]     = rs[mi*2+0];
            srs[wn*128 + wm*32 + mi*16 + rr + 8] = rs[mi*2+1];
        }
    }
    __syncthreads();
    if (tx < 128)
        g_fcsum[(size_t)n * Bc*Tc + btile*128 + tx] = srs[tx] + srs[128 + tx];
}

// ---------------- elementwise per-step kernels ----------------
__global__ void k_update(const float* __restrict__ router_w, const float* __restrict__ router_b, int step) {
    int bt = blockIdx.x;
    int e = threadIdx.x;
    __shared__ float sred[Ec];
    int gi = e >> 6, gd = e & 63;
    float fu = 0.f;
    #pragma unroll
    for (int l = 0; l < Lc; l++) {
        int n = l*Gc + gi;
        size_t row = (size_t)n*Bc*Tc + bt;
        float att = g_att[row*GDc + gd];
        float aps = g_apsum[n*GDc + gd];
        float fcs = g_fcsum[row];
        float mps = g_mpsum[n*GDc + gd];
        float w   = g_weff[step*NU + n];
        fu += (att*aps + fcs*mps) * w;
    }
    float pc = g_pcont[bt];
    float xv = g_x[(size_t)bt*Ec + e] + fu * pc;
    g_x[(size_t)bt*Ec + e] = xv;
    sred[e] = xv * router_w[e];
    __syncthreads();
    for (int s = 256; s > 0; s >>= 1) { if (e < s) sred[e] += sred[e+s]; __syncthreads(); }
    if (e == 0) {
        float ph = 1.f / (1.f + expf(-(sred[0] + router_b[0])));
        g_pcont[bt] = pc * (1.f - ph);
    }
}

__global__ void k_rmsfinal() {
    int bt = blockIdx.x;
    int tx = threadIdx.x;
    __shared__ float sred[256];
    float a = g_x[(size_t)bt*Ec + tx], b = g_x[(size_t)bt*Ec + tx + 256];
    sred[tx] = a*a + b*b;
    __syncthreads();
    for (int s = 128; s > 0; s >>= 1) { if (tx < s) sred[tx] += sred[tx+s]; __syncthreads(); }
    float r = rsqrtf(sred[0] / (float)Ec + EPSc);
    g_xn[(size_t)bt*Ec + tx]       = a*r;
    g_xn[(size_t)bt*Ec + tx + 256] = b*r;
}

// ---------------- launch ----------------
extern "C" void kernel_launch(void* const* d_in, const int* in_sizes, int n_in,
                              void* d_out, int out_size) {
    const int*   idx       = (const int*)  d_in[0];
    const float* wte       = (const float*)d_in[2];
    const float* adapters  = (const float*)d_in[3];
    const float* qkv_w     = (const float*)d_in[4];
    const float* attn_proj = (const float*)d_in[5];
    const float* mlp_fc    = (const float*)d_in[6];
    const float* mlp_proj  = (const float*)d_in[7];
    const float* dep       = (const float*)d_in[8];
    const float* router_w  = (const float*)d_in[9];
    const float* router_b  = (const float*)d_in[10];
    const float* lm_head   = (const float*)d_in[11];
    float* out = (float*)d_out;

    float *px, *pxn, *padap;
    __nv_bfloat16 *pah, *pal, *pfh, *plh, *pll, *pqh;
    cudaGetSymbolAddress((void**)&px,    g_x);
    cudaGetSymbolAddress((void**)&pxn,   g_xn);
    cudaGetSymbolAddress((void**)&padap, g_adap);
    cudaGetSymbolAddress((void**)&pah,   g_adap_h);
    cudaGetSymbolAddress((void**)&pal,   g_adap_l);
    cudaGetSymbolAddress((void**)&pfh,   g_fcw_h);
    cudaGetSymbolAddress((void**)&plh,   g_lmh_h);
    cudaGetSymbolAddress((void**)&pll,   g_lmh_l);
    cudaGetSymbolAddress((void**)&pqh,   g_qkvw_h);

    cudaFuncSetAttribute((const void*)mma_gemm<1,2,3>, cudaFuncAttributeMaxDynamicSharedMemorySize, SMEM_LM);
    cudaFuncSetAttribute((const void*)mma_gemm<2,1,2>, cudaFuncAttributeMaxDynamicSharedMemorySize, SMEM_XI);
    cudaFuncSetAttribute(k_fcmma,  cudaFuncAttributeMaxDynamicSharedMemorySize, SMEM_FC2);
    cudaFuncSetAttribute(k_qkvmma, cudaFuncAttributeMaxDynamicSharedMemorySize, SMEM_QKV2);

    k_tables<<<Tc, 32>>>();
    k_depths<<<1, NU>>>(dep);
    k_sums<<<(NU*GDc + 255)/256, 256>>>(attn_proj, mlp_proj);
    k_adap<<<(NU*GDc*Ec)/256, 256>>>(adapters);
    k_split<<<(NU*GDc*Ec + 255)/256, 256>>>(padap, pah, pal, NU*GDc*Ec, NU*GDc*Ec);
    k_split<<<(NU*256*GDc + 255)/256, 256>>>(mlp_fc, pfh, (__nv_bfloat16*)nullptr, NU*256*GDc, NU*256*GDc);
    k_split<<<(NU*192*GDc + 255)/256, 256>>>(qkv_w, pqh, (__nv_bfloat16*)nullptr, NU*192*GDc, NU*192*GDc);
    k_split<<<(VPAD*Ec + 255)/256, 256>>>(lm_head, plh, pll, Vc*Ec, VPAD*Ec);
    k_embed<<<Bc*Tc, 256>>>(idx, wte);

    for (int t = 0; t < Sc; t++) {
        // xi (bf16-hi out): M=512, N=4096, K=512, 2-term split, B=adapter hi
        mma_gemm<2,1,2><<<dim3(32, 4), 256, SMEM_XI>>>(px, pah, pal, (float*)nullptr, Bc*Tc, NU*GDc, Ec);
        k_qkvmma<<<dim3(Bc*Tc/128, NU), 256, SMEM_QKV2>>>();
        k_attn<<<dim3(4, NU, Bc), 128>>>();
        k_fcmma<<<dim3(Bc*Tc/128, NU), 256, SMEM_FC2>>>(pfh);
        k_update<<<Bc*Tc, Ec>>>(router_w, router_b, t);
    }

    k_rmsfinal<<<Bc*Tc, 256>>>();
    // logits: M=512 (2 x 256-row blocks), N=50257 (padded 50304), K=512, 3-term split
    mma_gemm<1,2,3><<<dim3(VPAD/128, 2), 256, SMEM_LM>>>(pxn, plh, pll, out, Bc*Tc, Vc, Ec);
}